// round 2
// baseline (speedup 1.0000x reference)
#include <cuda_runtime.h>
#include <cstdint>

#define HEADS   16
#define DHEAD   64
#define BATCH   2
#define NSEQ    2048
#define DIM     1024
#define SCALE   0.125f   // 64^-0.5

// Scratch (allocation-free contract: __device__ globals)
__device__ float g_w[(size_t)BATCH * NSEQ * DIM];    // shared q=k=v projection, (b*n, h*64+d)
__device__ float g_att[(size_t)BATCH * NSEQ * DIM];  // attention output, same layout

// ---------------------------------------------------------------------------
// SGEMM: C[M,N] = A[M,K] @ B[K,N] (+ bias per column). 128x128 tile, BK=16,
// 256 threads, 8x8 microtile. A staged transposed in smem.
// ---------------------------------------------------------------------------
#define BM 128
#define BN 128
#define BK 16

__global__ __launch_bounds__(256) void sgemm_kernel(
    const float* __restrict__ A, const float* __restrict__ Bm,
    const float* __restrict__ bias, float* __restrict__ C,
    int M, int N, int K)
{
    __shared__ float As[BK][BM];   // As[k][m]
    __shared__ float Bs[BK][BN];   // Bs[k][n]

    const int tid = threadIdx.x;
    const int tx  = tid & 15;
    const int ty  = tid >> 4;
    const int m0  = blockIdx.y * BM;
    const int n0  = blockIdx.x * BN;

    float acc[8][8];
    #pragma unroll
    for (int r = 0; r < 8; r++)
        #pragma unroll
        for (int c = 0; c < 8; c++) acc[r][c] = 0.0f;

    for (int k0 = 0; k0 < K; k0 += BK) {
        // Stage A (transposed) and B. 512 float4 each; 2 per thread.
        #pragma unroll
        for (int i = 0; i < 2; i++) {
            int f = tid * 2 + i;
            // A: row = f>>2 (0..127), kq = (f&3)*4
            int arow = f >> 2;
            int kq   = (f & 3) * 4;
            float4 a = *(const float4*)&A[(size_t)(m0 + arow) * K + k0 + kq];
            As[kq + 0][arow] = a.x;
            As[kq + 1][arow] = a.y;
            As[kq + 2][arow] = a.z;
            As[kq + 3][arow] = a.w;
            // B: krow = f>>5 (0..15), c4 = (f&31)*4
            int krow = f >> 5;
            int c4   = (f & 31) * 4;
            *(float4*)&Bs[krow][c4] =
                *(const float4*)&Bm[(size_t)(k0 + krow) * N + n0 + c4];
        }
        __syncthreads();

        #pragma unroll
        for (int k = 0; k < BK; k++) {
            float a[8], b[8];
            *(float4*)&a[0] = *(const float4*)&As[k][ty * 8];
            *(float4*)&a[4] = *(const float4*)&As[k][ty * 8 + 4];
            *(float4*)&b[0] = *(const float4*)&Bs[k][tx * 8];
            *(float4*)&b[4] = *(const float4*)&Bs[k][tx * 8 + 4];
            #pragma unroll
            for (int r = 0; r < 8; r++)
                #pragma unroll
                for (int c = 0; c < 8; c++)
                    acc[r][c] += a[r] * b[c];
        }
        __syncthreads();
    }

    #pragma unroll
    for (int r = 0; r < 8; r++) {
        int row = m0 + ty * 8 + r;
        #pragma unroll
        for (int c = 0; c < 8; c += 4) {
            int col = n0 + tx * 8 + c;
            float4 v = make_float4(acc[r][c], acc[r][c + 1], acc[r][c + 2], acc[r][c + 3]);
            if (bias) {
                v.x += bias[col];     v.y += bias[col + 1];
                v.z += bias[col + 2]; v.w += bias[col + 3];
            }
            *(float4*)&C[(size_t)row * N + col] = v;
        }
    }
}

// ---------------------------------------------------------------------------
// Attention (q=k=v=w). One CTA = one (b,h) x 64-row Q block. Flash-style
// online softmax over unmasked scores; post-softmax column mask folded into
// the PV numerator only. 256 threads (16x16), 4x4 microtiles.
// ---------------------------------------------------------------------------
#define PITCH 68          // 64 + 4 pad (float4-aligned rows)
#define QBLK  64

__global__ __launch_bounds__(256) void attn_kernel(const int* __restrict__ mask)
{
    extern __shared__ float smem[];
    float* Qt = smem;                  // Qt[d][r]  (scaled)
    float* Kt = Qt + QBLK * PITCH;     // Kt[d][j]
    float* Ks = Kt + QBLK * PITCH;     // Ks[j][d]  == V
    float* Ps = Ks + QBLK * PITCH;     // Ps[r][j]  masked probs
    float* Ms = Ps + QBLK * PITCH;     // Ms[j] = 1 - mask

    const int tid = threadIdx.x;
    const int tx  = tid & 15;
    const int ty  = tid >> 4;
    const int qb  = blockIdx.x;
    const int h   = blockIdx.y;
    const int b   = blockIdx.z;
    const int i0  = qb * QBLK;

    const float* wbase = g_w + (size_t)b * NSEQ * DIM + h * DHEAD;
    const int*   mrow  = mask + (size_t)b * NSEQ;

    // Load Q tile, transposed + pre-scaled. j = tid%64 keeps scatter stores
    // conflict-free (32 lanes -> 32 distinct banks).
    {
        int r = tid & 63;
        int dbase = (tid >> 6) * 16;
        const float* src = wbase + (size_t)(i0 + r) * DIM + dbase;
        #pragma unroll
        for (int q = 0; q < 4; q++) {
            float4 v = *(const float4*)(src + q * 4);
            int d = dbase + q * 4;
            Qt[(d + 0) * PITCH + r] = v.x * SCALE;
            Qt[(d + 1) * PITCH + r] = v.y * SCALE;
            Qt[(d + 2) * PITCH + r] = v.z * SCALE;
            Qt[(d + 3) * PITCH + r] = v.w * SCALE;
        }
    }

    float mrun[4], lrun[4], O[4][4];
    #pragma unroll
    for (int rr = 0; rr < 4; rr++) {
        mrun[rr] = -1e30f;
        lrun[rr] = 0.0f;
        #pragma unroll
        for (int cc = 0; cc < 4; cc++) O[rr][cc] = 0.0f;
    }

    for (int j0 = 0; j0 < NSEQ; j0 += QBLK) {
        __syncthreads();   // previous PV done -> safe to overwrite Ks/Kt

        // Load K/V tile: row-major (V) + transposed (for S), plus mask slice.
        {
            int j = tid & 63;
            int dbase = (tid >> 6) * 16;
            const float* src = wbase + (size_t)(j0 + j) * DIM + dbase;
            #pragma unroll
            for (int q = 0; q < 4; q++) {
                float4 v = *(const float4*)(src + q * 4);
                int d = dbase + q * 4;
                *(float4*)&Ks[j * PITCH + d] = v;
                Kt[(d + 0) * PITCH + j] = v.x;
                Kt[(d + 1) * PITCH + j] = v.y;
                Kt[(d + 2) * PITCH + j] = v.z;
                Kt[(d + 3) * PITCH + j] = v.w;
            }
            if (tid < QBLK) Ms[tid] = 1.0f - (float)mrow[j0 + tid];
        }
        __syncthreads();

        // S = (Q*scale) @ K^T for this 64x64 tile, 4x4 per thread.
        float s[4][4];
        #pragma unroll
        for (int rr = 0; rr < 4; rr++)
            #pragma unroll
            for (int jj = 0; jj < 4; jj++) s[rr][jj] = 0.0f;

        #pragma unroll 8
        for (int d = 0; d < QBLK; d++) {
            float4 q4 = *(const float4*)&Qt[d * PITCH + ty * 4];
            float4 k4 = *(const float4*)&Kt[d * PITCH + tx * 4];
            float qa[4] = {q4.x, q4.y, q4.z, q4.w};
            float ka[4] = {k4.x, k4.y, k4.z, k4.w};
            #pragma unroll
            for (int rr = 0; rr < 4; rr++)
                #pragma unroll
                for (int jj = 0; jj < 4; jj++)
                    s[rr][jj] += qa[rr] * ka[jj];
        }

        // Online softmax update (UNMASKED max & sum, per reference).
        #pragma unroll
        for (int rr = 0; rr < 4; rr++) {
            float rmax = s[rr][0];
            rmax = fmaxf(rmax, s[rr][1]);
            rmax = fmaxf(rmax, s[rr][2]);
            rmax = fmaxf(rmax, s[rr][3]);
            #pragma unroll
            for (int off = 8; off > 0; off >>= 1)
                rmax = fmaxf(rmax, __shfl_xor_sync(0xffffffffu, rmax, off, 16));

            float mnew = fmaxf(mrun[rr], rmax);
            float corr = __expf(mrun[rr] - mnew);

            float p0 = __expf(s[rr][0] - mnew);
            float p1 = __expf(s[rr][1] - mnew);
            float p2 = __expf(s[rr][2] - mnew);
            float p3 = __expf(s[rr][3] - mnew);
            s[rr][0] = p0; s[rr][1] = p1; s[rr][2] = p2; s[rr][3] = p3;

            float rsum = p0 + p1 + p2 + p3;
            #pragma unroll
            for (int off = 8; off > 0; off >>= 1)
                rsum += __shfl_xor_sync(0xffffffffu, rsum, off, 16);

            lrun[rr] = lrun[rr] * corr + rsum;
            mrun[rr] = mnew;
            #pragma unroll
            for (int cc = 0; cc < 4; cc++) O[rr][cc] *= corr;
        }

        // Store masked P (mask applied to numerator only).
        {
            float4 mv = *(const float4*)&Ms[tx * 4];
            #pragma unroll
            for (int rr = 0; rr < 4; rr++) {
                float4 pv = make_float4(s[rr][0] * mv.x, s[rr][1] * mv.y,
                                        s[rr][2] * mv.z, s[rr][3] * mv.w);
                *(float4*)&Ps[(ty * 4 + rr) * PITCH + tx * 4] = pv;
            }
        }
        __syncthreads();

        // O += P @ V. P read via 16-lane broadcast, V via float4.
        #pragma unroll 4
        for (int j = 0; j < QBLK; j++) {
            float4 v = *(const float4*)&Ks[j * PITCH + tx * 4];
            #pragma unroll
            for (int rr = 0; rr < 4; rr++) {
                float p = Ps[(ty * 4 + rr) * PITCH + j];
                O[rr][0] += p * v.x;
                O[rr][1] += p * v.y;
                O[rr][2] += p * v.z;
                O[rr][3] += p * v.w;
            }
        }
    }

    // Normalize and store to g_att in (b, n, h*64+d) layout.
    float* obase = g_att + ((size_t)b * NSEQ + i0) * DIM + h * DHEAD;
    #pragma unroll
    for (int rr = 0; rr < 4; rr++) {
        float inv = 1.0f / lrun[rr];
        float4 o = make_float4(O[rr][0] * inv, O[rr][1] * inv,
                               O[rr][2] * inv, O[rr][3] * inv);
        *(float4*)&obase[(size_t)(ty * 4 + rr) * DIM + tx * 4] = o;
    }
}

// ---------------------------------------------------------------------------
// Launch: x @ Wqkv -> attention -> @ Wout + bout
// ---------------------------------------------------------------------------
extern "C" void kernel_launch(void* const* d_in, const int* in_sizes, int n_in,
                              void* d_out, int out_size)
{
    const float* x    = (const float*)d_in[0];
    const int*   mask = (const int*)d_in[1];
    const float* Wqkv = (const float*)d_in[2];
    const float* Wout = (const float*)d_in[3];
    const float* bout = (const float*)d_in[4];
    float*       out  = (float*)d_out;

    float *wp = nullptr, *ap = nullptr;
    cudaGetSymbolAddress((void**)&wp, g_w);
    cudaGetSymbolAddress((void**)&ap, g_att);

    const int M = BATCH * NSEQ;          // 4096
    dim3 gg(DIM / BN, M / BM);           // (8, 32)

    // Stage 1: w = x @ Wqkv
    sgemm_kernel<<<gg, 256>>>(x, Wqkv, nullptr, wp, M, DIM, DIM);

    // Stage 2: attention
    size_t smem_bytes = (size_t)(4 * QBLK * PITCH + QBLK) * sizeof(float);  // ~70 KB
    cudaFuncSetAttribute(attn_kernel, cudaFuncAttributeMaxDynamicSharedMemorySize,
                         (int)smem_bytes);
    dim3 ga(NSEQ / QBLK, HEADS, BATCH);  // (32, 16, 2)
    attn_kernel<<<ga, 256, smem_bytes>>>(mask);

    // Stage 3: out = att @ Wout + bout
    sgemm_kernel<<<gg, 256>>>(ap, Wout, bout, out, M, DIM, DIM);
}

// round 4
// speedup vs baseline: 1.8573x; 1.8573x over previous
#include <cuda_runtime.h>
#include <cuda_bf16.h>
#include <cuda_fp16.h>
#include <cstdint>

#define HEADS 16
#define DHEAD 64
#define BATCH 2
#define NSEQ  2048
#define DIM   1024
#define BH    (BATCH*HEADS)

// ---------------- scratch (__device__ globals; allocation-free) -------------
__device__ __align__(256) float         g_w  [(size_t)BATCH*NSEQ*DIM];
__device__ __align__(256) float         g_att[(size_t)BATCH*NSEQ*DIM];
__device__ __align__(256) float         g_S  [(size_t)BH*NSEQ*NSEQ];
__device__ __align__(256) __half        g_P  [(size_t)BH*NSEQ*NSEQ];
__device__ __align__(256) __nv_bfloat16 g_xs  [(size_t)BATCH*NSEQ*3*DIM];
__device__ __align__(256) __nv_bfloat16 g_atts[(size_t)BATCH*NSEQ*3*DIM];
__device__ __align__(256) __nv_bfloat16 g_w1s [(size_t)DIM*3*DIM];
__device__ __align__(256) __nv_bfloat16 g_w2s [(size_t)DIM*3*DIM];
__device__ __align__(256) __nv_bfloat16 g_wA  [(size_t)BH*NSEQ*192];
__device__ __align__(256) __nv_bfloat16 g_wB  [(size_t)BH*NSEQ*192];
__device__ __align__(256) __half        g_vt  [(size_t)BH*DHEAD*NSEQ];

// ---------------------------------------------------------------------------
// mma.sync helpers (portable HMMA — no sm_103a-only instructions)
// ---------------------------------------------------------------------------
__device__ __forceinline__ void mma_bf16(float* d, const uint32_t* a, const uint32_t* b) {
    asm volatile(
        "mma.sync.aligned.m16n8k16.row.col.f32.bf16.bf16.f32 "
        "{%0,%1,%2,%3}, {%4,%5,%6,%7}, {%8,%9}, {%0,%1,%2,%3};"
        : "+f"(d[0]), "+f"(d[1]), "+f"(d[2]), "+f"(d[3])
        : "r"(a[0]), "r"(a[1]), "r"(a[2]), "r"(a[3]), "r"(b[0]), "r"(b[1]));
}
__device__ __forceinline__ void mma_f16(float* d, const uint32_t* a, const uint32_t* b) {
    asm volatile(
        "mma.sync.aligned.m16n8k16.row.col.f32.f16.f16.f32 "
        "{%0,%1,%2,%3}, {%4,%5,%6,%7}, {%8,%9}, {%0,%1,%2,%3};"
        : "+f"(d[0]), "+f"(d[1]), "+f"(d[2]), "+f"(d[3])
        : "r"(a[0]), "r"(a[1]), "r"(a[2]), "r"(a[3]), "r"(b[0]), "r"(b[1]));
}

// ---------------------------------------------------------------------------
// Batched HMMA GEMM: C[m,n] = sum_k A[m,k]*B[n,k] (+bias[n]).
// A: [bz][M,K] 2B K-major; B: [bz][N,K] 2B K-major. K multiple of 32.
// Tile 128 x BN, 256 threads (8 warps), double-buffered smem (pitch 40),
// one __syncthreads per K-chunk, gmem->reg prefetch.
// C offset = (bz % cNb1)*cS1 + (bz / cNb1)*cS2.
// ---------------------------------------------------------------------------
#define PITCH 40   // halfs per smem row (conflict-free fragment loads)

template<int BN, bool BF16>
__global__ __launch_bounds__(256, 2) void mma_gemm(
    const uint16_t* __restrict__ A, size_t aBatch, int lda,
    const uint16_t* __restrict__ B, size_t bBatch, int ldb,
    float* __restrict__ C, int ldc, size_t cS1, size_t cS2, int cNb1,
    int K, const float* __restrict__ bias)
{
    constexpr int MI = (BN == 128) ? 4 : 2;   // 16-row m-tiles per warp
    constexpr int NI = 4;                     // 8-col n-tiles per warp
    constexpr int WCOLS = BN / 32;            // warps along N
    constexpr int B_LD = (BN * 4) / 256;      // uint4 B loads per thread

    __shared__ __align__(16) uint16_t As[2][128 * PITCH];
    __shared__ __align__(16) uint16_t Bs[2][BN * PITCH];

    const int tid  = threadIdx.x;
    const int lane = tid & 31, warp = tid >> 5;
    const int g = lane >> 2, t = lane & 3;
    const int wm0 = (warp / WCOLS) * (MI * 16);
    const int wn0 = (warp % WCOLS) * 32;

    const int bz = blockIdx.z;
    const int m0 = blockIdx.y * 128, n0 = blockIdx.x * BN;

    const uint16_t* Ab = A + (size_t)bz * aBatch + (size_t)m0 * lda;
    const uint16_t* Bb = B + (size_t)bz * bBatch + (size_t)n0 * ldb;

    float acc[MI][NI][4];
    #pragma unroll
    for (int mi = 0; mi < MI; mi++)
        #pragma unroll
        for (int ni = 0; ni < NI; ni++)
            #pragma unroll
            for (int q = 0; q < 4; q++) acc[mi][ni][q] = 0.0f;

    const int NC = K >> 5;   // 32-half chunks

    // stage chunk 0
    {
        #pragma unroll
        for (int i = 0; i < 2; i++) {
            int idx = tid + i * 256;
            int r = idx >> 2, q = (idx & 3) * 8;
            *(uint4*)&As[0][r * PITCH + q] = *(const uint4*)(Ab + (size_t)r * lda + q);
        }
        #pragma unroll
        for (int i = 0; i < B_LD; i++) {
            int idx = tid + i * 256;
            int r = idx >> 2, q = (idx & 3) * 8;
            *(uint4*)&Bs[0][r * PITCH + q] = *(const uint4*)(Bb + (size_t)r * ldb + q);
        }
    }
    __syncthreads();

    for (int c = 0; c < NC; c++) {
        const int cur = c & 1, nxt = cur ^ 1;

        // prefetch chunk c+1 into registers
        uint4 ra[2], rb[B_LD];
        if (c + 1 < NC) {
            const uint16_t* ag = Ab + (size_t)(c + 1) * 32;
            const uint16_t* bg = Bb + (size_t)(c + 1) * 32;
            #pragma unroll
            for (int i = 0; i < 2; i++) {
                int idx = tid + i * 256;
                int r = idx >> 2, q = (idx & 3) * 8;
                ra[i] = *(const uint4*)(ag + (size_t)r * lda + q);
            }
            #pragma unroll
            for (int i = 0; i < B_LD; i++) {
                int idx = tid + i * 256;
                int r = idx >> 2, q = (idx & 3) * 8;
                rb[i] = *(const uint4*)(bg + (size_t)r * ldb + q);
            }
        }

        // compute on current buffer: two k16 steps
        #pragma unroll
        for (int ks = 0; ks < 2; ks++) {
            const int kb = ks * 16;
            uint32_t bf[NI][2];
            #pragma unroll
            for (int ni = 0; ni < NI; ni++) {
                const uint16_t* bp = &Bs[cur][(wn0 + ni * 8 + g) * PITCH + kb + 2 * t];
                bf[ni][0] = *(const uint32_t*)bp;
                bf[ni][1] = *(const uint32_t*)(bp + 8);
            }
            #pragma unroll
            for (int mi = 0; mi < MI; mi++) {
                const uint16_t* ap0 = &As[cur][(wm0 + mi * 16 + g) * PITCH + kb + 2 * t];
                const uint16_t* ap1 = ap0 + 8 * PITCH;
                uint32_t af[4];
                af[0] = *(const uint32_t*)ap0;
                af[1] = *(const uint32_t*)ap1;
                af[2] = *(const uint32_t*)(ap0 + 8);
                af[3] = *(const uint32_t*)(ap1 + 8);
                #pragma unroll
                for (int ni = 0; ni < NI; ni++) {
                    if (BF16) mma_bf16(acc[mi][ni], af, bf[ni]);
                    else      mma_f16 (acc[mi][ni], af, bf[ni]);
                }
            }
        }

        // store prefetched chunk into the other buffer
        if (c + 1 < NC) {
            #pragma unroll
            for (int i = 0; i < 2; i++) {
                int idx = tid + i * 256;
                int r = idx >> 2, q = (idx & 3) * 8;
                *(uint4*)&As[nxt][r * PITCH + q] = ra[i];
            }
            #pragma unroll
            for (int i = 0; i < B_LD; i++) {
                int idx = tid + i * 256;
                int r = idx >> 2, q = (idx & 3) * 8;
                *(uint4*)&Bs[nxt][r * PITCH + q] = rb[i];
            }
        }
        __syncthreads();
    }

    // epilogue: fragments -> gmem (float2 per lane, 32B sectors fully covered)
    const size_t cOff = (size_t)(bz % cNb1) * cS1 + (size_t)(bz / cNb1) * cS2;
    float* Cb = C + cOff + (size_t)m0 * ldc + n0;
    #pragma unroll
    for (int mi = 0; mi < MI; mi++) {
        #pragma unroll
        for (int ni = 0; ni < NI; ni++) {
            int col = wn0 + ni * 8 + 2 * t;
            float bx = 0.0f, by = 0.0f;
            if (bias) { bx = bias[n0 + col]; by = bias[n0 + col + 1]; }
            int r1 = wm0 + mi * 16 + g;
            float2 v0 = make_float2(acc[mi][ni][0] + bx, acc[mi][ni][1] + by);
            float2 v1 = make_float2(acc[mi][ni][2] + bx, acc[mi][ni][3] + by);
            *(float2*)(Cb + (size_t)r1 * ldc + col)       = v0;
            *(float2*)(Cb + (size_t)(r1 + 8) * ldc + col) = v1;
        }
    }
}

// ---------------- converters -------------------------------------------------
// fp32 [R,K] -> bf16 [R,3K] rows [hi|lo|hi]
__global__ void split_p1(const float* __restrict__ in, __nv_bfloat16* __restrict__ out,
                         int K, size_t total)
{
    size_t idx = (size_t)blockIdx.x * 256 + threadIdx.x;
    if (idx >= total) return;
    size_t r = idx / K; int k = (int)(idx % K);
    float x = in[idx];
    __nv_bfloat16 hi = __float2bfloat16(x);
    __nv_bfloat16 lo = __float2bfloat16(x - __bfloat162float(hi));
    __nv_bfloat16* o = out + r * (size_t)(3 * K);
    o[k] = hi; o[K + k] = lo; o[2 * K + k] = hi;
}

// fp32 W[K,N] -> bf16 out[N,3K] rows [hi|hi|lo] (transposed)
__global__ __launch_bounds__(256) void splitT_p2(const float* __restrict__ W,
                                                 __nv_bfloat16* __restrict__ out,
                                                 int Kd, int Nd)
{
    __shared__ float ts[32][33];
    int k0 = blockIdx.x * 32, n0 = blockIdx.y * 32;
    int tx = threadIdx.x & 31, ty = threadIdx.x >> 5;
    for (int r = ty; r < 32; r += 8) ts[r][tx] = W[(size_t)(k0 + r) * Nd + n0 + tx];
    __syncthreads();
    for (int r = ty; r < 32; r += 8) {
        float x = ts[tx][r];
        __nv_bfloat16 hi = __float2bfloat16(x);
        __nv_bfloat16 lo = __float2bfloat16(x - __bfloat162float(hi));
        __nv_bfloat16* o = out + (size_t)(n0 + r) * (3 * Kd) + k0 + tx;
        o[0] = hi; o[Kd] = hi; o[2 * Kd] = lo;
    }
}

// g_w -> per-head split: wA (scaled, [hi|lo|hi]) and wB ([hi|hi|lo]), [bh][n][192]
__global__ void w_split(const float* __restrict__ w,
                        __nv_bfloat16* __restrict__ wA, __nv_bfloat16* __restrict__ wB)
{
    size_t idx = (size_t)blockIdx.x * 256 + threadIdx.x;
    float v = w[idx];
    int c = (int)(idx & 1023);
    size_t bn = idx >> 10;
    int n = (int)(bn & 2047), b = (int)(bn >> 11);
    int h = c >> 6, kk = c & 63;
    size_t base = (((size_t)(b * 16 + h)) * NSEQ + n) * 192;
    float sv = v * 0.125f;
    __nv_bfloat16 hiA = __float2bfloat16(sv);
    __nv_bfloat16 loA = __float2bfloat16(sv - __bfloat162float(hiA));
    __nv_bfloat16 hiB = __float2bfloat16(v);
    __nv_bfloat16 loB = __float2bfloat16(v - __bfloat162float(hiB));
    wA[base + kk] = hiA; wA[base + 64 + kk] = loA; wA[base + 128 + kk] = hiA;
    wB[base + kk] = hiB; wB[base + 64 + kk] = hiB; wB[base + 128 + kk] = loB;
}

// g_w -> V^T f16: vt[bh][d][j] = (f16) w[b][j][h*64+d]
__global__ __launch_bounds__(256) void vt_trans(const float* __restrict__ w,
                                                __half* __restrict__ vt)
{
    __shared__ float ts[64][65];
    int j0 = blockIdx.x * 64, bh = blockIdx.y;
    int b = bh >> 4, h = bh & 15;
    const float* base = w + (size_t)b * NSEQ * DIM + h * 64;
    for (int idx = threadIdx.x; idx < 64 * 16; idx += 256) {
        int jj = idx >> 4, i = idx & 15;
        float4 v = *(const float4*)(base + (size_t)(j0 + jj) * DIM + i * 4);
        ts[jj][i*4] = v.x; ts[jj][i*4+1] = v.y; ts[jj][i*4+2] = v.z; ts[jj][i*4+3] = v.w;
    }
    __syncthreads();
    __half* o = vt + (size_t)bh * 64 * NSEQ + j0;
    for (int idx = threadIdx.x; idx < 64 * 64; idx += 256) {
        int d = idx >> 6, jj = idx & 63;
        o[(size_t)d * NSEQ + jj] = __float2half_rn(ts[jj][d]);
    }
}

// row softmax over S + post-softmax multiplicative mask -> P (f16)
__global__ __launch_bounds__(256) void softmax_mask(const int* __restrict__ mask)
{
    __shared__ float red[8];
    const int row = blockIdx.x;
    const float* s = g_S + (size_t)row * NSEQ;
    __half* p = g_P + (size_t)row * NSEQ;
    const int b = row >> 15;
    const int* mrow = mask + (size_t)b * NSEQ;
    const int tid = threadIdx.x, wid = tid >> 5, lid = tid & 31;

    float v[8];
    #pragma unroll
    for (int k = 0; k < 8; k++) v[k] = s[tid + k * 256];

    float m = v[0];
    #pragma unroll
    for (int k = 1; k < 8; k++) m = fmaxf(m, v[k]);
    #pragma unroll
    for (int o = 16; o > 0; o >>= 1) m = fmaxf(m, __shfl_xor_sync(0xffffffffu, m, o));
    if (lid == 0) red[wid] = m;
    __syncthreads();
    if (tid == 0) {
        float mm = red[0];
        #pragma unroll
        for (int i = 1; i < 8; i++) mm = fmaxf(mm, red[i]);
        red[0] = mm;
    }
    __syncthreads();
    m = red[0];
    __syncthreads();

    float e[8], sum = 0.0f;
    #pragma unroll
    for (int k = 0; k < 8; k++) { e[k] = __expf(v[k] - m); sum += e[k]; }
    #pragma unroll
    for (int o = 16; o > 0; o >>= 1) sum += __shfl_xor_sync(0xffffffffu, sum, o);
    if (lid == 0) red[wid] = sum;
    __syncthreads();
    if (tid == 0) {
        float tsum = 0.0f;
        #pragma unroll
        for (int i = 0; i < 8; i++) tsum += red[i];
        red[0] = tsum;
    }
    __syncthreads();
    float inv = 1.0f / red[0];

    #pragma unroll
    for (int k = 0; k < 8; k++) {
        int col = tid + k * 256;
        p[col] = __float2half_rn(e[k] * inv * (1.0f - (float)mrow[col]));
    }
}

// ---------------- launch ------------------------------------------------------
extern "C" void kernel_launch(void* const* d_in, const int* in_sizes, int n_in,
                              void* d_out, int out_size)
{
    const float* x    = (const float*)d_in[0];
    const int*   mask = (const int*)d_in[1];
    const float* Wqkv = (const float*)d_in[2];
    const float* Wout = (const float*)d_in[3];
    const float* bout = (const float*)d_in[4];
    float*       out  = (float*)d_out;

    float *wp, *ap, *Sp;
    __nv_bfloat16 *xs, *atts, *w1s, *w2s, *wA, *wB;
    __half *Pp, *vt;
    cudaGetSymbolAddress((void**)&wp,   g_w);
    cudaGetSymbolAddress((void**)&ap,   g_att);
    cudaGetSymbolAddress((void**)&Sp,   g_S);
    cudaGetSymbolAddress((void**)&Pp,   g_P);
    cudaGetSymbolAddress((void**)&xs,   g_xs);
    cudaGetSymbolAddress((void**)&atts, g_atts);
    cudaGetSymbolAddress((void**)&w1s,  g_w1s);
    cudaGetSymbolAddress((void**)&w2s,  g_w2s);
    cudaGetSymbolAddress((void**)&wA,   g_wA);
    cudaGetSymbolAddress((void**)&wB,   g_wB);
    cudaGetSymbolAddress((void**)&vt,   g_vt);

    // split inputs + weights
    split_p1<<<(BATCH*NSEQ*DIM + 255) / 256, 256>>>(x, xs, DIM, (size_t)BATCH*NSEQ*DIM);
    splitT_p2<<<dim3(DIM/32, DIM/32), 256>>>(Wqkv, w1s, DIM, DIM);
    splitT_p2<<<dim3(DIM/32, DIM/32), 256>>>(Wout, w2s, DIM, DIM);

    // stage 1: w = x @ Wqkv   (M=4096, N=1024, K'=3072)
    mma_gemm<128, true><<<dim3(DIM/128, (BATCH*NSEQ)/128, 1), 256>>>(
        (const uint16_t*)xs, 0, 3*DIM, (const uint16_t*)w1s, 0, 3*DIM,
        wp, DIM, 0, 0, 1, 3*DIM, nullptr);

    // per-head splits + V^T
    w_split<<<(BATCH*NSEQ*DIM)/256, 256>>>(wp, wA, wB);
    vt_trans<<<dim3(NSEQ/64, BH), 256>>>(wp, vt);

    // stage 2: S = (q*scale) @ k^T  (per bh: M=2048, N=2048, K'=192)
    mma_gemm<128, true><<<dim3(NSEQ/128, NSEQ/128, BH), 256>>>(
        (const uint16_t*)wA, (size_t)NSEQ*192, 192,
        (const uint16_t*)wB, (size_t)NSEQ*192, 192,
        Sp, NSEQ, (size_t)NSEQ*NSEQ, 0, BH, 192, nullptr);

    // softmax + mask -> P (f16)
    softmax_mask<<<BH*NSEQ, 256>>>(mask);

    // stage 3: att = P @ V   (per bh: M=2048, N=64, K=2048)
    mma_gemm<64, false><<<dim3(1, NSEQ/128, BH), 256>>>(
        (const uint16_t*)Pp, (size_t)NSEQ*NSEQ, NSEQ,
        (const uint16_t*)vt, (size_t)DHEAD*NSEQ, NSEQ,
        ap, DIM, DHEAD, (size_t)NSEQ*DIM, HEADS, NSEQ, nullptr);

    // stage 4: out = att @ Wout + bout
    split_p1<<<(BATCH*NSEQ*DIM + 255) / 256, 256>>>(ap, atts, DIM, (size_t)BATCH*NSEQ*DIM);
    mma_gemm<128, true><<<dim3(DIM/128, (BATCH*NSEQ)/128, 1), 256>>>(
        (const uint16_t*)atts, 0, 3*DIM, (const uint16_t*)w2s, 0, 3*DIM,
        out, DIM, 0, 0, 1, 3*DIM, bout);
}

// round 5
// speedup vs baseline: 2.5234x; 1.3586x over previous
#include <cuda_runtime.h>
#include <cuda_bf16.h>
#include <cuda_fp16.h>
#include <cstdint>

#define HEADS 16
#define DHEAD 64
#define BATCH 2
#define NSEQ  2048
#define DIM   1024
#define BH    (BATCH*HEADS)

// ---------------- scratch (__device__ globals; allocation-free) -------------
__device__ __align__(256) float         g_w  [(size_t)BATCH*NSEQ*DIM];
__device__ __align__(256) float         g_att[(size_t)BATCH*NSEQ*DIM];
__device__ __align__(256) __nv_bfloat16 g_xs  [(size_t)BATCH*NSEQ*3*DIM];
__device__ __align__(256) __nv_bfloat16 g_atts[(size_t)BATCH*NSEQ*3*DIM];
__device__ __align__(256) __nv_bfloat16 g_w1s [(size_t)DIM*3*DIM];
__device__ __align__(256) __nv_bfloat16 g_w2s [(size_t)DIM*3*DIM];
__device__ __align__(256) __nv_bfloat16 g_wA  [(size_t)BH*NSEQ*192];
__device__ __align__(256) __nv_bfloat16 g_wB  [(size_t)BH*NSEQ*192];
__device__ __align__(256) __half        g_vt  [(size_t)BH*DHEAD*NSEQ];

// ---------------- mma.sync helpers (portable HMMA) ---------------------------
__device__ __forceinline__ void mma_bf16(float* d, const uint32_t* a, const uint32_t* b) {
    asm volatile(
        "mma.sync.aligned.m16n8k16.row.col.f32.bf16.bf16.f32 "
        "{%0,%1,%2,%3}, {%4,%5,%6,%7}, {%8,%9}, {%0,%1,%2,%3};"
        : "+f"(d[0]), "+f"(d[1]), "+f"(d[2]), "+f"(d[3])
        : "r"(a[0]), "r"(a[1]), "r"(a[2]), "r"(a[3]), "r"(b[0]), "r"(b[1]));
}
__device__ __forceinline__ void mma_f16(float* d, const uint32_t* a, const uint32_t* b) {
    asm volatile(
        "mma.sync.aligned.m16n8k16.row.col.f32.f16.f16.f32 "
        "{%0,%1,%2,%3}, {%4,%5,%6,%7}, {%8,%9}, {%0,%1,%2,%3};"
        : "+f"(d[0]), "+f"(d[1]), "+f"(d[2]), "+f"(d[3])
        : "r"(a[0]), "r"(a[1]), "r"(a[2]), "r"(a[3]), "r"(b[0]), "r"(b[1]));
}

// ---------------------------------------------------------------------------
// Batched HMMA GEMM (unchanged from R4, validated)
// ---------------------------------------------------------------------------
#define GPITCH 40

template<int BN, bool BF16>
__global__ __launch_bounds__(256, 2) void mma_gemm(
    const uint16_t* __restrict__ A, size_t aBatch, int lda,
    const uint16_t* __restrict__ B, size_t bBatch, int ldb,
    float* __restrict__ C, int ldc, size_t cS1, size_t cS2, int cNb1,
    int K, const float* __restrict__ bias)
{
    constexpr int MI = (BN == 128) ? 4 : 2;
    constexpr int NI = 4;
    constexpr int WCOLS = BN / 32;
    constexpr int B_LD = (BN * 4) / 256;

    __shared__ __align__(16) uint16_t As[2][128 * GPITCH];
    __shared__ __align__(16) uint16_t Bs[2][BN * GPITCH];

    const int tid  = threadIdx.x;
    const int lane = tid & 31, warp = tid >> 5;
    const int g = lane >> 2, t = lane & 3;
    const int wm0 = (warp / WCOLS) * (MI * 16);
    const int wn0 = (warp % WCOLS) * 32;

    const int bz = blockIdx.z;
    const int m0 = blockIdx.y * 128, n0 = blockIdx.x * BN;

    const uint16_t* Ab = A + (size_t)bz * aBatch + (size_t)m0 * lda;
    const uint16_t* Bb = B + (size_t)bz * bBatch + (size_t)n0 * ldb;

    float acc[MI][NI][4];
    #pragma unroll
    for (int mi = 0; mi < MI; mi++)
        #pragma unroll
        for (int ni = 0; ni < NI; ni++)
            #pragma unroll
            for (int q = 0; q < 4; q++) acc[mi][ni][q] = 0.0f;

    const int NC = K >> 5;

    {
        #pragma unroll
        for (int i = 0; i < 2; i++) {
            int idx = tid + i * 256;
            int r = idx >> 2, q = (idx & 3) * 8;
            *(uint4*)&As[0][r * GPITCH + q] = *(const uint4*)(Ab + (size_t)r * lda + q);
        }
        #pragma unroll
        for (int i = 0; i < B_LD; i++) {
            int idx = tid + i * 256;
            int r = idx >> 2, q = (idx & 3) * 8;
            *(uint4*)&Bs[0][r * GPITCH + q] = *(const uint4*)(Bb + (size_t)r * ldb + q);
        }
    }
    __syncthreads();

    for (int c = 0; c < NC; c++) {
        const int cur = c & 1, nxt = cur ^ 1;

        uint4 ra[2], rb[B_LD];
        if (c + 1 < NC) {
            const uint16_t* ag = Ab + (size_t)(c + 1) * 32;
            const uint16_t* bg = Bb + (size_t)(c + 1) * 32;
            #pragma unroll
            for (int i = 0; i < 2; i++) {
                int idx = tid + i * 256;
                int r = idx >> 2, q = (idx & 3) * 8;
                ra[i] = *(const uint4*)(ag + (size_t)r * lda + q);
            }
            #pragma unroll
            for (int i = 0; i < B_LD; i++) {
                int idx = tid + i * 256;
                int r = idx >> 2, q = (idx & 3) * 8;
                rb[i] = *(const uint4*)(bg + (size_t)r * ldb + q);
            }
        }

        #pragma unroll
        for (int ks = 0; ks < 2; ks++) {
            const int kb = ks * 16;
            uint32_t bf[NI][2];
            #pragma unroll
            for (int ni = 0; ni < NI; ni++) {
                const uint16_t* bp = &Bs[cur][(wn0 + ni * 8 + g) * GPITCH + kb + 2 * t];
                bf[ni][0] = *(const uint32_t*)bp;
                bf[ni][1] = *(const uint32_t*)(bp + 8);
            }
            #pragma unroll
            for (int mi = 0; mi < MI; mi++) {
                const uint16_t* ap0 = &As[cur][(wm0 + mi * 16 + g) * GPITCH + kb + 2 * t];
                const uint16_t* ap1 = ap0 + 8 * GPITCH;
                uint32_t af[4];
                af[0] = *(const uint32_t*)ap0;
                af[1] = *(const uint32_t*)ap1;
                af[2] = *(const uint32_t*)(ap0 + 8);
                af[3] = *(const uint32_t*)(ap1 + 8);
                #pragma unroll
                for (int ni = 0; ni < NI; ni++) {
                    if (BF16) mma_bf16(acc[mi][ni], af, bf[ni]);
                    else      mma_f16 (acc[mi][ni], af, bf[ni]);
                }
            }
        }

        if (c + 1 < NC) {
            #pragma unroll
            for (int i = 0; i < 2; i++) {
                int idx = tid + i * 256;
                int r = idx >> 2, q = (idx & 3) * 8;
                *(uint4*)&As[nxt][r * GPITCH + q] = ra[i];
            }
            #pragma unroll
            for (int i = 0; i < B_LD; i++) {
                int idx = tid + i * 256;
                int r = idx >> 2, q = (idx & 3) * 8;
                *(uint4*)&Bs[nxt][r * GPITCH + q] = rb[i];
            }
        }
        __syncthreads();
    }

    const size_t cOff = (size_t)(bz % cNb1) * cS1 + (size_t)(bz / cNb1) * cS2;
    float* Cb = C + cOff + (size_t)m0 * ldc + n0;
    #pragma unroll
    for (int mi = 0; mi < MI; mi++) {
        #pragma unroll
        for (int ni = 0; ni < NI; ni++) {
            int col = wn0 + ni * 8 + 2 * t;
            float bx = 0.0f, by = 0.0f;
            if (bias) { bx = bias[n0 + col]; by = bias[n0 + col + 1]; }
            int r1 = wm0 + mi * 16 + g;
            float2 v0 = make_float2(acc[mi][ni][0] + bx, acc[mi][ni][1] + by);
            float2 v1 = make_float2(acc[mi][ni][2] + bx, acc[mi][ni][3] + by);
            *(float2*)(Cb + (size_t)r1 * ldc + col)       = v0;
            *(float2*)(Cb + (size_t)(r1 + 8) * ldc + col) = v1;
        }
    }
}

// ---------------------------------------------------------------------------
// Fused flash attention. CTA = 128 q-rows of one (b,h); 8 warps x 16 rows.
// Q split-fragments in registers; K(split)/V(f16)/mask double-buffered smem.
// Online softmax in fragments; P repacked in-register for PV mma.
// ---------------------------------------------------------------------------
#define KB   64
#define NIT  (NSEQ / KB)
#define KSP  200     // halfs per K-row (192 + 8; %32==8 -> conflict-free frags)
#define VSP  72      // halfs per Vt-row (64 + 8)
#define SM_K0 0
#define SM_K1 25600
#define SM_V0 51200
#define SM_V1 60416
#define SM_M0 69632
#define SM_M1 69888
#define SM_TOT 70144

__global__ __launch_bounds__(256, 1) void flash_attn(const int* __restrict__ mask)
{
    extern __shared__ char sm[];
    const int tid = threadIdx.x, lane = tid & 31, warp = tid >> 5;
    const int g = lane >> 2, t = lane & 3;
    const int i0 = blockIdx.x * 128;
    const int bh = blockIdx.y;
    const int b = bh >> 4, h = bh & 15;

    const uint16_t* wA = (const uint16_t*)g_wA + (size_t)bh * NSEQ * 192;
    const uint16_t* wB = (const uint16_t*)g_wB + (size_t)bh * NSEQ * 192;
    const uint16_t* vt = (const uint16_t*)g_vt + (size_t)bh * DHEAD * NSEQ;
    const int* mrow = mask + (size_t)b * NSEQ;

    // Q fragments: rows i0 + warp*16 + {g, g+8}, 12 k16 tiles over 192 (split)
    uint32_t qa[12][4];
    {
        const uint16_t* q0 = wA + (size_t)(i0 + warp * 16 + g) * 192 + 2 * t;
        #pragma unroll
        for (int kt = 0; kt < 12; kt++) {
            qa[kt][0] = *(const uint32_t*)(q0 + kt * 16);
            qa[kt][1] = *(const uint32_t*)(q0 + kt * 16 + 8 * 192);
            qa[kt][2] = *(const uint32_t*)(q0 + kt * 16 + 8);
            qa[kt][3] = *(const uint32_t*)(q0 + kt * 16 + 8 * 192 + 8);
        }
    }

    float Oa[8][4];
    #pragma unroll
    for (int nt = 0; nt < 8; nt++)
        #pragma unroll
        for (int q = 0; q < 4; q++) Oa[nt][q] = 0.0f;
    float mr0 = -1e30f, mr1 = -1e30f, lr0 = 0.0f, lr1 = 0.0f;

    // stage tile 0 into buffer 0
    {
        uint16_t* Kn = (uint16_t*)(sm + SM_K0);
        uint16_t* Vn = (uint16_t*)(sm + SM_V0);
        float*    Mn = (float*)(sm + SM_M0);
        #pragma unroll
        for (int i = 0; i < 6; i++) {
            int idx = tid + i * 256;
            int r = idx / 24, q = (idx % 24) * 8;
            *(uint4*)(Kn + r * KSP + q) = *(const uint4*)(wB + (size_t)r * 192 + q);
        }
        #pragma unroll
        for (int i = 0; i < 2; i++) {
            int idx = tid + i * 256;
            int r = idx >> 3, q = (idx & 7) * 8;
            *(uint4*)(Vn + r * VSP + q) = *(const uint4*)(vt + (size_t)r * NSEQ + q);
        }
        if (tid < KB) Mn[tid] = 1.0f - (float)mrow[tid];
    }
    __syncthreads();

    for (int it = 0; it < NIT; it++) {
        const int cur = it & 1;
        uint16_t* Ks = (uint16_t*)(sm + (cur ? SM_K1 : SM_K0));
        uint16_t* Vs = (uint16_t*)(sm + (cur ? SM_V1 : SM_V0));
        float*    Ms = (float*)(sm + (cur ? SM_M1 : SM_M0));

        // prefetch next tile into registers
        uint4 pk[6], pv2[2];
        float pmv = 0.0f;
        const bool pf = (it + 1 < NIT);
        if (pf) {
            const int j0n = (it + 1) * KB;
            #pragma unroll
            for (int i = 0; i < 6; i++) {
                int idx = tid + i * 256;
                int r = idx / 24, q = (idx % 24) * 8;
                pk[i] = *(const uint4*)(wB + (size_t)(j0n + r) * 192 + q);
            }
            #pragma unroll
            for (int i = 0; i < 2; i++) {
                int idx = tid + i * 256;
                int r = idx >> 3, q = (idx & 7) * 8;
                pv2[i] = *(const uint4*)(vt + (size_t)r * NSEQ + j0n + q);
            }
            if (tid < KB) pmv = 1.0f - (float)mrow[j0n + tid];
        }

        // ---- S tile: 16 rows x 64 keys, K'=192 split ----
        float sa[8][4];
        #pragma unroll
        for (int nt = 0; nt < 8; nt++)
            #pragma unroll
            for (int q = 0; q < 4; q++) sa[nt][q] = 0.0f;

        #pragma unroll
        for (int kt = 0; kt < 12; kt++) {
            #pragma unroll
            for (int nt = 0; nt < 8; nt++) {
                const uint16_t* bp = Ks + (nt * 8 + g) * KSP + kt * 16 + 2 * t;
                uint32_t bf[2];
                bf[0] = *(const uint32_t*)bp;
                bf[1] = *(const uint32_t*)(bp + 8);
                mma_bf16(sa[nt], qa[kt], bf);
            }
        }

        // ---- online softmax (rows g and g+8; quad-lane reductions) ----
        float bm0 = -1e30f, bm1 = -1e30f;
        #pragma unroll
        for (int nt = 0; nt < 8; nt++) {
            bm0 = fmaxf(bm0, fmaxf(sa[nt][0], sa[nt][1]));
            bm1 = fmaxf(bm1, fmaxf(sa[nt][2], sa[nt][3]));
        }
        bm0 = fmaxf(bm0, __shfl_xor_sync(0xffffffffu, bm0, 1));
        bm0 = fmaxf(bm0, __shfl_xor_sync(0xffffffffu, bm0, 2));
        bm1 = fmaxf(bm1, __shfl_xor_sync(0xffffffffu, bm1, 1));
        bm1 = fmaxf(bm1, __shfl_xor_sync(0xffffffffu, bm1, 2));

        const float mn0 = fmaxf(mr0, bm0), mn1 = fmaxf(mr1, bm1);
        const float sf0 = __expf(mr0 - mn0), sf1 = __expf(mr1 - mn1);
        mr0 = mn0; mr1 = mn1;

        float rs0 = 0.0f, rs1 = 0.0f;
        #pragma unroll
        for (int nt = 0; nt < 8; nt++) {
            sa[nt][0] = __expf(sa[nt][0] - mn0);
            sa[nt][1] = __expf(sa[nt][1] - mn0);
            sa[nt][2] = __expf(sa[nt][2] - mn1);
            sa[nt][3] = __expf(sa[nt][3] - mn1);
            rs0 += sa[nt][0] + sa[nt][1];
            rs1 += sa[nt][2] + sa[nt][3];
        }
        rs0 += __shfl_xor_sync(0xffffffffu, rs0, 1);
        rs0 += __shfl_xor_sync(0xffffffffu, rs0, 2);
        rs1 += __shfl_xor_sync(0xffffffffu, rs1, 1);
        rs1 += __shfl_xor_sync(0xffffffffu, rs1, 2);
        lr0 = lr0 * sf0 + rs0;
        lr1 = lr1 * sf1 + rs1;

        #pragma unroll
        for (int nt = 0; nt < 8; nt++) {
            Oa[nt][0] *= sf0; Oa[nt][1] *= sf0;
            Oa[nt][2] *= sf1; Oa[nt][3] *= sf1;
        }

        // ---- mask + repack P into f16 A-fragments (acc layout == A layout) ----
        uint32_t pfra[4][4];
        #pragma unroll
        for (int kt2 = 0; kt2 < 4; kt2++) {
            const int n0t = 2 * kt2, n1t = 2 * kt2 + 1;
            float2 mv0 = *(const float2*)&Ms[n0t * 8 + 2 * t];
            float2 mv1 = *(const float2*)&Ms[n1t * 8 + 2 * t];
            __half2 a0 = __floats2half2_rn(sa[n0t][0] * mv0.x, sa[n0t][1] * mv0.y);
            __half2 a1 = __floats2half2_rn(sa[n0t][2] * mv0.x, sa[n0t][3] * mv0.y);
            __half2 a2 = __floats2half2_rn(sa[n1t][0] * mv1.x, sa[n1t][1] * mv1.y);
            __half2 a3 = __floats2half2_rn(sa[n1t][2] * mv1.x, sa[n1t][3] * mv1.y);
            pfra[kt2][0] = *(uint32_t*)&a0;
            pfra[kt2][1] = *(uint32_t*)&a1;
            pfra[kt2][2] = *(uint32_t*)&a2;
            pfra[kt2][3] = *(uint32_t*)&a3;
        }

        // ---- O += P @ V  (V^T tile [d][j] in smem) ----
        #pragma unroll
        for (int nt = 0; nt < 8; nt++) {
            #pragma unroll
            for (int kt2 = 0; kt2 < 4; kt2++) {
                const uint16_t* vp = Vs + (nt * 8 + g) * VSP + kt2 * 16 + 2 * t;
                uint32_t bf[2];
                bf[0] = *(const uint32_t*)vp;
                bf[1] = *(const uint32_t*)(vp + 8);
                mma_f16(Oa[nt], pfra[kt2], bf);
            }
        }

        // ---- store prefetched tile ----
        if (pf) {
            const int nxt = cur ^ 1;
            uint16_t* Kn = (uint16_t*)(sm + (nxt ? SM_K1 : SM_K0));
            uint16_t* Vn = (uint16_t*)(sm + (nxt ? SM_V1 : SM_V0));
            float*    Mn = (float*)(sm + (nxt ? SM_M1 : SM_M0));
            #pragma unroll
            for (int i = 0; i < 6; i++) {
                int idx = tid + i * 256;
                int r = idx / 24, q = (idx % 24) * 8;
                *(uint4*)(Kn + r * KSP + q) = pk[i];
            }
            #pragma unroll
            for (int i = 0; i < 2; i++) {
                int idx = tid + i * 256;
                int r = idx >> 3, q = (idx & 7) * 8;
                *(uint4*)(Vn + r * VSP + q) = pv2[i];
            }
            if (tid < KB) Mn[tid] = pmv;
        }
        __syncthreads();
    }

    // ---- normalize + write (b, n, h*64+d) ----
    const float inv0 = 1.0f / lr0, inv1 = 1.0f / lr1;
    const int r0 = i0 + warp * 16 + g;
    float* ob = g_att + ((size_t)b * NSEQ + r0) * DIM + h * 64;
    #pragma unroll
    for (int nt = 0; nt < 8; nt++) {
        int col = nt * 8 + 2 * t;
        *(float2*)(ob + col) = make_float2(Oa[nt][0] * inv0, Oa[nt][1] * inv0);
        *(float2*)(ob + 8 * DIM + col) = make_float2(Oa[nt][2] * inv1, Oa[nt][3] * inv1);
    }
}

// ---------------- converters (unchanged) --------------------------------------
__global__ void split_p1(const float* __restrict__ in, __nv_bfloat16* __restrict__ out,
                         int K, size_t total)
{
    size_t idx = (size_t)blockIdx.x * 256 + threadIdx.x;
    if (idx >= total) return;
    size_t r = idx / K; int k = (int)(idx % K);
    float x = in[idx];
    __nv_bfloat16 hi = __float2bfloat16(x);
    __nv_bfloat16 lo = __float2bfloat16(x - __bfloat162float(hi));
    __nv_bfloat16* o = out + r * (size_t)(3 * K);
    o[k] = hi; o[K + k] = lo; o[2 * K + k] = hi;
}

__global__ __launch_bounds__(256) void splitT_p2(const float* __restrict__ W,
                                                 __nv_bfloat16* __restrict__ out,
                                                 int Kd, int Nd)
{
    __shared__ float ts[32][33];
    int k0 = blockIdx.x * 32, n0 = blockIdx.y * 32;
    int tx = threadIdx.x & 31, ty = threadIdx.x >> 5;
    for (int r = ty; r < 32; r += 8) ts[r][tx] = W[(size_t)(k0 + r) * Nd + n0 + tx];
    __syncthreads();
    for (int r = ty; r < 32; r += 8) {
        float x = ts[tx][r];
        __nv_bfloat16 hi = __float2bfloat16(x);
        __nv_bfloat16 lo = __float2bfloat16(x - __bfloat162float(hi));
        __nv_bfloat16* o = out + (size_t)(n0 + r) * (3 * Kd) + k0 + tx;
        o[0] = hi; o[Kd] = hi; o[2 * Kd] = lo;
    }
}

__global__ void w_split(const float* __restrict__ w,
                        __nv_bfloat16* __restrict__ wA, __nv_bfloat16* __restrict__ wB)
{
    size_t idx = (size_t)blockIdx.x * 256 + threadIdx.x;
    float v = w[idx];
    int c = (int)(idx & 1023);
    size_t bn = idx >> 10;
    int n = (int)(bn & 2047), b = (int)(bn >> 11);
    int h = c >> 6, kk = c & 63;
    size_t base = (((size_t)(b * 16 + h)) * NSEQ + n) * 192;
    float sv = v * 0.125f;
    __nv_bfloat16 hiA = __float2bfloat16(sv);
    __nv_bfloat16 loA = __float2bfloat16(sv - __bfloat162float(hiA));
    __nv_bfloat16 hiB = __float2bfloat16(v);
    __nv_bfloat16 loB = __float2bfloat16(v - __bfloat162float(hiB));
    wA[base + kk] = hiA; wA[base + 64 + kk] = loA; wA[base + 128 + kk] = hiA;
    wB[base + kk] = hiB; wB[base + 64 + kk] = hiB; wB[base + 128 + kk] = loB;
}

__global__ __launch_bounds__(256) void vt_trans(const float* __restrict__ w,
                                                __half* __restrict__ vt)
{
    __shared__ float ts[64][65];
    int j0 = blockIdx.x * 64, bh = blockIdx.y;
    int b = bh >> 4, h = bh & 15;
    const float* base = w + (size_t)b * NSEQ * DIM + h * 64;
    for (int idx = threadIdx.x; idx < 64 * 16; idx += 256) {
        int jj = idx >> 4, i = idx & 15;
        float4 v = *(const float4*)(base + (size_t)(j0 + jj) * DIM + i * 4);
        ts[jj][i*4] = v.x; ts[jj][i*4+1] = v.y; ts[jj][i*4+2] = v.z; ts[jj][i*4+3] = v.w;
    }
    __syncthreads();
    __half* o = vt + (size_t)bh * 64 * NSEQ + j0;
    for (int idx = threadIdx.x; idx < 64 * 64; idx += 256) {
        int d = idx >> 6, jj = idx & 63;
        o[(size_t)d * NSEQ + jj] = __float2half_rn(ts[jj][d]);
    }
}

// ---------------- launch ------------------------------------------------------
extern "C" void kernel_launch(void* const* d_in, const int* in_sizes, int n_in,
                              void* d_out, int out_size)
{
    const float* x    = (const float*)d_in[0];
    const int*   mask = (const int*)d_in[1];
    const float* Wqkv = (const float*)d_in[2];
    const float* Wout = (const float*)d_in[3];
    const float* bout = (const float*)d_in[4];
    float*       out  = (float*)d_out;

    float *wp, *ap;
    __nv_bfloat16 *xs, *atts, *w1s, *w2s, *wA, *wB;
    __half *vt;
    cudaGetSymbolAddress((void**)&wp,   g_w);
    cudaGetSymbolAddress((void**)&ap,   g_att);
    cudaGetSymbolAddress((void**)&xs,   g_xs);
    cudaGetSymbolAddress((void**)&atts, g_atts);
    cudaGetSymbolAddress((void**)&w1s,  g_w1s);
    cudaGetSymbolAddress((void**)&w2s,  g_w2s);
    cudaGetSymbolAddress((void**)&wA,   g_wA);
    cudaGetSymbolAddress((void**)&wB,   g_wB);
    cudaGetSymbolAddress((void**)&vt,   g_vt);

    cudaFuncSetAttribute(flash_attn, cudaFuncAttributeMaxDynamicSharedMemorySize, SM_TOT);

    split_p1<<<(BATCH*NSEQ*DIM + 255) / 256, 256>>>(x, xs, DIM, (size_t)BATCH*NSEQ*DIM);
    splitT_p2<<<dim3(DIM/32, DIM/32), 256>>>(Wqkv, w1s, DIM, DIM);
    splitT_p2<<<dim3(DIM/32, DIM/32), 256>>>(Wout, w2s, DIM, DIM);

    // stage 1: w = x @ Wqkv
    mma_gemm<128, true><<<dim3(DIM/128, (BATCH*NSEQ)/128, 1), 256>>>(
        (const uint16_t*)xs, 0, 3*DIM, (const uint16_t*)w1s, 0, 3*DIM,
        wp, DIM, 0, 0, 1, 3*DIM, nullptr);

    w_split<<<(BATCH*NSEQ*DIM)/256, 256>>>(wp, wA, wB);
    vt_trans<<<dim3(NSEQ/64, BH), 256>>>(wp, vt);

    // stage 2+3: fused flash attention -> g_att
    flash_attn<<<dim3(NSEQ/128, BH), 256, SM_TOT>>>(mask);

    // stage 4: out = att @ Wout + bout
    split_p1<<<(BATCH*NSEQ*DIM + 255) / 256, 256>>>(ap, atts, DIM, (size_t)BATCH*NSEQ*DIM);
    mma_gemm<128, true><<<dim3(DIM/128, (BATCH*NSEQ)/128, 1), 256>>>(
        (const uint16_t*)atts, 0, 3*DIM, (const uint16_t*)w2s, 0, 3*DIM,
        out, DIM, 0, 0, 1, 3*DIM, bout);
}

// round 6
// speedup vs baseline: 2.9381x; 1.1644x over previous
#include <cuda_runtime.h>
#include <cuda_bf16.h>
#include <cuda_fp16.h>
#include <cstdint>

#define HEADS 16
#define DHEAD 64
#define BATCH 2
#define NSEQ  2048
#define DIM   1024
#define BH    (BATCH*HEADS)

// ---------------- scratch (__device__ globals; allocation-free) -------------
__device__ __align__(256) float         g_w  [(size_t)BATCH*NSEQ*DIM];
__device__ __align__(256) float         g_att[(size_t)BATCH*NSEQ*DIM];
__device__ __align__(256) __nv_bfloat16 g_xs  [(size_t)BATCH*NSEQ*3*DIM];
__device__ __align__(256) __nv_bfloat16 g_atts[(size_t)BATCH*NSEQ*3*DIM];
__device__ __align__(256) __nv_bfloat16 g_w1s [(size_t)DIM*3*DIM];
__device__ __align__(256) __nv_bfloat16 g_w2s [(size_t)DIM*3*DIM];
__device__ __align__(256) __nv_bfloat16 g_wA  [(size_t)BH*NSEQ*192];
__device__ __align__(256) __nv_bfloat16 g_wB  [(size_t)BH*NSEQ*192];
__device__ __align__(256) __half        g_vt  [(size_t)BH*DHEAD*NSEQ];

// ---------------- PTX helpers -------------------------------------------------
__device__ __forceinline__ void mma_bf16(float* d, const uint32_t* a, const uint32_t* b) {
    asm volatile(
        "mma.sync.aligned.m16n8k16.row.col.f32.bf16.bf16.f32 "
        "{%0,%1,%2,%3}, {%4,%5,%6,%7}, {%8,%9}, {%0,%1,%2,%3};"
        : "+f"(d[0]), "+f"(d[1]), "+f"(d[2]), "+f"(d[3])
        : "r"(a[0]), "r"(a[1]), "r"(a[2]), "r"(a[3]), "r"(b[0]), "r"(b[1]));
}
__device__ __forceinline__ void mma_f16(float* d, const uint32_t* a, const uint32_t* b) {
    asm volatile(
        "mma.sync.aligned.m16n8k16.row.col.f32.f16.f16.f32 "
        "{%0,%1,%2,%3}, {%4,%5,%6,%7}, {%8,%9}, {%0,%1,%2,%3};"
        : "+f"(d[0]), "+f"(d[1]), "+f"(d[2]), "+f"(d[3])
        : "r"(a[0]), "r"(a[1]), "r"(a[2]), "r"(a[3]), "r"(b[0]), "r"(b[1]));
}
__device__ __forceinline__ uint32_t cvta_s(const void* p) {
    return (uint32_t)__cvta_generic_to_shared(p);
}
#define CP_ASYNC16(dst, src) \
    asm volatile("cp.async.cg.shared.global [%0], [%1], 16;" :: "r"(dst), "l"(src))
#define CP_COMMIT() asm volatile("cp.async.commit_group;")
#define CP_WAIT(n)  asm volatile("cp.async.wait_group %0;" :: "n"(n))
#define LDMX4(r0, r1, r2, r3, addr) \
    asm volatile("ldmatrix.sync.aligned.m8n8.x4.shared.b16 {%0,%1,%2,%3}, [%4];" \
        : "=r"(r0), "=r"(r1), "=r"(r2), "=r"(r3) : "r"(addr))

// ---------------------------------------------------------------------------
// HMMA GEMM, cp.async 4-stage pipeline + ldmatrix fragments.
// C[m,n] = sum_k A[m,k]*B[n,k] (+bias[n]); A,B bf16 K-major; K mult of 32.
// Tile 128x128, 256 threads (2x4 warps, 64x32 warp tiles).
// ---------------------------------------------------------------------------
#define GP   40      // halfs per smem row
#define GSTG 4

__global__ __launch_bounds__(256, 2) void mma_gemm(
    const uint16_t* __restrict__ A, int lda,
    const uint16_t* __restrict__ B, int ldb,
    float* __restrict__ C, int ldc, int K, const float* __restrict__ bias)
{
    extern __shared__ __align__(16) uint16_t gsm[];   // GSTG stages of (128 A + 128 B) rows
    const int tid = threadIdx.x, lane = tid & 31, warp = tid >> 5;
    const int g = lane >> 2, t = lane & 3;
    const int wm0 = (warp >> 2) * 64, wn0 = (warp & 3) * 32;
    const int m0 = blockIdx.y * 128, n0 = blockIdx.x * 128;

    const uint16_t* Ab = A + (size_t)m0 * lda;
    const uint16_t* Bb = B + (size_t)n0 * ldb;
    const uint32_t smb = cvta_s(gsm);

    float acc[4][4][4] = {};
    const int NC = K >> 5;

    auto issue = [&](int c) {
        const uint32_t dst = smb + (uint32_t)(c % GSTG) * (256 * GP * 2);
        const uint16_t* ag = Ab + c * 32;
        const uint16_t* bg = Bb + c * 32;
        #pragma unroll
        for (int i = 0; i < 2; i++) {
            int idx = tid + i * 256;
            int r = idx >> 2, q = (idx & 3) * 8;
            CP_ASYNC16(dst + (uint32_t)(r * GP + q) * 2, ag + (size_t)r * lda + q);
        }
        #pragma unroll
        for (int i = 0; i < 2; i++) {
            int idx = tid + i * 256;
            int r = idx >> 2, q = (idx & 3) * 8;
            CP_ASYNC16(dst + (uint32_t)((128 + r) * GP + q) * 2, bg + (size_t)r * ldb + q);
        }
        CP_COMMIT();
    };

    #pragma unroll
    for (int s = 0; s < GSTG - 1; s++) issue(s);   // NC >= 3 always here

    for (int c = 0; c < NC; c++) {
        CP_WAIT(GSTG - 2);
        __syncthreads();
        if (c + GSTG - 1 < NC) issue(c + GSTG - 1);
        else                   CP_COMMIT();        // empty group keeps accounting exact

        const uint32_t asv = smb + (uint32_t)(c % GSTG) * (256 * GP * 2);
        const uint32_t bsv = asv + 128 * GP * 2;

        #pragma unroll
        for (int ks = 0; ks < 2; ks++) {
            const int kb = ks * 16;
            uint32_t bf[4][2];
            #pragma unroll
            for (int ni2 = 0; ni2 < 2; ni2++) {
                uint32_t r0, r1, r2, r3;
                uint32_t addr = bsv + (uint32_t)(((wn0 + ni2 * 16 + ((lane >> 4) << 3) + (lane & 7)) * GP
                                                 + kb + ((lane >> 3) & 1) * 8) << 1);
                LDMX4(r0, r1, r2, r3, addr);
                bf[ni2 * 2][0] = r0; bf[ni2 * 2][1] = r1;
                bf[ni2 * 2 + 1][0] = r2; bf[ni2 * 2 + 1][1] = r3;
            }
            #pragma unroll
            for (int mi = 0; mi < 4; mi++) {
                uint32_t af[4];
                uint32_t addr = asv + (uint32_t)(((wm0 + mi * 16 + (lane & 15)) * GP
                                                 + kb + (lane >> 4) * 8) << 1);
                LDMX4(af[0], af[1], af[2], af[3], addr);
                #pragma unroll
                for (int ni = 0; ni < 4; ni++) mma_bf16(acc[mi][ni], af, bf[ni]);
            }
        }
    }

    float* Cb = C + (size_t)m0 * ldc + n0;
    #pragma unroll
    for (int mi = 0; mi < 4; mi++) {
        #pragma unroll
        for (int ni = 0; ni < 4; ni++) {
            int col = wn0 + ni * 8 + 2 * t;
            float bx = 0.0f, by = 0.0f;
            if (bias) { bx = bias[n0 + col]; by = bias[n0 + col + 1]; }
            int r1 = wm0 + mi * 16 + g;
            *(float2*)(Cb + (size_t)r1 * ldc + col) =
                make_float2(acc[mi][ni][0] + bx, acc[mi][ni][1] + by);
            *(float2*)(Cb + (size_t)(r1 + 8) * ldc + col) =
                make_float2(acc[mi][ni][2] + bx, acc[mi][ni][3] + by);
        }
    }
}

// ---------------------------------------------------------------------------
// Fused flash attention (cp.async double buffer + ldmatrix K/V fragments).
// CTA = 128 q-rows of one (b,h); 8 warps x 16 rows.
// ---------------------------------------------------------------------------
#define KB    64
#define NIT   (NSEQ / KB)
#define KSP   200    // halfs per K-row (400B; mod128 = 16 -> ldmatrix conflict-free)
#define VSP   72     // halfs per Vt-row (144B; mod128 = 16)
#define SM_K0 0
#define SM_K1 25600
#define SM_V0 51200
#define SM_V1 60416
#define SM_M0 69632
#define SM_M1 69888
#define SM_TOT 70144

__global__ __launch_bounds__(256, 1) void flash_attn(const int* __restrict__ mask)
{
    extern __shared__ char sm[];
    const int tid = threadIdx.x, lane = tid & 31, warp = tid >> 5;
    const int g = lane >> 2, t = lane & 3;
    const int i0 = blockIdx.x * 128;
    const int bh = blockIdx.y;
    const int b = bh >> 4, h = bh & 15;

    const uint16_t* wA = (const uint16_t*)g_wA + (size_t)bh * NSEQ * 192;
    const uint16_t* wB = (const uint16_t*)g_wB + (size_t)bh * NSEQ * 192;
    const uint16_t* vt = (const uint16_t*)g_vt + (size_t)bh * DHEAD * NSEQ;
    const int* mrow = mask + (size_t)b * NSEQ;
    const uint32_t smb = cvta_s(sm);

    auto issue = [&](int it2, int buf) {
        const int j0 = it2 * KB;
        const uint32_t kd = smb + (buf ? SM_K1 : SM_K0);
        const uint32_t vd = smb + (buf ? SM_V1 : SM_V0);
        const uint32_t md = smb + (buf ? SM_M1 : SM_M0);
        #pragma unroll
        for (int i = 0; i < 6; i++) {
            int idx = tid + i * 256;
            int r = idx / 24, q = (idx % 24) * 8;
            CP_ASYNC16(kd + (uint32_t)(r * KSP + q) * 2, wB + (size_t)(j0 + r) * 192 + q);
        }
        #pragma unroll
        for (int i = 0; i < 2; i++) {
            int idx = tid + i * 256;
            int r = idx >> 3, q = (idx & 7) * 8;
            CP_ASYNC16(vd + (uint32_t)(r * VSP + q) * 2, vt + (size_t)r * NSEQ + j0 + q);
        }
        if (tid < 16) CP_ASYNC16(md + tid * 16, mrow + j0 + tid * 4);
        CP_COMMIT();
    };

    // Q fragments: rows i0 + warp*16 + {g, g+8}, 12 k16 tiles over split-192
    uint32_t qa[12][4];
    {
        const uint16_t* q0 = wA + (size_t)(i0 + warp * 16 + g) * 192 + 2 * t;
        #pragma unroll
        for (int kt = 0; kt < 12; kt++) {
            qa[kt][0] = *(const uint32_t*)(q0 + kt * 16);
            qa[kt][1] = *(const uint32_t*)(q0 + kt * 16 + 8 * 192);
            qa[kt][2] = *(const uint32_t*)(q0 + kt * 16 + 8);
            qa[kt][3] = *(const uint32_t*)(q0 + kt * 16 + 8 * 192 + 8);
        }
    }

    float Oa[8][4] = {};
    float mr0 = -1e30f, mr1 = -1e30f, lr0 = 0.0f, lr1 = 0.0f;

    issue(0, 0);
    CP_WAIT(0);
    __syncthreads();

    for (int it = 0; it < NIT; it++) {
        const int cur = it & 1;
        const uint32_t ksv = smb + (cur ? SM_K1 : SM_K0);
        const uint32_t vsv = smb + (cur ? SM_V1 : SM_V0);
        const int* Mi = (const int*)(sm + (cur ? SM_M1 : SM_M0));

        if (it + 1 < NIT) issue(it + 1, cur ^ 1);
        else              CP_COMMIT();

        // ---- S tile: 16 rows x 64 keys, split K'=192 ----
        float sa[8][4] = {};
        #pragma unroll
        for (int kt = 0; kt < 12; kt++) {
            #pragma unroll
            for (int nt2 = 0; nt2 < 4; nt2++) {
                uint32_t r0, r1, r2, r3;
                uint32_t addr = ksv + (uint32_t)(((nt2 * 16 + ((lane >> 4) << 3) + (lane & 7)) * KSP
                                                 + kt * 16 + ((lane >> 3) & 1) * 8) << 1);
                LDMX4(r0, r1, r2, r3, addr);
                uint32_t b0[2] = {r0, r1}, b1[2] = {r2, r3};
                mma_bf16(sa[nt2 * 2],     qa[kt], b0);
                mma_bf16(sa[nt2 * 2 + 1], qa[kt], b1);
            }
        }

        // ---- online softmax (rows g and g+8; quad-lane reductions) ----
        float bm0 = -1e30f, bm1 = -1e30f;
        #pragma unroll
        for (int nt = 0; nt < 8; nt++) {
            bm0 = fmaxf(bm0, fmaxf(sa[nt][0], sa[nt][1]));
            bm1 = fmaxf(bm1, fmaxf(sa[nt][2], sa[nt][3]));
        }
        bm0 = fmaxf(bm0, __shfl_xor_sync(0xffffffffu, bm0, 1));
        bm0 = fmaxf(bm0, __shfl_xor_sync(0xffffffffu, bm0, 2));
        bm1 = fmaxf(bm1, __shfl_xor_sync(0xffffffffu, bm1, 1));
        bm1 = fmaxf(bm1, __shfl_xor_sync(0xffffffffu, bm1, 2));

        const float mn0 = fmaxf(mr0, bm0), mn1 = fmaxf(mr1, bm1);
        const float sf0 = __expf(mr0 - mn0), sf1 = __expf(mr1 - mn1);
        mr0 = mn0; mr1 = mn1;

        float rs0 = 0.0f, rs1 = 0.0f;
        #pragma unroll
        for (int nt = 0; nt < 8; nt++) {
            sa[nt][0] = __expf(sa[nt][0] - mn0);
            sa[nt][1] = __expf(sa[nt][1] - mn0);
            sa[nt][2] = __expf(sa[nt][2] - mn1);
            sa[nt][3] = __expf(sa[nt][3] - mn1);
            rs0 += sa[nt][0] + sa[nt][1];
            rs1 += sa[nt][2] + sa[nt][3];
        }
        rs0 += __shfl_xor_sync(0xffffffffu, rs0, 1);
        rs0 += __shfl_xor_sync(0xffffffffu, rs0, 2);
        rs1 += __shfl_xor_sync(0xffffffffu, rs1, 1);
        rs1 += __shfl_xor_sync(0xffffffffu, rs1, 2);
        lr0 = lr0 * sf0 + rs0;
        lr1 = lr1 * sf1 + rs1;

        #pragma unroll
        for (int nt = 0; nt < 8; nt++) {
            Oa[nt][0] *= sf0; Oa[nt][1] *= sf0;
            Oa[nt][2] *= sf1; Oa[nt][3] *= sf1;
        }

        // ---- mask + repack P into f16 A-fragments ----
        uint32_t pfra[4][4];
        #pragma unroll
        for (int kt2 = 0; kt2 < 4; kt2++) {
            const int n0t = 2 * kt2, n1t = 2 * kt2 + 1;
            int2 mi0 = *(const int2*)&Mi[n0t * 8 + 2 * t];
            int2 mi1 = *(const int2*)&Mi[n1t * 8 + 2 * t];
            float m0x = 1.0f - (float)mi0.x, m0y = 1.0f - (float)mi0.y;
            float m1x = 1.0f - (float)mi1.x, m1y = 1.0f - (float)mi1.y;
            __half2 a0 = __floats2half2_rn(sa[n0t][0] * m0x, sa[n0t][1] * m0y);
            __half2 a1 = __floats2half2_rn(sa[n0t][2] * m0x, sa[n0t][3] * m0y);
            __half2 a2 = __floats2half2_rn(sa[n1t][0] * m1x, sa[n1t][1] * m1y);
            __half2 a3 = __floats2half2_rn(sa[n1t][2] * m1x, sa[n1t][3] * m1y);
            pfra[kt2][0] = *(uint32_t*)&a0;
            pfra[kt2][1] = *(uint32_t*)&a1;
            pfra[kt2][2] = *(uint32_t*)&a2;
            pfra[kt2][3] = *(uint32_t*)&a3;
        }

        // ---- O += P @ V  (V^T tile [d][j]) ----
        #pragma unroll
        for (int nt2 = 0; nt2 < 4; nt2++) {
            #pragma unroll
            for (int kt2 = 0; kt2 < 4; kt2++) {
                uint32_t r0, r1, r2, r3;
                uint32_t addr = vsv + (uint32_t)(((nt2 * 16 + ((lane >> 4) << 3) + (lane & 7)) * VSP
                                                 + kt2 * 16 + ((lane >> 3) & 1) * 8) << 1);
                LDMX4(r0, r1, r2, r3, addr);
                uint32_t b0[2] = {r0, r1}, b1[2] = {r2, r3};
                mma_f16(Oa[nt2 * 2],     pfra[kt2], b0);
                mma_f16(Oa[nt2 * 2 + 1], pfra[kt2], b1);
            }
        }

        CP_WAIT(0);
        __syncthreads();
    }

    // ---- normalize + write (b, n, h*64+d) ----
    const float inv0 = 1.0f / lr0, inv1 = 1.0f / lr1;
    const int r0 = i0 + warp * 16 + g;
    float* ob = g_att + ((size_t)b * NSEQ + r0) * DIM + h * 64;
    #pragma unroll
    for (int nt = 0; nt < 8; nt++) {
        int col = nt * 8 + 2 * t;
        *(float2*)(ob + col) = make_float2(Oa[nt][0] * inv0, Oa[nt][1] * inv0);
        *(float2*)(ob + 8 * DIM + col) = make_float2(Oa[nt][2] * inv1, Oa[nt][3] * inv1);
    }
}

// ---------------- converters (unchanged, validated) ---------------------------
__global__ void split_p1(const float* __restrict__ in, __nv_bfloat16* __restrict__ out,
                         int K, size_t total)
{
    size_t idx = (size_t)blockIdx.x * 256 + threadIdx.x;
    if (idx >= total) return;
    size_t r = idx / K; int k = (int)(idx % K);
    float x = in[idx];
    __nv_bfloat16 hi = __float2bfloat16(x);
    __nv_bfloat16 lo = __float2bfloat16(x - __bfloat162float(hi));
    __nv_bfloat16* o = out + r * (size_t)(3 * K);
    o[k] = hi; o[K + k] = lo; o[2 * K + k] = hi;
}

__global__ __launch_bounds__(256) void splitT_p2(const float* __restrict__ W,
                                                 __nv_bfloat16* __restrict__ out,
                                                 int Kd, int Nd)
{
    __shared__ float ts[32][33];
    int k0 = blockIdx.x * 32, n0 = blockIdx.y * 32;
    int tx = threadIdx.x & 31, ty = threadIdx.x >> 5;
    for (int r = ty; r < 32; r += 8) ts[r][tx] = W[(size_t)(k0 + r) * Nd + n0 + tx];
    __syncthreads();
    for (int r = ty; r < 32; r += 8) {
        float x = ts[tx][r];
        __nv_bfloat16 hi = __float2bfloat16(x);
        __nv_bfloat16 lo = __float2bfloat16(x - __bfloat162float(hi));
        __nv_bfloat16* o = out + (size_t)(n0 + r) * (3 * Kd) + k0 + tx;
        o[0] = hi; o[Kd] = hi; o[2 * Kd] = lo;
    }
}

__global__ void w_split(const float* __restrict__ w,
                        __nv_bfloat16* __restrict__ wA, __nv_bfloat16* __restrict__ wB)
{
    size_t idx = (size_t)blockIdx.x * 256 + threadIdx.x;
    float v = w[idx];
    int c = (int)(idx & 1023);
    size_t bn = idx >> 10;
    int n = (int)(bn & 2047), b = (int)(bn >> 11);
    int h = c >> 6, kk = c & 63;
    size_t base = (((size_t)(b * 16 + h)) * NSEQ + n) * 192;
    float sv = v * 0.125f;
    __nv_bfloat16 hiA = __float2bfloat16(sv);
    __nv_bfloat16 loA = __float2bfloat16(sv - __bfloat162float(hiA));
    __nv_bfloat16 hiB = __float2bfloat16(v);
    __nv_bfloat16 loB = __float2bfloat16(v - __bfloat162float(hiB));
    wA[base + kk] = hiA; wA[base + 64 + kk] = loA; wA[base + 128 + kk] = hiA;
    wB[base + kk] = hiB; wB[base + 64 + kk] = hiB; wB[base + 128 + kk] = loB;
}

__global__ __launch_bounds__(256) void vt_trans(const float* __restrict__ w,
                                                __half* __restrict__ vt)
{
    __shared__ float ts[64][65];
    int j0 = blockIdx.x * 64, bh = blockIdx.y;
    int b = bh >> 4, h = bh & 15;
    const float* base = w + (size_t)b * NSEQ * DIM + h * 64;
    for (int idx = threadIdx.x; idx < 64 * 16; idx += 256) {
        int jj = idx >> 4, i = idx & 15;
        float4 v = *(const float4*)(base + (size_t)(j0 + jj) * DIM + i * 4);
        ts[jj][i*4] = v.x; ts[jj][i*4+1] = v.y; ts[jj][i*4+2] = v.z; ts[jj][i*4+3] = v.w;
    }
    __syncthreads();
    __half* o = vt + (size_t)bh * 64 * NSEQ + j0;
    for (int idx = threadIdx.x; idx < 64 * 64; idx += 256) {
        int d = idx >> 6, jj = idx & 63;
        o[(size_t)d * NSEQ + jj] = __float2half_rn(ts[jj][d]);
    }
}

// ---------------- launch ------------------------------------------------------
extern "C" void kernel_launch(void* const* d_in, const int* in_sizes, int n_in,
                              void* d_out, int out_size)
{
    const float* x    = (const float*)d_in[0];
    const int*   mask = (const int*)d_in[1];
    const float* Wqkv = (const float*)d_in[2];
    const float* Wout = (const float*)d_in[3];
    const float* bout = (const float*)d_in[4];
    float*       out  = (float*)d_out;

    float *wp, *ap;
    __nv_bfloat16 *xs, *atts, *w1s, *w2s;
    cudaGetSymbolAddress((void**)&wp,   g_w);
    cudaGetSymbolAddress((void**)&ap,   g_att);
    cudaGetSymbolAddress((void**)&xs,   g_xs);
    cudaGetSymbolAddress((void**)&atts, g_atts);
    cudaGetSymbolAddress((void**)&w1s,  g_w1s);
    cudaGetSymbolAddress((void**)&w2s,  g_w2s);
    __nv_bfloat16 *wA, *wB; __half *vt;
    cudaGetSymbolAddress((void**)&wA, g_wA);
    cudaGetSymbolAddress((void**)&wB, g_wB);
    cudaGetSymbolAddress((void**)&vt, g_vt);

    const int GEMM_SMEM = GSTG * 256 * GP * 2;   // 81920
    cudaFuncSetAttribute(mma_gemm, cudaFuncAttributeMaxDynamicSharedMemorySize, GEMM_SMEM);
    cudaFuncSetAttribute(flash_attn, cudaFuncAttributeMaxDynamicSharedMemorySize, SM_TOT);

    split_p1<<<(BATCH*NSEQ*DIM + 255) / 256, 256>>>(x, xs, DIM, (size_t)BATCH*NSEQ*DIM);
    splitT_p2<<<dim3(DIM/32, DIM/32), 256>>>(Wqkv, w1s, DIM, DIM);
    splitT_p2<<<dim3(DIM/32, DIM/32), 256>>>(Wout, w2s, DIM, DIM);

    // stage 1: w = x @ Wqkv  (M=4096, N=1024, K'=3072)
    mma_gemm<<<dim3(DIM/128, (BATCH*NSEQ)/128), 256, GEMM_SMEM>>>(
        (const uint16_t*)xs, 3*DIM, (const uint16_t*)w1s, 3*DIM, wp, DIM, 3*DIM, nullptr);

    w_split<<<(BATCH*NSEQ*DIM)/256, 256>>>(wp, wA, wB);
    vt_trans<<<dim3(NSEQ/64, BH), 256>>>(wp, vt);

    // stage 2+3: fused flash attention -> g_att
    flash_attn<<<dim3(NSEQ/128, BH), 256, SM_TOT>>>(mask);

    // stage 4: out = att @ Wout + bout
    split_p1<<<(BATCH*NSEQ*DIM + 255) / 256, 256>>>(ap, atts, DIM, (size_t)BATCH*NSEQ*DIM);
    mma_gemm<<<dim3(DIM/128, (BATCH*NSEQ)/128), 256, GEMM_SMEM>>>(
        (const uint16_t*)atts, 3*DIM, (const uint16_t*)w2s, 3*DIM, out, DIM, 3*DIM, bout);
}

// round 7
// speedup vs baseline: 3.1080x; 1.0578x over previous
#include <cuda_runtime.h>
#include <cuda_bf16.h>
#include <cuda_fp16.h>
#include <cstdint>

#define HEADS 16
#define DHEAD 64
#define BATCH 2
#define NSEQ  2048
#define DIM   1024
#define BH    (BATCH*HEADS)

// ---------------- scratch (__device__ globals; allocation-free) -------------
__device__ __align__(256) float         g_w  [(size_t)BATCH*NSEQ*DIM];
__device__ __align__(256) __nv_bfloat16 g_xs  [(size_t)BATCH*NSEQ*3*DIM];
__device__ __align__(256) __nv_bfloat16 g_atts[(size_t)BATCH*NSEQ*3*DIM];
__device__ __align__(256) __nv_bfloat16 g_w1s [(size_t)DIM*3*DIM];
__device__ __align__(256) __nv_bfloat16 g_w2s [(size_t)DIM*3*DIM];
__device__ __align__(256) __nv_bfloat16 g_wA  [(size_t)BH*NSEQ*128];   // [hi|lo], scaled
__device__ __align__(256) __nv_bfloat16 g_wB  [(size_t)BH*NSEQ*128];   // [hi|lo]
__device__ __align__(256) __half        g_vt  [(size_t)BH*DHEAD*NSEQ];

// ---------------- PTX helpers -------------------------------------------------
__device__ __forceinline__ void mma_bf16(float* d, const uint32_t* a, const uint32_t* b) {
    asm volatile(
        "mma.sync.aligned.m16n8k16.row.col.f32.bf16.bf16.f32 "
        "{%0,%1,%2,%3}, {%4,%5,%6,%7}, {%8,%9}, {%0,%1,%2,%3};"
        : "+f"(d[0]), "+f"(d[1]), "+f"(d[2]), "+f"(d[3])
        : "r"(a[0]), "r"(a[1]), "r"(a[2]), "r"(a[3]), "r"(b[0]), "r"(b[1]));
}
__device__ __forceinline__ void mma_f16(float* d, const uint32_t* a, const uint32_t* b) {
    asm volatile(
        "mma.sync.aligned.m16n8k16.row.col.f32.f16.f16.f32 "
        "{%0,%1,%2,%3}, {%4,%5,%6,%7}, {%8,%9}, {%0,%1,%2,%3};"
        : "+f"(d[0]), "+f"(d[1]), "+f"(d[2]), "+f"(d[3])
        : "r"(a[0]), "r"(a[1]), "r"(a[2]), "r"(a[3]), "r"(b[0]), "r"(b[1]));
}
__device__ __forceinline__ uint32_t cvta_s(const void* p) {
    return (uint32_t)__cvta_generic_to_shared(p);
}
#define CP_ASYNC16(dst, src) \
    asm volatile("cp.async.cg.shared.global [%0], [%1], 16;" :: "r"(dst), "l"(src))
#define CP_COMMIT() asm volatile("cp.async.commit_group;")
#define CP_WAIT(n)  asm volatile("cp.async.wait_group %0;" :: "n"(n))
#define LDMX4(r0, r1, r2, r3, addr) \
    asm volatile("ldmatrix.sync.aligned.m8n8.x4.shared.b16 {%0,%1,%2,%3}, [%4];" \
        : "=r"(r0), "=r"(r1), "=r"(r2), "=r"(r3) : "r"(addr))

// ---------------------------------------------------------------------------
// HMMA GEMM, cp.async 3-stage pipeline + ldmatrix. 2 CTAs/SM -> single wave.
// ---------------------------------------------------------------------------
#define GP   40
#define GSTG 3

__global__ __launch_bounds__(256, 2) void mma_gemm(
    const uint16_t* __restrict__ A, int lda,
    const uint16_t* __restrict__ B, int ldb,
    float* __restrict__ C, int ldc, int K, const float* __restrict__ bias)
{
    extern __shared__ __align__(16) uint16_t gsm[];
    const int tid = threadIdx.x, lane = tid & 31, warp = tid >> 5;
    const int g = lane >> 2, t = lane & 3;
    const int wm0 = (warp >> 2) * 64, wn0 = (warp & 3) * 32;
    const int m0 = blockIdx.y * 128, n0 = blockIdx.x * 128;

    const uint16_t* Ab = A + (size_t)m0 * lda;
    const uint16_t* Bb = B + (size_t)n0 * ldb;
    const uint32_t smb = cvta_s(gsm);

    float acc[4][4][4] = {};
    const int NC = K >> 5;

    auto issue = [&](int c) {
        const uint32_t dst = smb + (uint32_t)(c % GSTG) * (256 * GP * 2);
        const uint16_t* ag = Ab + c * 32;
        const uint16_t* bg = Bb + c * 32;
        #pragma unroll
        for (int i = 0; i < 2; i++) {
            int idx = tid + i * 256;
            int r = idx >> 2, q = (idx & 3) * 8;
            CP_ASYNC16(dst + (uint32_t)(r * GP + q) * 2, ag + (size_t)r * lda + q);
        }
        #pragma unroll
        for (int i = 0; i < 2; i++) {
            int idx = tid + i * 256;
            int r = idx >> 2, q = (idx & 3) * 8;
            CP_ASYNC16(dst + (uint32_t)((128 + r) * GP + q) * 2, bg + (size_t)r * ldb + q);
        }
        CP_COMMIT();
    };

    #pragma unroll
    for (int s = 0; s < GSTG - 1; s++) issue(s);

    for (int c = 0; c < NC; c++) {
        CP_WAIT(GSTG - 2);
        __syncthreads();
        if (c + GSTG - 1 < NC) issue(c + GSTG - 1);
        else                   CP_COMMIT();

        const uint32_t asv = smb + (uint32_t)(c % GSTG) * (256 * GP * 2);
        const uint32_t bsv = asv + 128 * GP * 2;

        #pragma unroll
        for (int ks = 0; ks < 2; ks++) {
            const int kb = ks * 16;
            uint32_t bf[4][2];
            #pragma unroll
            for (int ni2 = 0; ni2 < 2; ni2++) {
                uint32_t r0, r1, r2, r3;
                uint32_t addr = bsv + (uint32_t)(((wn0 + ni2 * 16 + ((lane >> 4) << 3) + (lane & 7)) * GP
                                                 + kb + ((lane >> 3) & 1) * 8) << 1);
                LDMX4(r0, r1, r2, r3, addr);
                bf[ni2 * 2][0] = r0; bf[ni2 * 2][1] = r1;
                bf[ni2 * 2 + 1][0] = r2; bf[ni2 * 2 + 1][1] = r3;
            }
            #pragma unroll
            for (int mi = 0; mi < 4; mi++) {
                uint32_t af[4];
                uint32_t addr = asv + (uint32_t)(((wm0 + mi * 16 + (lane & 15)) * GP
                                                 + kb + (lane >> 4) * 8) << 1);
                LDMX4(af[0], af[1], af[2], af[3], addr);
                #pragma unroll
                for (int ni = 0; ni < 4; ni++) mma_bf16(acc[mi][ni], af, bf[ni]);
            }
        }
    }

    float* Cb = C + (size_t)m0 * ldc + n0;
    #pragma unroll
    for (int mi = 0; mi < 4; mi++) {
        #pragma unroll
        for (int ni = 0; ni < 4; ni++) {
            int col = wn0 + ni * 8 + 2 * t;
            float bx = 0.0f, by = 0.0f;
            if (bias) { bx = bias[n0 + col]; by = bias[n0 + col + 1]; }
            int r1 = wm0 + mi * 16 + g;
            *(float2*)(Cb + (size_t)r1 * ldc + col) =
                make_float2(acc[mi][ni][0] + bx, acc[mi][ni][1] + by);
            *(float2*)(Cb + (size_t)(r1 + 8) * ldc + col) =
                make_float2(acc[mi][ni][2] + bx, acc[mi][ni][3] + by);
        }
    }
}

// ---------------------------------------------------------------------------
// Fused flash attention. K/Q stored [hi|lo]; S = Qh*Kh + Ql*Kh + Qh*Kl.
// Writes split-bf16 atts directly ([hi|lo|hi] rows of 3*DIM).
// ---------------------------------------------------------------------------
#define KB    64
#define NIT   (NSEQ / KB)
#define KSP   136    // halfs per K-row (272B; mod128=16 -> conflict-free)
#define VSP   72
#define SM_K0 0
#define SM_K1 17408
#define SM_V0 34816
#define SM_V1 44032
#define SM_M0 53248
#define SM_M1 53504
#define SM_TOT 53760

__global__ __launch_bounds__(256, 1) void flash_attn(const int* __restrict__ mask)
{
    extern __shared__ char sm[];
    const int tid = threadIdx.x, lane = tid & 31, warp = tid >> 5;
    const int g = lane >> 2, t = lane & 3;
    const int i0 = blockIdx.x * 128;
    const int bh = blockIdx.y;
    const int b = bh >> 4, h = bh & 15;

    const uint16_t* wA = (const uint16_t*)g_wA + (size_t)bh * NSEQ * 128;
    const uint16_t* wB = (const uint16_t*)g_wB + (size_t)bh * NSEQ * 128;
    const uint16_t* vt = (const uint16_t*)g_vt + (size_t)bh * DHEAD * NSEQ;
    const int* mrow = mask + (size_t)b * NSEQ;
    const uint32_t smb = cvta_s(sm);

    auto issue = [&](int it2, int buf) {
        const int j0 = it2 * KB;
        const uint32_t kd = smb + (buf ? SM_K1 : SM_K0);
        const uint32_t vd = smb + (buf ? SM_V1 : SM_V0);
        const uint32_t md = smb + (buf ? SM_M1 : SM_M0);
        #pragma unroll
        for (int i = 0; i < 4; i++) {
            int idx = tid + i * 256;
            int r = idx >> 4, q = (idx & 15) * 8;
            CP_ASYNC16(kd + (uint32_t)(r * KSP + q) * 2, wB + (size_t)(j0 + r) * 128 + q);
        }
        #pragma unroll
        for (int i = 0; i < 2; i++) {
            int idx = tid + i * 256;
            int r = idx >> 3, q = (idx & 7) * 8;
            CP_ASYNC16(vd + (uint32_t)(r * VSP + q) * 2, vt + (size_t)r * NSEQ + j0 + q);
        }
        if (tid < 16) CP_ASYNC16(md + tid * 16, mrow + j0 + tid * 4);
        CP_COMMIT();
    };

    // Q fragments (rows i0+warp*16+{g,g+8}): 4 hi tiles + 4 lo tiles over 128 cols
    uint32_t qh[4][4], ql[4][4];
    {
        const uint16_t* q0 = wA + (size_t)(i0 + warp * 16 + g) * 128 + 2 * t;
        #pragma unroll
        for (int j = 0; j < 4; j++) {
            qh[j][0] = *(const uint32_t*)(q0 + j * 16);
            qh[j][1] = *(const uint32_t*)(q0 + j * 16 + 8 * 128);
            qh[j][2] = *(const uint32_t*)(q0 + j * 16 + 8);
            qh[j][3] = *(const uint32_t*)(q0 + j * 16 + 8 * 128 + 8);
            ql[j][0] = *(const uint32_t*)(q0 + 64 + j * 16);
            ql[j][1] = *(const uint32_t*)(q0 + 64 + j * 16 + 8 * 128);
            ql[j][2] = *(const uint32_t*)(q0 + 64 + j * 16 + 8);
            ql[j][3] = *(const uint32_t*)(q0 + 64 + j * 16 + 8 * 128 + 8);
        }
    }

    float Oa[8][4] = {};
    float mr0 = -1e30f, mr1 = -1e30f, lr0 = 0.0f, lr1 = 0.0f;

    issue(0, 0);
    CP_WAIT(0);
    __syncthreads();

    for (int it = 0; it < NIT; it++) {
        const int cur = it & 1;
        const uint32_t ksv = smb + (cur ? SM_K1 : SM_K0);
        const uint32_t vsv = smb + (cur ? SM_V1 : SM_V0);
        const int* Mi = (const int*)(sm + (cur ? SM_M1 : SM_M0));

        if (it + 1 < NIT) issue(it + 1, cur ^ 1);
        else              CP_COMMIT();

        // ---- S tile: Qh*Kh + Ql*Kh + Qh*Kl (K fragment shared by first two) ----
        float sa[8][4] = {};
        #pragma unroll
        for (int j = 0; j < 4; j++) {
            #pragma unroll
            for (int nt2 = 0; nt2 < 4; nt2++) {
                const uint32_t rowoff =
                    (uint32_t)((nt2 * 16 + ((lane >> 4) << 3) + (lane & 7)) * KSP
                               + ((lane >> 3) & 1) * 8);
                uint32_t r0, r1, r2, r3;
                LDMX4(r0, r1, r2, r3, ksv + ((rowoff + j * 16) << 1));
                uint32_t b0[2] = {r0, r1}, b1[2] = {r2, r3};
                mma_bf16(sa[nt2 * 2],     qh[j], b0);
                mma_bf16(sa[nt2 * 2 + 1], qh[j], b1);
                mma_bf16(sa[nt2 * 2],     ql[j], b0);
                mma_bf16(sa[nt2 * 2 + 1], ql[j], b1);
                LDMX4(r0, r1, r2, r3, ksv + ((rowoff + 64 + j * 16) << 1));
                uint32_t c0[2] = {r0, r1}, c1[2] = {r2, r3};
                mma_bf16(sa[nt2 * 2],     qh[j], c0);
                mma_bf16(sa[nt2 * 2 + 1], qh[j], c1);
            }
        }

        // ---- online softmax ----
        float bm0 = -1e30f, bm1 = -1e30f;
        #pragma unroll
        for (int nt = 0; nt < 8; nt++) {
            bm0 = fmaxf(bm0, fmaxf(sa[nt][0], sa[nt][1]));
            bm1 = fmaxf(bm1, fmaxf(sa[nt][2], sa[nt][3]));
        }
        bm0 = fmaxf(bm0, __shfl_xor_sync(0xffffffffu, bm0, 1));
        bm0 = fmaxf(bm0, __shfl_xor_sync(0xffffffffu, bm0, 2));
        bm1 = fmaxf(bm1, __shfl_xor_sync(0xffffffffu, bm1, 1));
        bm1 = fmaxf(bm1, __shfl_xor_sync(0xffffffffu, bm1, 2));

        const float mn0 = fmaxf(mr0, bm0), mn1 = fmaxf(mr1, bm1);
        const float sf0 = __expf(mr0 - mn0), sf1 = __expf(mr1 - mn1);
        mr0 = mn0; mr1 = mn1;

        float rs0 = 0.0f, rs1 = 0.0f;
        #pragma unroll
        for (int nt = 0; nt < 8; nt++) {
            sa[nt][0] = __expf(sa[nt][0] - mn0);
            sa[nt][1] = __expf(sa[nt][1] - mn0);
            sa[nt][2] = __expf(sa[nt][2] - mn1);
            sa[nt][3] = __expf(sa[nt][3] - mn1);
            rs0 += sa[nt][0] + sa[nt][1];
            rs1 += sa[nt][2] + sa[nt][3];
        }
        rs0 += __shfl_xor_sync(0xffffffffu, rs0, 1);
        rs0 += __shfl_xor_sync(0xffffffffu, rs0, 2);
        rs1 += __shfl_xor_sync(0xffffffffu, rs1, 1);
        rs1 += __shfl_xor_sync(0xffffffffu, rs1, 2);
        lr0 = lr0 * sf0 + rs0;
        lr1 = lr1 * sf1 + rs1;

        #pragma unroll
        for (int nt = 0; nt < 8; nt++) {
            Oa[nt][0] *= sf0; Oa[nt][1] *= sf0;
            Oa[nt][2] *= sf1; Oa[nt][3] *= sf1;
        }

        // ---- mask + repack P ----
        uint32_t pfra[4][4];
        #pragma unroll
        for (int kt2 = 0; kt2 < 4; kt2++) {
            const int n0t = 2 * kt2, n1t = 2 * kt2 + 1;
            int2 mi0 = *(const int2*)&Mi[n0t * 8 + 2 * t];
            int2 mi1 = *(const int2*)&Mi[n1t * 8 + 2 * t];
            float m0x = 1.0f - (float)mi0.x, m0y = 1.0f - (float)mi0.y;
            float m1x = 1.0f - (float)mi1.x, m1y = 1.0f - (float)mi1.y;
            __half2 a0 = __floats2half2_rn(sa[n0t][0] * m0x, sa[n0t][1] * m0y);
            __half2 a1 = __floats2half2_rn(sa[n0t][2] * m0x, sa[n0t][3] * m0y);
            __half2 a2 = __floats2half2_rn(sa[n1t][0] * m1x, sa[n1t][1] * m1y);
            __half2 a3 = __floats2half2_rn(sa[n1t][2] * m1x, sa[n1t][3] * m1y);
            pfra[kt2][0] = *(uint32_t*)&a0;
            pfra[kt2][1] = *(uint32_t*)&a1;
            pfra[kt2][2] = *(uint32_t*)&a2;
            pfra[kt2][3] = *(uint32_t*)&a3;
        }

        // ---- O += P @ V ----
        #pragma unroll
        for (int nt2 = 0; nt2 < 4; nt2++) {
            #pragma unroll
            for (int kt2 = 0; kt2 < 4; kt2++) {
                uint32_t r0, r1, r2, r3;
                uint32_t addr = vsv + (uint32_t)(((nt2 * 16 + ((lane >> 4) << 3) + (lane & 7)) * VSP
                                                 + kt2 * 16 + ((lane >> 3) & 1) * 8) << 1);
                LDMX4(r0, r1, r2, r3, addr);
                uint32_t b0[2] = {r0, r1}, b1[2] = {r2, r3};
                mma_f16(Oa[nt2 * 2],     pfra[kt2], b0);
                mma_f16(Oa[nt2 * 2 + 1], pfra[kt2], b1);
            }
        }

        CP_WAIT(0);
        __syncthreads();
    }

    // ---- normalize + write split atts directly ([hi|lo|hi], row len 3*DIM) ----
    const float inv0 = 1.0f / lr0, inv1 = 1.0f / lr1;
    const int r0 = i0 + warp * 16 + g;
    __nv_bfloat16* ob = g_atts + ((size_t)b * NSEQ + r0) * (3 * DIM) + h * 64;
    __nv_bfloat16* ob8 = ob + (size_t)8 * (3 * DIM);
    #pragma unroll
    for (int nt = 0; nt < 8; nt++) {
        #pragma unroll
        for (int e = 0; e < 2; e++) {
            int col = nt * 8 + 2 * t + e;
            float v0 = Oa[nt][e] * inv0;
            __nv_bfloat16 h0 = __float2bfloat16(v0);
            __nv_bfloat16 l0 = __float2bfloat16(v0 - __bfloat162float(h0));
            ob[col] = h0; ob[DIM + col] = l0; ob[2 * DIM + col] = h0;
            float v1 = Oa[nt][2 + e] * inv1;
            __nv_bfloat16 h1 = __float2bfloat16(v1);
            __nv_bfloat16 l1 = __float2bfloat16(v1 - __bfloat162float(h1));
            ob8[col] = h1; ob8[DIM + col] = l1; ob8[2 * DIM + col] = h1;
        }
    }
}

// ---------------- converters ---------------------------------------------------
__global__ void split_p1(const float* __restrict__ in, __nv_bfloat16* __restrict__ out,
                         int K, size_t total)
{
    size_t idx = (size_t)blockIdx.x * 256 + threadIdx.x;
    if (idx >= total) return;
    size_t r = idx / K; int k = (int)(idx % K);
    float x = in[idx];
    __nv_bfloat16 hi = __float2bfloat16(x);
    __nv_bfloat16 lo = __float2bfloat16(x - __bfloat162float(hi));
    __nv_bfloat16* o = out + r * (size_t)(3 * K);
    o[k] = hi; o[K + k] = lo; o[2 * K + k] = hi;
}

__global__ __launch_bounds__(256) void splitT_p2(const float* __restrict__ W,
                                                 __nv_bfloat16* __restrict__ out,
                                                 int Kd, int Nd)
{
    __shared__ float ts[32][33];
    int k0 = blockIdx.x * 32, n0 = blockIdx.y * 32;
    int tx = threadIdx.x & 31, ty = threadIdx.x >> 5;
    for (int r = ty; r < 32; r += 8) ts[r][tx] = W[(size_t)(k0 + r) * Nd + n0 + tx];
    __syncthreads();
    for (int r = ty; r < 32; r += 8) {
        float x = ts[tx][r];
        __nv_bfloat16 hi = __float2bfloat16(x);
        __nv_bfloat16 lo = __float2bfloat16(x - __bfloat162float(hi));
        __nv_bfloat16* o = out + (size_t)(n0 + r) * (3 * Kd) + k0 + tx;
        o[0] = hi; o[Kd] = hi; o[2 * Kd] = lo;
    }
}

// fused per-head split + V^T (one read of g_w)
__global__ __launch_bounds__(256) void wsplit_vt(const float* __restrict__ w,
                                                 __nv_bfloat16* __restrict__ wA,
                                                 __nv_bfloat16* __restrict__ wB,
                                                 __half* __restrict__ vt)
{
    __shared__ float ts[64][65];
    int j0 = blockIdx.x * 64, bh = blockIdx.y;
    int b = bh >> 4, h = bh & 15;
    const float* base = w + (size_t)b * NSEQ * DIM + h * 64;
    for (int idx = threadIdx.x; idx < 64 * 16; idx += 256) {
        int jj = idx >> 4, i = idx & 15;
        float4 v = *(const float4*)(base + (size_t)(j0 + jj) * DIM + i * 4);
        ts[jj][i*4] = v.x; ts[jj][i*4+1] = v.y; ts[jj][i*4+2] = v.z; ts[jj][i*4+3] = v.w;
    }
    __syncthreads();
    // wA/wB rows [hi|lo] (128 cols)
    for (int idx = threadIdx.x; idx < 64 * 64; idx += 256) {
        int jj = idx >> 6, d = idx & 63;
        float v = ts[jj][d];
        size_t rb = ((size_t)bh * NSEQ + j0 + jj) * 128;
        float sv = v * 0.125f;
        __nv_bfloat16 hiA = __float2bfloat16(sv);
        wA[rb + d] = hiA;
        wA[rb + 64 + d] = __float2bfloat16(sv - __bfloat162float(hiA));
        __nv_bfloat16 hiB = __float2bfloat16(v);
        wB[rb + d] = hiB;
        wB[rb + 64 + d] = __float2bfloat16(v - __bfloat162float(hiB));
    }
    // V^T
    __half* o = vt + (size_t)bh * 64 * NSEQ + j0;
    for (int idx = threadIdx.x; idx < 64 * 64; idx += 256) {
        int d = idx >> 6, jj = idx & 63;
        o[(size_t)d * NSEQ + jj] = __float2half_rn(ts[jj][d]);
    }
}

// ---------------- launch ------------------------------------------------------
extern "C" void kernel_launch(void* const* d_in, const int* in_sizes, int n_in,
                              void* d_out, int out_size)
{
    const float* x    = (const float*)d_in[0];
    const int*   mask = (const int*)d_in[1];
    const float* Wqkv = (const float*)d_in[2];
    const float* Wout = (const float*)d_in[3];
    const float* bout = (const float*)d_in[4];
    float*       out  = (float*)d_out;

    float *wp;
    __nv_bfloat16 *xs, *atts, *w1s, *w2s, *wA, *wB;
    __half *vt;
    cudaGetSymbolAddress((void**)&wp,   g_w);
    cudaGetSymbolAddress((void**)&xs,   g_xs);
    cudaGetSymbolAddress((void**)&atts, g_atts);
    cudaGetSymbolAddress((void**)&w1s,  g_w1s);
    cudaGetSymbolAddress((void**)&w2s,  g_w2s);
    cudaGetSymbolAddress((void**)&wA,   g_wA);
    cudaGetSymbolAddress((void**)&wB,   g_wB);
    cudaGetSymbolAddress((void**)&vt,   g_vt);

    const int GEMM_SMEM = GSTG * 256 * GP * 2;   // 61440 -> 2 CTAs/SM
    cudaFuncSetAttribute(mma_gemm, cudaFuncAttributeMaxDynamicSharedMemorySize, GEMM_SMEM);
    cudaFuncSetAttribute(flash_attn, cudaFuncAttributeMaxDynamicSharedMemorySize, SM_TOT);

    split_p1<<<(BATCH*NSEQ*DIM + 255) / 256, 256>>>(x, xs, DIM, (size_t)BATCH*NSEQ*DIM);
    splitT_p2<<<dim3(DIM/32, DIM/32), 256>>>(Wqkv, w1s, DIM, DIM);
    splitT_p2<<<dim3(DIM/32, DIM/32), 256>>>(Wout, w2s, DIM, DIM);

    // stage 1: w = x @ Wqkv
    mma_gemm<<<dim3(DIM/128, (BATCH*NSEQ)/128), 256, GEMM_SMEM>>>(
        (const uint16_t*)xs, 3*DIM, (const uint16_t*)w1s, 3*DIM, wp, DIM, 3*DIM, nullptr);

    wsplit_vt<<<dim3(NSEQ/64, BH), 256>>>(wp, wA, wB, vt);

    // stage 2+3: fused flash attention -> split atts
    flash_attn<<<dim3(NSEQ/128, BH), 256, SM_TOT>>>(mask);

    // stage 4: out = atts @ Wout + bout
    mma_gemm<<<dim3(DIM/128, (BATCH*NSEQ)/128), 256, GEMM_SMEM>>>(
        (const uint16_t*)atts, 3*DIM, (const uint16_t*)w2s, 3*DIM, out, DIM, 3*DIM, bout);
}

// round 8
// speedup vs baseline: 3.6419x; 1.1718x over previous
#include <cuda_runtime.h>
#include <cuda_bf16.h>
#include <cuda_fp16.h>
#include <cstdint>

#define HEADS 16
#define DHEAD 64
#define BATCH 2
#define NSEQ  2048
#define DIM   1024
#define BH    (BATCH*HEADS)

// ---------------- scratch (__device__ globals; allocation-free) -------------
__device__ __align__(256) float         g_w  [(size_t)BATCH*NSEQ*DIM];
__device__ __align__(256) __half        g_xs  [(size_t)BATCH*NSEQ*2*DIM];   // [hi|lo]
__device__ __align__(256) __half        g_atts[(size_t)BATCH*NSEQ*2*DIM];   // [hi|lo]
__device__ __align__(256) __half        g_w1s [(size_t)DIM*2*DIM];          // [hi|hi]
__device__ __align__(256) __half        g_w2s [(size_t)DIM*2*DIM];          // [hi|hi]
__device__ __align__(256) __nv_bfloat16 g_wA  [(size_t)BH*NSEQ*128];        // bf16 [hi|lo], scaled
__device__ __align__(256) __nv_bfloat16 g_wB  [(size_t)BH*NSEQ*128];        // bf16 [hi|lo]
__device__ __align__(256) __half        g_vt  [(size_t)BH*DHEAD*NSEQ];

// ---------------- PTX helpers -------------------------------------------------
__device__ __forceinline__ void mma_bf16(float* d, const uint32_t* a, const uint32_t* b) {
    asm volatile(
        "mma.sync.aligned.m16n8k16.row.col.f32.bf16.bf16.f32 "
        "{%0,%1,%2,%3}, {%4,%5,%6,%7}, {%8,%9}, {%0,%1,%2,%3};"
        : "+f"(d[0]), "+f"(d[1]), "+f"(d[2]), "+f"(d[3])
        : "r"(a[0]), "r"(a[1]), "r"(a[2]), "r"(a[3]), "r"(b[0]), "r"(b[1]));
}
__device__ __forceinline__ void mma_f16(float* d, const uint32_t* a, const uint32_t* b) {
    asm volatile(
        "mma.sync.aligned.m16n8k16.row.col.f32.f16.f16.f32 "
        "{%0,%1,%2,%3}, {%4,%5,%6,%7}, {%8,%9}, {%0,%1,%2,%3};"
        : "+f"(d[0]), "+f"(d[1]), "+f"(d[2]), "+f"(d[3])
        : "r"(a[0]), "r"(a[1]), "r"(a[2]), "r"(a[3]), "r"(b[0]), "r"(b[1]));
}
__device__ __forceinline__ uint32_t cvta_s(const void* p) {
    return (uint32_t)__cvta_generic_to_shared(p);
}
#define CP_ASYNC16(dst, src) \
    asm volatile("cp.async.cg.shared.global [%0], [%1], 16;" :: "r"(dst), "l"(src))
#define CP_COMMIT() asm volatile("cp.async.commit_group;")
#define CP_WAIT(n)  asm volatile("cp.async.wait_group %0;" :: "n"(n))
#define LDMX4(r0, r1, r2, r3, addr) \
    asm volatile("ldmatrix.sync.aligned.m8n8.x4.shared.b16 {%0,%1,%2,%3}, [%4];" \
        : "=r"(r0), "=r"(r1), "=r"(r2), "=r"(r3) : "r"(addr))

// ---------------------------------------------------------------------------
// HMMA GEMM (f16), cp.async 3-stage pipeline + ldmatrix.
// C[m,n] = sum_k A[m,k]*B[n,k] (+bias[n]); A,B f16 K-major; K mult of 32.
// ---------------------------------------------------------------------------
#define GP   40
#define GSTG 3

__global__ __launch_bounds__(256, 2) void mma_gemm(
    const uint16_t* __restrict__ A, int lda,
    const uint16_t* __restrict__ B, int ldb,
    float* __restrict__ C, int ldc, int K, const float* __restrict__ bias)
{
    extern __shared__ __align__(16) uint16_t gsm[];
    const int tid = threadIdx.x, lane = tid & 31, warp = tid >> 5;
    const int g = lane >> 2, t = lane & 3;
    const int wm0 = (warp >> 2) * 64, wn0 = (warp & 3) * 32;
    const int m0 = blockIdx.y * 128, n0 = blockIdx.x * 128;

    const uint16_t* Ab = A + (size_t)m0 * lda;
    const uint16_t* Bb = B + (size_t)n0 * ldb;
    const uint32_t smb = cvta_s(gsm);

    float acc[4][4][4] = {};
    const int NC = K >> 5;

    auto issue = [&](int c) {
        const uint32_t dst = smb + (uint32_t)(c % GSTG) * (256 * GP * 2);
        const uint16_t* ag = Ab + c * 32;
        const uint16_t* bg = Bb + c * 32;
        #pragma unroll
        for (int i = 0; i < 2; i++) {
            int idx = tid + i * 256;
            int r = idx >> 2, q = (idx & 3) * 8;
            CP_ASYNC16(dst + (uint32_t)(r * GP + q) * 2, ag + (size_t)r * lda + q);
        }
        #pragma unroll
        for (int i = 0; i < 2; i++) {
            int idx = tid + i * 256;
            int r = idx >> 2, q = (idx & 3) * 8;
            CP_ASYNC16(dst + (uint32_t)((128 + r) * GP + q) * 2, bg + (size_t)r * ldb + q);
        }
        CP_COMMIT();
    };

    #pragma unroll
    for (int s = 0; s < GSTG - 1; s++) issue(s);

    for (int c = 0; c < NC; c++) {
        CP_WAIT(GSTG - 2);
        __syncthreads();
        if (c + GSTG - 1 < NC) issue(c + GSTG - 1);
        else                   CP_COMMIT();

        const uint32_t asv = smb + (uint32_t)(c % GSTG) * (256 * GP * 2);
        const uint32_t bsv = asv + 128 * GP * 2;

        #pragma unroll
        for (int ks = 0; ks < 2; ks++) {
            const int kb = ks * 16;
            uint32_t bf[4][2];
            #pragma unroll
            for (int ni2 = 0; ni2 < 2; ni2++) {
                uint32_t r0, r1, r2, r3;
                uint32_t addr = bsv + (uint32_t)(((wn0 + ni2 * 16 + ((lane >> 4) << 3) + (lane & 7)) * GP
                                                 + kb + ((lane >> 3) & 1) * 8) << 1);
                LDMX4(r0, r1, r2, r3, addr);
                bf[ni2 * 2][0] = r0; bf[ni2 * 2][1] = r1;
                bf[ni2 * 2 + 1][0] = r2; bf[ni2 * 2 + 1][1] = r3;
            }
            #pragma unroll
            for (int mi = 0; mi < 4; mi++) {
                uint32_t af[4];
                uint32_t addr = asv + (uint32_t)(((wm0 + mi * 16 + (lane & 15)) * GP
                                                 + kb + (lane >> 4) * 8) << 1);
                LDMX4(af[0], af[1], af[2], af[3], addr);
                #pragma unroll
                for (int ni = 0; ni < 4; ni++) mma_f16(acc[mi][ni], af, bf[ni]);
            }
        }
    }

    float* Cb = C + (size_t)m0 * ldc + n0;
    #pragma unroll
    for (int mi = 0; mi < 4; mi++) {
        #pragma unroll
        for (int ni = 0; ni < 4; ni++) {
            int col = wn0 + ni * 8 + 2 * t;
            float bx = 0.0f, by = 0.0f;
            if (bias) { bx = bias[n0 + col]; by = bias[n0 + col + 1]; }
            int r1 = wm0 + mi * 16 + g;
            *(float2*)(Cb + (size_t)r1 * ldc + col) =
                make_float2(acc[mi][ni][0] + bx, acc[mi][ni][1] + by);
            *(float2*)(Cb + (size_t)(r1 + 8) * ldc + col) =
                make_float2(acc[mi][ni][2] + bx, acc[mi][ni][3] + by);
        }
    }
}

// ---------------------------------------------------------------------------
// Fused flash attention (unchanged core: 3-term bf16 S, f16 PV).
// Epilogue now writes f16 [hi|lo] atts rows (2*DIM).
// ---------------------------------------------------------------------------
#define KB    64
#define NIT   (NSEQ / KB)
#define KSP   136
#define VSP   72
#define SM_K0 0
#define SM_K1 17408
#define SM_V0 34816
#define SM_V1 44032
#define SM_M0 53248
#define SM_M1 53504
#define SM_TOT 53760

__global__ __launch_bounds__(256, 1) void flash_attn(const int* __restrict__ mask)
{
    extern __shared__ char sm[];
    const int tid = threadIdx.x, lane = tid & 31, warp = tid >> 5;
    const int g = lane >> 2, t = lane & 3;
    const int i0 = blockIdx.x * 128;
    const int bh = blockIdx.y;
    const int b = bh >> 4, h = bh & 15;

    const uint16_t* wA = (const uint16_t*)g_wA + (size_t)bh * NSEQ * 128;
    const uint16_t* wB = (const uint16_t*)g_wB + (size_t)bh * NSEQ * 128;
    const uint16_t* vt = (const uint16_t*)g_vt + (size_t)bh * DHEAD * NSEQ;
    const int* mrow = mask + (size_t)b * NSEQ;
    const uint32_t smb = cvta_s(sm);

    auto issue = [&](int it2, int buf) {
        const int j0 = it2 * KB;
        const uint32_t kd = smb + (buf ? SM_K1 : SM_K0);
        const uint32_t vd = smb + (buf ? SM_V1 : SM_V0);
        const uint32_t md = smb + (buf ? SM_M1 : SM_M0);
        #pragma unroll
        for (int i = 0; i < 4; i++) {
            int idx = tid + i * 256;
            int r = idx >> 4, q = (idx & 15) * 8;
            CP_ASYNC16(kd + (uint32_t)(r * KSP + q) * 2, wB + (size_t)(j0 + r) * 128 + q);
        }
        #pragma unroll
        for (int i = 0; i < 2; i++) {
            int idx = tid + i * 256;
            int r = idx >> 3, q = (idx & 7) * 8;
            CP_ASYNC16(vd + (uint32_t)(r * VSP + q) * 2, vt + (size_t)r * NSEQ + j0 + q);
        }
        if (tid < 16) CP_ASYNC16(md + tid * 16, mrow + j0 + tid * 4);
        CP_COMMIT();
    };

    uint32_t qh[4][4], ql[4][4];
    {
        const uint16_t* q0 = wA + (size_t)(i0 + warp * 16 + g) * 128 + 2 * t;
        #pragma unroll
        for (int j = 0; j < 4; j++) {
            qh[j][0] = *(const uint32_t*)(q0 + j * 16);
            qh[j][1] = *(const uint32_t*)(q0 + j * 16 + 8 * 128);
            qh[j][2] = *(const uint32_t*)(q0 + j * 16 + 8);
            qh[j][3] = *(const uint32_t*)(q0 + j * 16 + 8 * 128 + 8);
            ql[j][0] = *(const uint32_t*)(q0 + 64 + j * 16);
            ql[j][1] = *(const uint32_t*)(q0 + 64 + j * 16 + 8 * 128);
            ql[j][2] = *(const uint32_t*)(q0 + 64 + j * 16 + 8);
            ql[j][3] = *(const uint32_t*)(q0 + 64 + j * 16 + 8 * 128 + 8);
        }
    }

    float Oa[8][4] = {};
    float mr0 = -1e30f, mr1 = -1e30f, lr0 = 0.0f, lr1 = 0.0f;

    issue(0, 0);
    CP_WAIT(0);
    __syncthreads();

    for (int it = 0; it < NIT; it++) {
        const int cur = it & 1;
        const uint32_t ksv = smb + (cur ? SM_K1 : SM_K0);
        const uint32_t vsv = smb + (cur ? SM_V1 : SM_V0);
        const int* Mi = (const int*)(sm + (cur ? SM_M1 : SM_M0));

        if (it + 1 < NIT) issue(it + 1, cur ^ 1);
        else              CP_COMMIT();

        float sa[8][4] = {};
        #pragma unroll
        for (int j = 0; j < 4; j++) {
            #pragma unroll
            for (int nt2 = 0; nt2 < 4; nt2++) {
                const uint32_t rowoff =
                    (uint32_t)((nt2 * 16 + ((lane >> 4) << 3) + (lane & 7)) * KSP
                               + ((lane >> 3) & 1) * 8);
                uint32_t r0, r1, r2, r3;
                LDMX4(r0, r1, r2, r3, ksv + ((rowoff + j * 16) << 1));
                uint32_t b0[2] = {r0, r1}, b1[2] = {r2, r3};
                mma_bf16(sa[nt2 * 2],     qh[j], b0);
                mma_bf16(sa[nt2 * 2 + 1], qh[j], b1);
                mma_bf16(sa[nt2 * 2],     ql[j], b0);
                mma_bf16(sa[nt2 * 2 + 1], ql[j], b1);
                LDMX4(r0, r1, r2, r3, ksv + ((rowoff + 64 + j * 16) << 1));
                uint32_t c0[2] = {r0, r1}, c1[2] = {r2, r3};
                mma_bf16(sa[nt2 * 2],     qh[j], c0);
                mma_bf16(sa[nt2 * 2 + 1], qh[j], c1);
            }
        }

        float bm0 = -1e30f, bm1 = -1e30f;
        #pragma unroll
        for (int nt = 0; nt < 8; nt++) {
            bm0 = fmaxf(bm0, fmaxf(sa[nt][0], sa[nt][1]));
            bm1 = fmaxf(bm1, fmaxf(sa[nt][2], sa[nt][3]));
        }
        bm0 = fmaxf(bm0, __shfl_xor_sync(0xffffffffu, bm0, 1));
        bm0 = fmaxf(bm0, __shfl_xor_sync(0xffffffffu, bm0, 2));
        bm1 = fmaxf(bm1, __shfl_xor_sync(0xffffffffu, bm1, 1));
        bm1 = fmaxf(bm1, __shfl_xor_sync(0xffffffffu, bm1, 2));

        const float mn0 = fmaxf(mr0, bm0), mn1 = fmaxf(mr1, bm1);
        const float sf0 = __expf(mr0 - mn0), sf1 = __expf(mr1 - mn1);
        mr0 = mn0; mr1 = mn1;

        float rs0 = 0.0f, rs1 = 0.0f;
        #pragma unroll
        for (int nt = 0; nt < 8; nt++) {
            sa[nt][0] = __expf(sa[nt][0] - mn0);
            sa[nt][1] = __expf(sa[nt][1] - mn0);
            sa[nt][2] = __expf(sa[nt][2] - mn1);
            sa[nt][3] = __expf(sa[nt][3] - mn1);
            rs0 += sa[nt][0] + sa[nt][1];
            rs1 += sa[nt][2] + sa[nt][3];
        }
        rs0 += __shfl_xor_sync(0xffffffffu, rs0, 1);
        rs0 += __shfl_xor_sync(0xffffffffu, rs0, 2);
        rs1 += __shfl_xor_sync(0xffffffffu, rs1, 1);
        rs1 += __shfl_xor_sync(0xffffffffu, rs1, 2);
        lr0 = lr0 * sf0 + rs0;
        lr1 = lr1 * sf1 + rs1;

        #pragma unroll
        for (int nt = 0; nt < 8; nt++) {
            Oa[nt][0] *= sf0; Oa[nt][1] *= sf0;
            Oa[nt][2] *= sf1; Oa[nt][3] *= sf1;
        }

        uint32_t pfra[4][4];
        #pragma unroll
        for (int kt2 = 0; kt2 < 4; kt2++) {
            const int n0t = 2 * kt2, n1t = 2 * kt2 + 1;
            int2 mi0 = *(const int2*)&Mi[n0t * 8 + 2 * t];
            int2 mi1 = *(const int2*)&Mi[n1t * 8 + 2 * t];
            float m0x = 1.0f - (float)mi0.x, m0y = 1.0f - (float)mi0.y;
            float m1x = 1.0f - (float)mi1.x, m1y = 1.0f - (float)mi1.y;
            __half2 a0 = __floats2half2_rn(sa[n0t][0] * m0x, sa[n0t][1] * m0y);
            __half2 a1 = __floats2half2_rn(sa[n0t][2] * m0x, sa[n0t][3] * m0y);
            __half2 a2 = __floats2half2_rn(sa[n1t][0] * m1x, sa[n1t][1] * m1y);
            __half2 a3 = __floats2half2_rn(sa[n1t][2] * m1x, sa[n1t][3] * m1y);
            pfra[kt2][0] = *(uint32_t*)&a0;
            pfra[kt2][1] = *(uint32_t*)&a1;
            pfra[kt2][2] = *(uint32_t*)&a2;
            pfra[kt2][3] = *(uint32_t*)&a3;
        }

        #pragma unroll
        for (int nt2 = 0; nt2 < 4; nt2++) {
            #pragma unroll
            for (int kt2 = 0; kt2 < 4; kt2++) {
                uint32_t r0, r1, r2, r3;
                uint32_t addr = vsv + (uint32_t)(((nt2 * 16 + ((lane >> 4) << 3) + (lane & 7)) * VSP
                                                 + kt2 * 16 + ((lane >> 3) & 1) * 8) << 1);
                LDMX4(r0, r1, r2, r3, addr);
                uint32_t b0[2] = {r0, r1}, b1[2] = {r2, r3};
                mma_f16(Oa[nt2 * 2],     pfra[kt2], b0);
                mma_f16(Oa[nt2 * 2 + 1], pfra[kt2], b1);
            }
        }

        CP_WAIT(0);
        __syncthreads();
    }

    // ---- normalize + write f16 [hi|lo] atts rows (2*DIM) ----
    const float inv0 = 1.0f / lr0, inv1 = 1.0f / lr1;
    const int r0 = i0 + warp * 16 + g;
    __half* ob  = g_atts + ((size_t)b * NSEQ + r0) * (2 * DIM) + h * 64;
    __half* ob8 = ob + (size_t)8 * (2 * DIM);
    #pragma unroll
    for (int nt = 0; nt < 8; nt++) {
        #pragma unroll
        for (int e = 0; e < 2; e++) {
            int col = nt * 8 + 2 * t + e;
            float v0 = Oa[nt][e] * inv0;
            __half h0 = __float2half_rn(v0);
            ob[col] = h0; ob[DIM + col] = __float2half_rn(v0 - __half2float(h0));
            float v1 = Oa[nt][2 + e] * inv1;
            __half h1 = __float2half_rn(v1);
            ob8[col] = h1; ob8[DIM + col] = __float2half_rn(v1 - __half2float(h1));
        }
    }
}

// ---------------- converters ---------------------------------------------------
// fp32 [R,K] -> f16 [R,2K] rows [hi|lo]
__global__ void splitA_f16(const float* __restrict__ in, __half* __restrict__ out,
                           int K, size_t total)
{
    size_t idx = (size_t)blockIdx.x * 256 + threadIdx.x;
    if (idx >= total) return;
    size_t r = idx / K; int k = (int)(idx % K);
    float x = in[idx];
    __half hi = __float2half_rn(x);
    __half* o = out + r * (size_t)(2 * K);
    o[k] = hi; o[K + k] = __float2half_rn(x - __half2float(hi));
}

// fp32 W[K,N] -> f16 out[N,2K] rows [hi|hi] (transposed, duplicated)
__global__ __launch_bounds__(256) void splitB_f16(const float* __restrict__ W,
                                                  __half* __restrict__ out,
                                                  int Kd, int Nd)
{
    __shared__ float ts[32][33];
    int k0 = blockIdx.x * 32, n0 = blockIdx.y * 32;
    int tx = threadIdx.x & 31, ty = threadIdx.x >> 5;
    for (int r = ty; r < 32; r += 8) ts[r][tx] = W[(size_t)(k0 + r) * Nd + n0 + tx];
    __syncthreads();
    for (int r = ty; r < 32; r += 8) {
        __half hi = __float2half_rn(ts[tx][r]);
        __half* o = out + (size_t)(n0 + r) * (2 * Kd) + k0 + tx;
        o[0] = hi; o[Kd] = hi;
    }
}

// fused per-head bf16 split + V^T (one read of g_w)
__global__ __launch_bounds__(256) void wsplit_vt(const float* __restrict__ w,
                                                 __nv_bfloat16* __restrict__ wA,
                                                 __nv_bfloat16* __restrict__ wB,
                                                 __half* __restrict__ vt)
{
    __shared__ float ts[64][65];
    int j0 = blockIdx.x * 64, bh = blockIdx.y;
    int b = bh >> 4, h = bh & 15;
    const float* base = w + (size_t)b * NSEQ * DIM + h * 64;
    for (int idx = threadIdx.x; idx < 64 * 16; idx += 256) {
        int jj = idx >> 4, i = idx & 15;
        float4 v = *(const float4*)(base + (size_t)(j0 + jj) * DIM + i * 4);
        ts[jj][i*4] = v.x; ts[jj][i*4+1] = v.y; ts[jj][i*4+2] = v.z; ts[jj][i*4+3] = v.w;
    }
    __syncthreads();
    for (int idx = threadIdx.x; idx < 64 * 64; idx += 256) {
        int jj = idx >> 6, d = idx & 63;
        float v = ts[jj][d];
        size_t rb = ((size_t)bh * NSEQ + j0 + jj) * 128;
        float sv = v * 0.125f;
        __nv_bfloat16 hiA = __float2bfloat16(sv);
        wA[rb + d] = hiA;
        wA[rb + 64 + d] = __float2bfloat16(sv - __bfloat162float(hiA));
        __nv_bfloat16 hiB = __float2bfloat16(v);
        wB[rb + d] = hiB;
        wB[rb + 64 + d] = __float2bfloat16(v - __bfloat162float(hiB));
    }
    __half* o = vt + (size_t)bh * 64 * NSEQ + j0;
    for (int idx = threadIdx.x; idx < 64 * 64; idx += 256) {
        int d = idx >> 6, jj = idx & 63;
        o[(size_t)d * NSEQ + jj] = __float2half_rn(ts[jj][d]);
    }
}

// ---------------- launch ------------------------------------------------------
extern "C" void kernel_launch(void* const* d_in, const int* in_sizes, int n_in,
                              void* d_out, int out_size)
{
    const float* x    = (const float*)d_in[0];
    const int*   mask = (const int*)d_in[1];
    const float* Wqkv = (const float*)d_in[2];
    const float* Wout = (const float*)d_in[3];
    const float* bout = (const float*)d_in[4];
    float*       out  = (float*)d_out;

    float *wp;
    __half *xs, *atts, *w1s, *w2s, *vt;
    __nv_bfloat16 *wA, *wB;
    cudaGetSymbolAddress((void**)&wp,   g_w);
    cudaGetSymbolAddress((void**)&xs,   g_xs);
    cudaGetSymbolAddress((void**)&atts, g_atts);
    cudaGetSymbolAddress((void**)&w1s,  g_w1s);
    cudaGetSymbolAddress((void**)&w2s,  g_w2s);
    cudaGetSymbolAddress((void**)&wA,   g_wA);
    cudaGetSymbolAddress((void**)&wB,   g_wB);
    cudaGetSymbolAddress((void**)&vt,   g_vt);

    const int GEMM_SMEM = GSTG * 256 * GP * 2;   // 61440
    cudaFuncSetAttribute(mma_gemm, cudaFuncAttributeMaxDynamicSharedMemorySize, GEMM_SMEM);
    cudaFuncSetAttribute(flash_attn, cudaFuncAttributeMaxDynamicSharedMemorySize, SM_TOT);

    splitA_f16<<<(BATCH*NSEQ*DIM + 255) / 256, 256>>>(x, xs, DIM, (size_t)BATCH*NSEQ*DIM);
    splitB_f16<<<dim3(DIM/32, DIM/32), 256>>>(Wqkv, w1s, DIM, DIM);
    splitB_f16<<<dim3(DIM/32, DIM/32), 256>>>(Wout, w2s, DIM, DIM);

    // stage 1: w = x @ Wqkv  (f16 2-split, K'=2048)
    mma_gemm<<<dim3(DIM/128, (BATCH*NSEQ)/128), 256, GEMM_SMEM>>>(
        (const uint16_t*)xs, 2*DIM, (const uint16_t*)w1s, 2*DIM, wp, DIM, 2*DIM, nullptr);

    wsplit_vt<<<dim3(NSEQ/64, BH), 256>>>(wp, wA, wB, vt);

    // stage 2+3: fused flash attention -> f16 [hi|lo] atts
    flash_attn<<<dim3(NSEQ/128, BH), 256, SM_TOT>>>(mask);

    // stage 4: out = atts @ Wout + bout  (f16 2-split, K'=2048)
    mma_gemm<<<dim3(DIM/128, (BATCH*NSEQ)/128), 256, GEMM_SMEM>>>(
        (const uint16_t*)atts, 2*DIM, (const uint16_t*)w2s, 2*DIM, out, DIM, 2*DIM, bout);
}

// round 9
// speedup vs baseline: 4.0897x; 1.1230x over previous
#include <cuda_runtime.h>
#include <cuda_bf16.h>
#include <cuda_fp16.h>
#include <cstdint>

#define HEADS 16
#define DHEAD 64
#define BATCH 2
#define NSEQ  2048
#define DIM   1024
#define BH    (BATCH*HEADS)

// ---------------- scratch (__device__ globals; allocation-free) -------------
__device__ __align__(256) float  g_w  [(size_t)BATCH*NSEQ*DIM];
__device__ __align__(256) __half g_xs  [(size_t)BATCH*NSEQ*2*DIM];   // [hi|lo]
__device__ __align__(256) __half g_atts[(size_t)BATCH*NSEQ*2*DIM];   // [hi|lo]
__device__ __align__(256) __half g_w1s [(size_t)DIM*2*DIM];          // [hi|hi]
__device__ __align__(256) __half g_w2s [(size_t)DIM*2*DIM];          // [hi|hi]
__device__ __align__(256) __half g_wQ  [(size_t)BH*NSEQ*128];        // f16 [hi|lo], unscaled (Q and K)
__device__ __align__(256) __half g_vt  [(size_t)BH*DHEAD*NSEQ];

// ---------------- PTX helpers -------------------------------------------------
__device__ __forceinline__ void mma_f16(float* d, const uint32_t* a, const uint32_t* b) {
    asm volatile(
        "mma.sync.aligned.m16n8k16.row.col.f32.f16.f16.f32 "
        "{%0,%1,%2,%3}, {%4,%5,%6,%7}, {%8,%9}, {%0,%1,%2,%3};"
        : "+f"(d[0]), "+f"(d[1]), "+f"(d[2]), "+f"(d[3])
        : "r"(a[0]), "r"(a[1]), "r"(a[2]), "r"(a[3]), "r"(b[0]), "r"(b[1]));
}
__device__ __forceinline__ uint32_t cvta_s(const void* p) {
    return (uint32_t)__cvta_generic_to_shared(p);
}
#define CP_ASYNC16(dst, src) \
    asm volatile("cp.async.cg.shared.global [%0], [%1], 16;" :: "r"(dst), "l"(src))
#define CP_COMMIT() asm volatile("cp.async.commit_group;")
#define CP_WAIT(n)  asm volatile("cp.async.wait_group %0;" :: "n"(n))
#define LDMX4(r0, r1, r2, r3, addr) \
    asm volatile("ldmatrix.sync.aligned.m8n8.x4.shared.b16 {%0,%1,%2,%3}, [%4];" \
        : "=r"(r0), "=r"(r1), "=r"(r2), "=r"(r3) : "r"(addr))

// ---------------------------------------------------------------------------
// HMMA GEMM (f16), cp.async 3-stage pipeline + ldmatrix. (validated R8)
// ---------------------------------------------------------------------------
#define GP   40
#define GSTG 3

__global__ __launch_bounds__(256, 2) void mma_gemm(
    const uint16_t* __restrict__ A, int lda,
    const uint16_t* __restrict__ B, int ldb,
    float* __restrict__ C, int ldc, int K, const float* __restrict__ bias)
{
    extern __shared__ __align__(16) uint16_t gsm[];
    const int tid = threadIdx.x, lane = tid & 31, warp = tid >> 5;
    const int g = lane >> 2, t = lane & 3;
    const int wm0 = (warp >> 2) * 64, wn0 = (warp & 3) * 32;
    const int m0 = blockIdx.y * 128, n0 = blockIdx.x * 128;

    const uint16_t* Ab = A + (size_t)m0 * lda;
    const uint16_t* Bb = B + (size_t)n0 * ldb;
    const uint32_t smb = cvta_s(gsm);

    float acc[4][4][4] = {};
    const int NC = K >> 5;

    auto issue = [&](int c) {
        const uint32_t dst = smb + (uint32_t)(c % GSTG) * (256 * GP * 2);
        const uint16_t* ag = Ab + c * 32;
        const uint16_t* bg = Bb + c * 32;
        #pragma unroll
        for (int i = 0; i < 2; i++) {
            int idx = tid + i * 256;
            int r = idx >> 2, q = (idx & 3) * 8;
            CP_ASYNC16(dst + (uint32_t)(r * GP + q) * 2, ag + (size_t)r * lda + q);
        }
        #pragma unroll
        for (int i = 0; i < 2; i++) {
            int idx = tid + i * 256;
            int r = idx >> 2, q = (idx & 3) * 8;
            CP_ASYNC16(dst + (uint32_t)((128 + r) * GP + q) * 2, bg + (size_t)r * ldb + q);
        }
        CP_COMMIT();
    };

    #pragma unroll
    for (int s = 0; s < GSTG - 1; s++) issue(s);

    for (int c = 0; c < NC; c++) {
        CP_WAIT(GSTG - 2);
        __syncthreads();
        if (c + GSTG - 1 < NC) issue(c + GSTG - 1);
        else                   CP_COMMIT();

        const uint32_t asv = smb + (uint32_t)(c % GSTG) * (256 * GP * 2);
        const uint32_t bsv = asv + 128 * GP * 2;

        #pragma unroll
        for (int ks = 0; ks < 2; ks++) {
            const int kb = ks * 16;
            uint32_t bf[4][2];
            #pragma unroll
            for (int ni2 = 0; ni2 < 2; ni2++) {
                uint32_t r0, r1, r2, r3;
                uint32_t addr = bsv + (uint32_t)(((wn0 + ni2 * 16 + ((lane >> 4) << 3) + (lane & 7)) * GP
                                                 + kb + ((lane >> 3) & 1) * 8) << 1);
                LDMX4(r0, r1, r2, r3, addr);
                bf[ni2 * 2][0] = r0; bf[ni2 * 2][1] = r1;
                bf[ni2 * 2 + 1][0] = r2; bf[ni2 * 2 + 1][1] = r3;
            }
            #pragma unroll
            for (int mi = 0; mi < 4; mi++) {
                uint32_t af[4];
                uint32_t addr = asv + (uint32_t)(((wm0 + mi * 16 + (lane & 15)) * GP
                                                 + kb + (lane >> 4) * 8) << 1);
                LDMX4(af[0], af[1], af[2], af[3], addr);
                #pragma unroll
                for (int ni = 0; ni < 4; ni++) mma_f16(acc[mi][ni], af, bf[ni]);
            }
        }
    }

    float* Cb = C + (size_t)m0 * ldc + n0;
    #pragma unroll
    for (int mi = 0; mi < 4; mi++) {
        #pragma unroll
        for (int ni = 0; ni < 4; ni++) {
            int col = wn0 + ni * 8 + 2 * t;
            float bx = 0.0f, by = 0.0f;
            if (bias) { bx = bias[n0 + col]; by = bias[n0 + col + 1]; }
            int r1 = wm0 + mi * 16 + g;
            *(float2*)(Cb + (size_t)r1 * ldc + col) =
                make_float2(acc[mi][ni][0] + bx, acc[mi][ni][1] + by);
            *(float2*)(Cb + (size_t)(r1 + 8) * ldc + col) =
                make_float2(acc[mi][ni][2] + bx, acc[mi][ni][3] + by);
        }
    }
}

// ---------------------------------------------------------------------------
// Fused flash attention. S = (Qh*Kh + Ql*Kh) * 0.125 in f16 (2-term split,
// K uses hi only); f16 PV. Q/K read from one unscaled f16 [hi|lo] array.
// ---------------------------------------------------------------------------
#define KB    64
#define NIT   (NSEQ / KB)
#define KSP   72     // halfs per K-row (144B; mod128=16 -> ldmatrix conflict-free)
#define VSP   72
#define SM_K0 0
#define SM_K1 9216
#define SM_V0 18432
#define SM_V1 27648
#define SM_M0 36864
#define SM_M1 37120
#define SM_TOT 37376

__global__ __launch_bounds__(256, 1) void flash_attn(const int* __restrict__ mask)
{
    extern __shared__ char sm[];
    const int tid = threadIdx.x, lane = tid & 31, warp = tid >> 5;
    const int g = lane >> 2, t = lane & 3;
    const int i0 = blockIdx.x * 128;
    const int bh = blockIdx.y;
    const int b = bh >> 4, h = bh & 15;

    const uint16_t* wQ = (const uint16_t*)g_wQ + (size_t)bh * NSEQ * 128;
    const uint16_t* vt = (const uint16_t*)g_vt + (size_t)bh * DHEAD * NSEQ;
    const int* mrow = mask + (size_t)b * NSEQ;
    const uint32_t smb = cvta_s(sm);

    auto issue = [&](int it2, int buf) {
        const int j0 = it2 * KB;
        const uint32_t kd = smb + (buf ? SM_K1 : SM_K0);
        const uint32_t vd = smb + (buf ? SM_V1 : SM_V0);
        const uint32_t md = smb + (buf ? SM_M1 : SM_M0);
        // K tile: hi halves only (64 rows x 64 halfs)
        #pragma unroll
        for (int i = 0; i < 2; i++) {
            int idx = tid + i * 256;
            int r = idx >> 3, q = (idx & 7) * 8;
            CP_ASYNC16(kd + (uint32_t)(r * KSP + q) * 2, wQ + (size_t)(j0 + r) * 128 + q);
        }
        #pragma unroll
        for (int i = 0; i < 2; i++) {
            int idx = tid + i * 256;
            int r = idx >> 3, q = (idx & 7) * 8;
            CP_ASYNC16(vd + (uint32_t)(r * VSP + q) * 2, vt + (size_t)r * NSEQ + j0 + q);
        }
        if (tid < 16) CP_ASYNC16(md + tid * 16, mrow + j0 + tid * 4);
        CP_COMMIT();
    };

    // Q fragments (rows i0+warp*16+{g,g+8}): 4 hi tiles + 4 lo tiles, unscaled f16
    uint32_t qh[4][4], ql[4][4];
    {
        const uint16_t* q0 = wQ + (size_t)(i0 + warp * 16 + g) * 128 + 2 * t;
        #pragma unroll
        for (int j = 0; j < 4; j++) {
            qh[j][0] = *(const uint32_t*)(q0 + j * 16);
            qh[j][1] = *(const uint32_t*)(q0 + j * 16 + 8 * 128);
            qh[j][2] = *(const uint32_t*)(q0 + j * 16 + 8);
            qh[j][3] = *(const uint32_t*)(q0 + j * 16 + 8 * 128 + 8);
            ql[j][0] = *(const uint32_t*)(q0 + 64 + j * 16);
            ql[j][1] = *(const uint32_t*)(q0 + 64 + j * 16 + 8 * 128);
            ql[j][2] = *(const uint32_t*)(q0 + 64 + j * 16 + 8);
            ql[j][3] = *(const uint32_t*)(q0 + 64 + j * 16 + 8 * 128 + 8);
        }
    }

    float Oa[8][4] = {};
    float mr0 = -1e30f, mr1 = -1e30f, lr0 = 0.0f, lr1 = 0.0f;

    issue(0, 0);
    CP_WAIT(0);
    __syncthreads();

    for (int it = 0; it < NIT; it++) {
        const int cur = it & 1;
        const uint32_t ksv = smb + (cur ? SM_K1 : SM_K0);
        const uint32_t vsv = smb + (cur ? SM_V1 : SM_V0);
        const int* Mi = (const int*)(sm + (cur ? SM_M1 : SM_M0));

        if (it + 1 < NIT) issue(it + 1, cur ^ 1);
        else              CP_COMMIT();

        // ---- S tile: Qh*Kh + Ql*Kh (f16), one K fragment per (j, nt2) ----
        float sa[8][4] = {};
        #pragma unroll
        for (int j = 0; j < 4; j++) {
            #pragma unroll
            for (int nt2 = 0; nt2 < 4; nt2++) {
                uint32_t r0, r1, r2, r3;
                uint32_t addr = ksv + (uint32_t)(((nt2 * 16 + ((lane >> 4) << 3) + (lane & 7)) * KSP
                                                 + j * 16 + ((lane >> 3) & 1) * 8) << 1);
                LDMX4(r0, r1, r2, r3, addr);
                uint32_t b0[2] = {r0, r1}, b1[2] = {r2, r3};
                mma_f16(sa[nt2 * 2],     qh[j], b0);
                mma_f16(sa[nt2 * 2 + 1], qh[j], b1);
                mma_f16(sa[nt2 * 2],     ql[j], b0);
                mma_f16(sa[nt2 * 2 + 1], ql[j], b1);
            }
        }
        // fold softmax scale (exact power of two)
        #pragma unroll
        for (int nt = 0; nt < 8; nt++) {
            sa[nt][0] *= 0.125f; sa[nt][1] *= 0.125f;
            sa[nt][2] *= 0.125f; sa[nt][3] *= 0.125f;
        }

        // ---- online softmax ----
        float bm0 = -1e30f, bm1 = -1e30f;
        #pragma unroll
        for (int nt = 0; nt < 8; nt++) {
            bm0 = fmaxf(bm0, fmaxf(sa[nt][0], sa[nt][1]));
            bm1 = fmaxf(bm1, fmaxf(sa[nt][2], sa[nt][3]));
        }
        bm0 = fmaxf(bm0, __shfl_xor_sync(0xffffffffu, bm0, 1));
        bm0 = fmaxf(bm0, __shfl_xor_sync(0xffffffffu, bm0, 2));
        bm1 = fmaxf(bm1, __shfl_xor_sync(0xffffffffu, bm1, 1));
        bm1 = fmaxf(bm1, __shfl_xor_sync(0xffffffffu, bm1, 2));

        const float mn0 = fmaxf(mr0, bm0), mn1 = fmaxf(mr1, bm1);
        const float sf0 = __expf(mr0 - mn0), sf1 = __expf(mr1 - mn1);
        mr0 = mn0; mr1 = mn1;

        float rs0 = 0.0f, rs1 = 0.0f;
        #pragma unroll
        for (int nt = 0; nt < 8; nt++) {
            sa[nt][0] = __expf(sa[nt][0] - mn0);
            sa[nt][1] = __expf(sa[nt][1] - mn0);
            sa[nt][2] = __expf(sa[nt][2] - mn1);
            sa[nt][3] = __expf(sa[nt][3] - mn1);
            rs0 += sa[nt][0] + sa[nt][1];
            rs1 += sa[nt][2] + sa[nt][3];
        }
        rs0 += __shfl_xor_sync(0xffffffffu, rs0, 1);
        rs0 += __shfl_xor_sync(0xffffffffu, rs0, 2);
        rs1 += __shfl_xor_sync(0xffffffffu, rs1, 1);
        rs1 += __shfl_xor_sync(0xffffffffu, rs1, 2);
        lr0 = lr0 * sf0 + rs0;
        lr1 = lr1 * sf1 + rs1;

        #pragma unroll
        for (int nt = 0; nt < 8; nt++) {
            Oa[nt][0] *= sf0; Oa[nt][1] *= sf0;
            Oa[nt][2] *= sf1; Oa[nt][3] *= sf1;
        }

        // ---- mask + repack P into f16 A-fragments ----
        uint32_t pfra[4][4];
        #pragma unroll
        for (int kt2 = 0; kt2 < 4; kt2++) {
            const int n0t = 2 * kt2, n1t = 2 * kt2 + 1;
            int2 mi0 = *(const int2*)&Mi[n0t * 8 + 2 * t];
            int2 mi1 = *(const int2*)&Mi[n1t * 8 + 2 * t];
            float m0x = 1.0f - (float)mi0.x, m0y = 1.0f - (float)mi0.y;
            float m1x = 1.0f - (float)mi1.x, m1y = 1.0f - (float)mi1.y;
            __half2 a0 = __floats2half2_rn(sa[n0t][0] * m0x, sa[n0t][1] * m0y);
            __half2 a1 = __floats2half2_rn(sa[n0t][2] * m0x, sa[n0t][3] * m0y);
            __half2 a2 = __floats2half2_rn(sa[n1t][0] * m1x, sa[n1t][1] * m1y);
            __half2 a3 = __floats2half2_rn(sa[n1t][2] * m1x, sa[n1t][3] * m1y);
            pfra[kt2][0] = *(uint32_t*)&a0;
            pfra[kt2][1] = *(uint32_t*)&a1;
            pfra[kt2][2] = *(uint32_t*)&a2;
            pfra[kt2][3] = *(uint32_t*)&a3;
        }

        // ---- O += P @ V ----
        #pragma unroll
        for (int nt2 = 0; nt2 < 4; nt2++) {
            #pragma unroll
            for (int kt2 = 0; kt2 < 4; kt2++) {
                uint32_t r0, r1, r2, r3;
                uint32_t addr = vsv + (uint32_t)(((nt2 * 16 + ((lane >> 4) << 3) + (lane & 7)) * VSP
                                                 + kt2 * 16 + ((lane >> 3) & 1) * 8) << 1);
                LDMX4(r0, r1, r2, r3, addr);
                uint32_t b0[2] = {r0, r1}, b1[2] = {r2, r3};
                mma_f16(Oa[nt2 * 2],     pfra[kt2], b0);
                mma_f16(Oa[nt2 * 2 + 1], pfra[kt2], b1);
            }
        }

        CP_WAIT(0);
        __syncthreads();
    }

    // ---- normalize + write f16 [hi|lo] atts rows (2*DIM) ----
    const float inv0 = 1.0f / lr0, inv1 = 1.0f / lr1;
    const int r0 = i0 + warp * 16 + g;
    __half* ob  = g_atts + ((size_t)b * NSEQ + r0) * (2 * DIM) + h * 64;
    __half* ob8 = ob + (size_t)8 * (2 * DIM);
    #pragma unroll
    for (int nt = 0; nt < 8; nt++) {
        #pragma unroll
        for (int e = 0; e < 2; e++) {
            int col = nt * 8 + 2 * t + e;
            float v0 = Oa[nt][e] * inv0;
            __half h0 = __float2half_rn(v0);
            ob[col] = h0; ob[DIM + col] = __float2half_rn(v0 - __half2float(h0));
            float v1 = Oa[nt][2 + e] * inv1;
            __half h1 = __float2half_rn(v1);
            ob8[col] = h1; ob8[DIM + col] = __float2half_rn(v1 - __half2float(h1));
        }
    }
}

// ---------------- converters ---------------------------------------------------
// fp32 [R,K] -> f16 [R,2K] rows [hi|lo]
__global__ void splitA_f16(const float* __restrict__ in, __half* __restrict__ out,
                           int K, size_t total)
{
    size_t idx = (size_t)blockIdx.x * 256 + threadIdx.x;
    if (idx >= total) return;
    size_t r = idx / K; int k = (int)(idx % K);
    float x = in[idx];
    __half hi = __float2half_rn(x);
    __half* o = out + r * (size_t)(2 * K);
    o[k] = hi; o[K + k] = __float2half_rn(x - __half2float(hi));
}

// fp32 W[K,N] -> f16 out[N,2K] rows [hi|hi] (transposed, duplicated)
__global__ __launch_bounds__(256) void splitB_f16(const float* __restrict__ W,
                                                  __half* __restrict__ out,
                                                  int Kd, int Nd)
{
    __shared__ float ts[32][33];
    int k0 = blockIdx.x * 32, n0 = blockIdx.y * 32;
    int tx = threadIdx.x & 31, ty = threadIdx.x >> 5;
    for (int r = ty; r < 32; r += 8) ts[r][tx] = W[(size_t)(k0 + r) * Nd + n0 + tx];
    __syncthreads();
    for (int r = ty; r < 32; r += 8) {
        __half hi = __float2half_rn(ts[tx][r]);
        __half* o = out + (size_t)(n0 + r) * (2 * Kd) + k0 + tx;
        o[0] = hi; o[Kd] = hi;
    }
}

// fused per-head f16 [hi|lo] split + V^T (one read of g_w)
__global__ __launch_bounds__(256) void wsplit_vt(const float* __restrict__ w,
                                                 __half* __restrict__ wQ,
                                                 __half* __restrict__ vt)
{
    __shared__ float ts[64][65];
    int j0 = blockIdx.x * 64, bh = blockIdx.y;
    int b = bh >> 4, h = bh & 15;
    const float* base = w + (size_t)b * NSEQ * DIM + h * 64;
    for (int idx = threadIdx.x; idx < 64 * 16; idx += 256) {
        int jj = idx >> 4, i = idx & 15;
        float4 v = *(const float4*)(base + (size_t)(j0 + jj) * DIM + i * 4);
        ts[jj][i*4] = v.x; ts[jj][i*4+1] = v.y; ts[jj][i*4+2] = v.z; ts[jj][i*4+3] = v.w;
    }
    __syncthreads();
    for (int idx = threadIdx.x; idx < 64 * 64; idx += 256) {
        int jj = idx >> 6, d = idx & 63;
        float v = ts[jj][d];
        size_t rb = ((size_t)bh * NSEQ + j0 + jj) * 128;
        __half hi = __float2half_rn(v);
        wQ[rb + d] = hi;
        wQ[rb + 64 + d] = __float2half_rn(v - __half2float(hi));
    }
    __half* o = vt + (size_t)bh * 64 * NSEQ + j0;
    for (int idx = threadIdx.x; idx < 64 * 64; idx += 256) {
        int d = idx >> 6, jj = idx & 63;
        o[(size_t)d * NSEQ + jj] = __float2half_rn(ts[jj][d]);
    }
}

// ---------------- launch ------------------------------------------------------
extern "C" void kernel_launch(void* const* d_in, const int* in_sizes, int n_in,
                              void* d_out, int out_size)
{
    const float* x    = (const float*)d_in[0];
    const int*   mask = (const int*)d_in[1];
    const float* Wqkv = (const float*)d_in[2];
    const float* Wout = (const float*)d_in[3];
    const float* bout = (const float*)d_in[4];
    float*       out  = (float*)d_out;

    float *wp;
    __half *xs, *atts, *w1s, *w2s, *wQ, *vt;
    cudaGetSymbolAddress((void**)&wp,   g_w);
    cudaGetSymbolAddress((void**)&xs,   g_xs);
    cudaGetSymbolAddress((void**)&atts, g_atts);
    cudaGetSymbolAddress((void**)&w1s,  g_w1s);
    cudaGetSymbolAddress((void**)&w2s,  g_w2s);
    cudaGetSymbolAddress((void**)&wQ,   g_wQ);
    cudaGetSymbolAddress((void**)&vt,   g_vt);

    const int GEMM_SMEM = GSTG * 256 * GP * 2;   // 61440
    cudaFuncSetAttribute(mma_gemm, cudaFuncAttributeMaxDynamicSharedMemorySize, GEMM_SMEM);
    cudaFuncSetAttribute(flash_attn, cudaFuncAttributeMaxDynamicSharedMemorySize, SM_TOT);

    splitA_f16<<<(BATCH*NSEQ*DIM + 255) / 256, 256>>>(x, xs, DIM, (size_t)BATCH*NSEQ*DIM);
    splitB_f16<<<dim3(DIM/32, DIM/32), 256>>>(Wqkv, w1s, DIM, DIM);
    splitB_f16<<<dim3(DIM/32, DIM/32), 256>>>(Wout, w2s, DIM, DIM);

    // stage 1: w = x @ Wqkv  (f16 2-split, K'=2048)
    mma_gemm<<<dim3(DIM/128, (BATCH*NSEQ)/128), 256, GEMM_SMEM>>>(
        (const uint16_t*)xs, 2*DIM, (const uint16_t*)w1s, 2*DIM, wp, DIM, 2*DIM, nullptr);

    wsplit_vt<<<dim3(NSEQ/64, BH), 256>>>(wp, wQ, vt);

    // stage 2+3: fused flash attention -> f16 [hi|lo] atts
    flash_attn<<<dim3(NSEQ/128, BH), 256, SM_TOT>>>(mask);

    // stage 4: out = atts @ Wout + bout  (f16 2-split, K'=2048)
    mma_gemm<<<dim3(DIM/128, (BATCH*NSEQ)/128), 256, GEMM_SMEM>>>(
        (const uint16_t*)atts, 2*DIM, (const uint16_t*)w2s, 2*DIM, out, DIM, 2*DIM, bout);
}

// round 10
// speedup vs baseline: 4.5638x; 1.1159x over previous
#include <cuda_runtime.h>
#include <cuda_bf16.h>
#include <cuda_fp16.h>
#include <cstdint>

#define HEADS 16
#define DHEAD 64
#define BATCH 2
#define NSEQ  2048
#define DIM   1024
#define BH    (BATCH*HEADS)

// ---------------- scratch (__device__ globals; allocation-free) -------------
__device__ __align__(256) float  g_w  [(size_t)BATCH*NSEQ*DIM];
__device__ __align__(256) __half g_xs  [(size_t)BATCH*NSEQ*2*DIM];   // [hi|lo]
__device__ __align__(256) __half g_atts[(size_t)BATCH*NSEQ*2*DIM];   // [hi|lo]
__device__ __align__(256) __half g_w1s [(size_t)DIM*2*DIM];          // [hi|hi]
__device__ __align__(256) __half g_w2s [(size_t)DIM*2*DIM];          // [hi|hi]
__device__ __align__(256) __half g_wQ  [(size_t)BH*NSEQ*128];        // f16 [hi|lo], unscaled
__device__ __align__(256) __half g_vt  [(size_t)BH*DHEAD*NSEQ];

// ---------------- PTX helpers -------------------------------------------------
__device__ __forceinline__ void mma_f16(float* d, const uint32_t* a, const uint32_t* b) {
    asm volatile(
        "mma.sync.aligned.m16n8k16.row.col.f32.f16.f16.f32 "
        "{%0,%1,%2,%3}, {%4,%5,%6,%7}, {%8,%9}, {%0,%1,%2,%3};"
        : "+f"(d[0]), "+f"(d[1]), "+f"(d[2]), "+f"(d[3])
        : "r"(a[0]), "r"(a[1]), "r"(a[2]), "r"(a[3]), "r"(b[0]), "r"(b[1]));
}
__device__ __forceinline__ uint32_t cvta_s(const void* p) {
    return (uint32_t)__cvta_generic_to_shared(p);
}
#define CP_ASYNC16(dst, src) \
    asm volatile("cp.async.cg.shared.global [%0], [%1], 16;" :: "r"(dst), "l"(src))
#define CP_COMMIT() asm volatile("cp.async.commit_group;")
#define CP_WAIT(n)  asm volatile("cp.async.wait_group %0;" :: "n"(n))
#define LDMX4(r0, r1, r2, r3, addr) \
    asm volatile("ldmatrix.sync.aligned.m8n8.x4.shared.b16 {%0,%1,%2,%3}, [%4];" \
        : "=r"(r0), "=r"(r1), "=r"(r2), "=r"(r3) : "r"(addr))

// ---------------------------------------------------------------------------
// HMMA GEMM (f16), cp.async 3-stage pipeline + ldmatrix. (validated R8/R9)
// ---------------------------------------------------------------------------
#define GP   40
#define GSTG 3

__global__ __launch_bounds__(256, 2) void mma_gemm(
    const uint16_t* __restrict__ A, int lda,
    const uint16_t* __restrict__ B, int ldb,
    float* __restrict__ C, int ldc, int K, const float* __restrict__ bias)
{
    extern __shared__ __align__(16) uint16_t gsm[];
    const int tid = threadIdx.x, lane = tid & 31, warp = tid >> 5;
    const int g = lane >> 2, t = lane & 3;
    const int wm0 = (warp >> 2) * 64, wn0 = (warp & 3) * 32;
    const int m0 = blockIdx.y * 128, n0 = blockIdx.x * 128;

    const uint16_t* Ab = A + (size_t)m0 * lda;
    const uint16_t* Bb = B + (size_t)n0 * ldb;
    const uint32_t smb = cvta_s(gsm);

    float acc[4][4][4] = {};
    const int NC = K >> 5;

    auto issue = [&](int c) {
        const uint32_t dst = smb + (uint32_t)(c % GSTG) * (256 * GP * 2);
        const uint16_t* ag = Ab + c * 32;
        const uint16_t* bg = Bb + c * 32;
        #pragma unroll
        for (int i = 0; i < 2; i++) {
            int idx = tid + i * 256;
            int r = idx >> 2, q = (idx & 3) * 8;
            CP_ASYNC16(dst + (uint32_t)(r * GP + q) * 2, ag + (size_t)r * lda + q);
        }
        #pragma unroll
        for (int i = 0; i < 2; i++) {
            int idx = tid + i * 256;
            int r = idx >> 2, q = (idx & 3) * 8;
            CP_ASYNC16(dst + (uint32_t)((128 + r) * GP + q) * 2, bg + (size_t)r * ldb + q);
        }
        CP_COMMIT();
    };

    #pragma unroll
    for (int s = 0; s < GSTG - 1; s++) issue(s);

    for (int c = 0; c < NC; c++) {
        CP_WAIT(GSTG - 2);
        __syncthreads();
        if (c + GSTG - 1 < NC) issue(c + GSTG - 1);
        else                   CP_COMMIT();

        const uint32_t asv = smb + (uint32_t)(c % GSTG) * (256 * GP * 2);
        const uint32_t bsv = asv + 128 * GP * 2;

        #pragma unroll
        for (int ks = 0; ks < 2; ks++) {
            const int kb = ks * 16;
            uint32_t bf[4][2];
            #pragma unroll
            for (int ni2 = 0; ni2 < 2; ni2++) {
                uint32_t r0, r1, r2, r3;
                uint32_t addr = bsv + (uint32_t)(((wn0 + ni2 * 16 + ((lane >> 4) << 3) + (lane & 7)) * GP
                                                 + kb + ((lane >> 3) & 1) * 8) << 1);
                LDMX4(r0, r1, r2, r3, addr);
                bf[ni2 * 2][0] = r0; bf[ni2 * 2][1] = r1;
                bf[ni2 * 2 + 1][0] = r2; bf[ni2 * 2 + 1][1] = r3;
            }
            #pragma unroll
            for (int mi = 0; mi < 4; mi++) {
                uint32_t af[4];
                uint32_t addr = asv + (uint32_t)(((wm0 + mi * 16 + (lane & 15)) * GP
                                                 + kb + (lane >> 4) * 8) << 1);
                LDMX4(af[0], af[1], af[2], af[3], addr);
                #pragma unroll
                for (int ni = 0; ni < 4; ni++) mma_f16(acc[mi][ni], af, bf[ni]);
            }
        }
    }

    float* Cb = C + (size_t)m0 * ldc + n0;
    #pragma unroll
    for (int mi = 0; mi < 4; mi++) {
        #pragma unroll
        for (int ni = 0; ni < 4; ni++) {
            int col = wn0 + ni * 8 + 2 * t;
            float bx = 0.0f, by = 0.0f;
            if (bias) { bx = bias[n0 + col]; by = bias[n0 + col + 1]; }
            int r1 = wm0 + mi * 16 + g;
            *(float2*)(Cb + (size_t)r1 * ldc + col) =
                make_float2(acc[mi][ni][0] + bx, acc[mi][ni][1] + by);
            *(float2*)(Cb + (size_t)(r1 + 8) * ldc + col) =
                make_float2(acc[mi][ni][2] + bx, acc[mi][ni][3] + by);
        }
    }
}

// ---------------------------------------------------------------------------
// Fused flash attention. 128 threads / 4 warps / 64 q-rows per CTA ->
// 3 CTAs (12 warps) per SM. Per-warp work identical to R9 (bit-identical math).
// S = (Qh*Kh + Ql*Kh) * 0.125 f16; f16 PV.
// ---------------------------------------------------------------------------
#define KB    64
#define NIT   (NSEQ / KB)
#define KSP   72
#define VSP   72
#define SM_K0 0
#define SM_K1 9216
#define SM_V0 18432
#define SM_V1 27648
#define SM_M0 36864
#define SM_M1 37120
#define SM_TOT 37376

__global__ __launch_bounds__(128, 3) void flash_attn(const int* __restrict__ mask)
{
    extern __shared__ char sm[];
    const int tid = threadIdx.x, lane = tid & 31, warp = tid >> 5;
    const int g = lane >> 2, t = lane & 3;
    const int i0 = blockIdx.x * 64;
    const int bh = blockIdx.y;
    const int b = bh >> 4, h = bh & 15;

    const uint16_t* wQ = (const uint16_t*)g_wQ + (size_t)bh * NSEQ * 128;
    const uint16_t* vt = (const uint16_t*)g_vt + (size_t)bh * DHEAD * NSEQ;
    const int* mrow = mask + (size_t)b * NSEQ;
    const uint32_t smb = cvta_s(sm);

    auto issue = [&](int it2, int buf) {
        const int j0 = it2 * KB;
        const uint32_t kd = smb + (buf ? SM_K1 : SM_K0);
        const uint32_t vd = smb + (buf ? SM_V1 : SM_V0);
        const uint32_t md = smb + (buf ? SM_M1 : SM_M0);
        #pragma unroll
        for (int i = 0; i < 4; i++) {
            int idx = tid + i * 128;
            int r = idx >> 3, q = (idx & 7) * 8;
            CP_ASYNC16(kd + (uint32_t)(r * KSP + q) * 2, wQ + (size_t)(j0 + r) * 128 + q);
        }
        #pragma unroll
        for (int i = 0; i < 4; i++) {
            int idx = tid + i * 128;
            int r = idx >> 3, q = (idx & 7) * 8;
            CP_ASYNC16(vd + (uint32_t)(r * VSP + q) * 2, vt + (size_t)r * NSEQ + j0 + q);
        }
        if (tid < 16) CP_ASYNC16(md + tid * 16, mrow + j0 + tid * 4);
        CP_COMMIT();
    };

    // Q fragments (rows i0+warp*16+{g,g+8}): 4 hi + 4 lo k16 tiles, unscaled f16
    uint32_t qh[4][4], ql[4][4];
    {
        const uint16_t* q0 = wQ + (size_t)(i0 + warp * 16 + g) * 128 + 2 * t;
        #pragma unroll
        for (int j = 0; j < 4; j++) {
            qh[j][0] = *(const uint32_t*)(q0 + j * 16);
            qh[j][1] = *(const uint32_t*)(q0 + j * 16 + 8 * 128);
            qh[j][2] = *(const uint32_t*)(q0 + j * 16 + 8);
            qh[j][3] = *(const uint32_t*)(q0 + j * 16 + 8 * 128 + 8);
            ql[j][0] = *(const uint32_t*)(q0 + 64 + j * 16);
            ql[j][1] = *(const uint32_t*)(q0 + 64 + j * 16 + 8 * 128);
            ql[j][2] = *(const uint32_t*)(q0 + 64 + j * 16 + 8);
            ql[j][3] = *(const uint32_t*)(q0 + 64 + j * 16 + 8 * 128 + 8);
        }
    }

    float Oa[8][4] = {};
    float mr0 = -1e30f, mr1 = -1e30f, lr0 = 0.0f, lr1 = 0.0f;

    issue(0, 0);
    CP_WAIT(0);
    __syncthreads();

    for (int it = 0; it < NIT; it++) {
        const int cur = it & 1;
        const uint32_t ksv = smb + (cur ? SM_K1 : SM_K0);
        const uint32_t vsv = smb + (cur ? SM_V1 : SM_V0);
        const int* Mi = (const int*)(sm + (cur ? SM_M1 : SM_M0));

        if (it + 1 < NIT) issue(it + 1, cur ^ 1);
        else              CP_COMMIT();

        // ---- S tile: Qh*Kh + Ql*Kh (f16) ----
        float sa[8][4] = {};
        #pragma unroll
        for (int j = 0; j < 4; j++) {
            #pragma unroll
            for (int nt2 = 0; nt2 < 4; nt2++) {
                uint32_t r0, r1, r2, r3;
                uint32_t addr = ksv + (uint32_t)(((nt2 * 16 + ((lane >> 4) << 3) + (lane & 7)) * KSP
                                                 + j * 16 + ((lane >> 3) & 1) * 8) << 1);
                LDMX4(r0, r1, r2, r3, addr);
                uint32_t b0[2] = {r0, r1}, b1[2] = {r2, r3};
                mma_f16(sa[nt2 * 2],     qh[j], b0);
                mma_f16(sa[nt2 * 2 + 1], qh[j], b1);
                mma_f16(sa[nt2 * 2],     ql[j], b0);
                mma_f16(sa[nt2 * 2 + 1], ql[j], b1);
            }
        }
        #pragma unroll
        for (int nt = 0; nt < 8; nt++) {
            sa[nt][0] *= 0.125f; sa[nt][1] *= 0.125f;
            sa[nt][2] *= 0.125f; sa[nt][3] *= 0.125f;
        }

        // ---- online softmax ----
        float bm0 = -1e30f, bm1 = -1e30f;
        #pragma unroll
        for (int nt = 0; nt < 8; nt++) {
            bm0 = fmaxf(bm0, fmaxf(sa[nt][0], sa[nt][1]));
            bm1 = fmaxf(bm1, fmaxf(sa[nt][2], sa[nt][3]));
        }
        bm0 = fmaxf(bm0, __shfl_xor_sync(0xffffffffu, bm0, 1));
        bm0 = fmaxf(bm0, __shfl_xor_sync(0xffffffffu, bm0, 2));
        bm1 = fmaxf(bm1, __shfl_xor_sync(0xffffffffu, bm1, 1));
        bm1 = fmaxf(bm1, __shfl_xor_sync(0xffffffffu, bm1, 2));

        const float mn0 = fmaxf(mr0, bm0), mn1 = fmaxf(mr1, bm1);
        const float sf0 = __expf(mr0 - mn0), sf1 = __expf(mr1 - mn1);
        mr0 = mn0; mr1 = mn1;

        float rs0 = 0.0f, rs1 = 0.0f;
        #pragma unroll
        for (int nt = 0; nt < 8; nt++) {
            sa[nt][0] = __expf(sa[nt][0] - mn0);
            sa[nt][1] = __expf(sa[nt][1] - mn0);
            sa[nt][2] = __expf(sa[nt][2] - mn1);
            sa[nt][3] = __expf(sa[nt][3] - mn1);
            rs0 += sa[nt][0] + sa[nt][1];
            rs1 += sa[nt][2] + sa[nt][3];
        }
        rs0 += __shfl_xor_sync(0xffffffffu, rs0, 1);
        rs0 += __shfl_xor_sync(0xffffffffu, rs0, 2);
        rs1 += __shfl_xor_sync(0xffffffffu, rs1, 1);
        rs1 += __shfl_xor_sync(0xffffffffu, rs1, 2);
        lr0 = lr0 * sf0 + rs0;
        lr1 = lr1 * sf1 + rs1;

        #pragma unroll
        for (int nt = 0; nt < 8; nt++) {
            Oa[nt][0] *= sf0; Oa[nt][1] *= sf0;
            Oa[nt][2] *= sf1; Oa[nt][3] *= sf1;
        }

        // ---- mask + repack P into f16 A-fragments ----
        uint32_t pfra[4][4];
        #pragma unroll
        for (int kt2 = 0; kt2 < 4; kt2++) {
            const int n0t = 2 * kt2, n1t = 2 * kt2 + 1;
            int2 mi0 = *(const int2*)&Mi[n0t * 8 + 2 * t];
            int2 mi1 = *(const int2*)&Mi[n1t * 8 + 2 * t];
            float m0x = 1.0f - (float)mi0.x, m0y = 1.0f - (float)mi0.y;
            float m1x = 1.0f - (float)mi1.x, m1y = 1.0f - (float)mi1.y;
            __half2 a0 = __floats2half2_rn(sa[n0t][0] * m0x, sa[n0t][1] * m0y);
            __half2 a1 = __floats2half2_rn(sa[n0t][2] * m0x, sa[n0t][3] * m0y);
            __half2 a2 = __floats2half2_rn(sa[n1t][0] * m1x, sa[n1t][1] * m1y);
            __half2 a3 = __floats2half2_rn(sa[n1t][2] * m1x, sa[n1t][3] * m1y);
            pfra[kt2][0] = *(uint32_t*)&a0;
            pfra[kt2][1] = *(uint32_t*)&a1;
            pfra[kt2][2] = *(uint32_t*)&a2;
            pfra[kt2][3] = *(uint32_t*)&a3;
        }

        // ---- O += P @ V ----
        #pragma unroll
        for (int nt2 = 0; nt2 < 4; nt2++) {
            #pragma unroll
            for (int kt2 = 0; kt2 < 4; kt2++) {
                uint32_t r0, r1, r2, r3;
                uint32_t addr = vsv + (uint32_t)(((nt2 * 16 + ((lane >> 4) << 3) + (lane & 7)) * VSP
                                                 + kt2 * 16 + ((lane >> 3) & 1) * 8) << 1);
                LDMX4(r0, r1, r2, r3, addr);
                uint32_t b0[2] = {r0, r1}, b1[2] = {r2, r3};
                mma_f16(Oa[nt2 * 2],     pfra[kt2], b0);
                mma_f16(Oa[nt2 * 2 + 1], pfra[kt2], b1);
            }
        }

        CP_WAIT(0);
        __syncthreads();
    }

    // ---- normalize + write f16 [hi|lo] atts rows (2*DIM) ----
    const float inv0 = 1.0f / lr0, inv1 = 1.0f / lr1;
    const int r0 = i0 + warp * 16 + g;
    __half* ob  = g_atts + ((size_t)b * NSEQ + r0) * (2 * DIM) + h * 64;
    __half* ob8 = ob + (size_t)8 * (2 * DIM);
    #pragma unroll
    for (int nt = 0; nt < 8; nt++) {
        #pragma unroll
        for (int e = 0; e < 2; e++) {
            int col = nt * 8 + 2 * t + e;
            float v0 = Oa[nt][e] * inv0;
            __half h0 = __float2half_rn(v0);
            ob[col] = h0; ob[DIM + col] = __float2half_rn(v0 - __half2float(h0));
            float v1 = Oa[nt][2 + e] * inv1;
            __half h1 = __float2half_rn(v1);
            ob8[col] = h1; ob8[DIM + col] = __float2half_rn(v1 - __half2float(h1));
        }
    }
}

// ---------------- converters ---------------------------------------------------
// fp32 [R,K] -> f16 [R,2K] rows [hi|lo]
__global__ void splitA_f16(const float* __restrict__ in, __half* __restrict__ out,
                           int K, size_t total)
{
    size_t idx = (size_t)blockIdx.x * 256 + threadIdx.x;
    if (idx >= total) return;
    size_t r = idx / K; int k = (int)(idx % K);
    float x = in[idx];
    __half hi = __float2half_rn(x);
    __half* o = out + r * (size_t)(2 * K);
    o[k] = hi; o[K + k] = __float2half_rn(x - __half2float(hi));
}

// fp32 W[K,N] -> f16 out[N,2K] rows [hi|hi] (transposed); z selects weight
__global__ __launch_bounds__(256) void splitB_f16_2(const float* __restrict__ W0,
                                                    const float* __restrict__ W1,
                                                    __half* __restrict__ O0,
                                                    __half* __restrict__ O1,
                                                    int Kd, int Nd)
{
    __shared__ float ts[32][33];
    const float* W = blockIdx.z ? W1 : W0;
    __half* out = blockIdx.z ? O1 : O0;
    int k0 = blockIdx.x * 32, n0 = blockIdx.y * 32;
    int tx = threadIdx.x & 31, ty = threadIdx.x >> 5;
    for (int r = ty; r < 32; r += 8) ts[r][tx] = W[(size_t)(k0 + r) * Nd + n0 + tx];
    __syncthreads();
    for (int r = ty; r < 32; r += 8) {
        __half hi = __float2half_rn(ts[tx][r]);
        __half* o = out + (size_t)(n0 + r) * (2 * Kd) + k0 + tx;
        o[0] = hi; o[Kd] = hi;
    }
}

// fused per-head f16 [hi|lo] split + V^T (one read of g_w)
__global__ __launch_bounds__(256) void wsplit_vt(const float* __restrict__ w,
                                                 __half* __restrict__ wQ,
                                                 __half* __restrict__ vt)
{
    __shared__ float ts[64][65];
    int j0 = blockIdx.x * 64, bh = blockIdx.y;
    int b = bh >> 4, h = bh & 15;
    const float* base = w + (size_t)b * NSEQ * DIM + h * 64;
    for (int idx = threadIdx.x; idx < 64 * 16; idx += 256) {
        int jj = idx >> 4, i = idx & 15;
        float4 v = *(const float4*)(base + (size_t)(j0 + jj) * DIM + i * 4);
        ts[jj][i*4] = v.x; ts[jj][i*4+1] = v.y; ts[jj][i*4+2] = v.z; ts[jj][i*4+3] = v.w;
    }
    __syncthreads();
    for (int idx = threadIdx.x; idx < 64 * 64; idx += 256) {
        int jj = idx >> 6, d = idx & 63;
        float v = ts[jj][d];
        size_t rb = ((size_t)bh * NSEQ + j0 + jj) * 128;
        __half hi = __float2half_rn(v);
        wQ[rb + d] = hi;
        wQ[rb + 64 + d] = __float2half_rn(v - __half2float(hi));
    }
    __half* o = vt + (size_t)bh * 64 * NSEQ + j0;
    for (int idx = threadIdx.x; idx < 64 * 64; idx += 256) {
        int d = idx >> 6, jj = idx & 63;
        o[(size_t)d * NSEQ + jj] = __float2half_rn(ts[jj][d]);
    }
}

// ---------------- launch ------------------------------------------------------
extern "C" void kernel_launch(void* const* d_in, const int* in_sizes, int n_in,
                              void* d_out, int out_size)
{
    const float* x    = (const float*)d_in[0];
    const int*   mask = (const int*)d_in[1];
    const float* Wqkv = (const float*)d_in[2];
    const float* Wout = (const float*)d_in[3];
    const float* bout = (const float*)d_in[4];
    float*       out  = (float*)d_out;

    float *wp;
    __half *xs, *atts, *w1s, *w2s, *wQ, *vt;
    cudaGetSymbolAddress((void**)&wp,   g_w);
    cudaGetSymbolAddress((void**)&xs,   g_xs);
    cudaGetSymbolAddress((void**)&atts, g_atts);
    cudaGetSymbolAddress((void**)&w1s,  g_w1s);
    cudaGetSymbolAddress((void**)&w2s,  g_w2s);
    cudaGetSymbolAddress((void**)&wQ,   g_wQ);
    cudaGetSymbolAddress((void**)&vt,   g_vt);

    const int GEMM_SMEM = GSTG * 256 * GP * 2;   // 61440
    cudaFuncSetAttribute(mma_gemm, cudaFuncAttributeMaxDynamicSharedMemorySize, GEMM_SMEM);
    cudaFuncSetAttribute(flash_attn, cudaFuncAttributeMaxDynamicSharedMemorySize, SM_TOT);

    splitA_f16<<<(BATCH*NSEQ*DIM + 255) / 256, 256>>>(x, xs, DIM, (size_t)BATCH*NSEQ*DIM);
    splitB_f16_2<<<dim3(DIM/32, DIM/32, 2), 256>>>(Wqkv, Wout, w1s, w2s, DIM, DIM);

    // stage 1: w = x @ Wqkv  (f16 2-split, K'=2048)
    mma_gemm<<<dim3(DIM/128, (BATCH*NSEQ)/128), 256, GEMM_SMEM>>>(
        (const uint16_t*)xs, 2*DIM, (const uint16_t*)w1s, 2*DIM, wp, DIM, 2*DIM, nullptr);

    wsplit_vt<<<dim3(NSEQ/64, BH), 256>>>(wp, wQ, vt);

    // stage 2+3: fused flash attention -> f16 [hi|lo] atts (64 q-rows/CTA)
    flash_attn<<<dim3(NSEQ/64, BH), 128, SM_TOT>>>(mask);

    // stage 4: out = atts @ Wout + bout  (f16 2-split, K'=2048)
    mma_gemm<<<dim3(DIM/128, (BATCH*NSEQ)/128), 256, GEMM_SMEM>>>(
        (const uint16_t*)atts, 2*DIM, (const uint16_t*)w2s, 2*DIM, out, DIM, 2*DIM, bout);
}

// round 11
// speedup vs baseline: 5.0311x; 1.1024x over previous
#include <cuda_runtime.h>
#include <cuda_bf16.h>
#include <cuda_fp16.h>
#include <cstdint>

#define HEADS 16
#define DHEAD 64
#define BATCH 2
#define NSEQ  2048
#define DIM   1024
#define BH    (BATCH*HEADS)

// ---------------- scratch (__device__ globals; allocation-free) -------------
__device__ __align__(256) __half g_xs  [(size_t)BATCH*NSEQ*2*DIM];   // x [hi|lo]
__device__ __align__(256) __half g_att16[(size_t)BATCH*NSEQ*DIM];    // atts single f16
__device__ __align__(256) __half g_w1s [(size_t)DIM*2*DIM];          // Wqkv^T [hi|hi]
__device__ __align__(256) __half g_w2s [(size_t)DIM*DIM];            // Wout^T single
__device__ __align__(256) __half g_wQ  [(size_t)BH*NSEQ*128];        // f16 [hi|lo], unscaled
__device__ __align__(256) __half g_vt  [(size_t)BH*DHEAD*NSEQ];

// ---------------- PTX helpers -------------------------------------------------
__device__ __forceinline__ void mma_f16(float* d, const uint32_t* a, const uint32_t* b) {
    asm volatile(
        "mma.sync.aligned.m16n8k16.row.col.f32.f16.f16.f32 "
        "{%0,%1,%2,%3}, {%4,%5,%6,%7}, {%8,%9}, {%0,%1,%2,%3};"
        : "+f"(d[0]), "+f"(d[1]), "+f"(d[2]), "+f"(d[3])
        : "r"(a[0]), "r"(a[1]), "r"(a[2]), "r"(a[3]), "r"(b[0]), "r"(b[1]));
}
__device__ __forceinline__ uint32_t cvta_s(const void* p) {
    return (uint32_t)__cvta_generic_to_shared(p);
}
#define CP_ASYNC16(dst, src) \
    asm volatile("cp.async.cg.shared.global [%0], [%1], 16;" :: "r"(dst), "l"(src))
#define CP_COMMIT() asm volatile("cp.async.commit_group;")
#define CP_WAIT(n)  asm volatile("cp.async.wait_group %0;" :: "n"(n))
#define LDMX4(r0, r1, r2, r3, addr) \
    asm volatile("ldmatrix.sync.aligned.m8n8.x4.shared.b16 {%0,%1,%2,%3}, [%4];" \
        : "=r"(r0), "=r"(r1), "=r"(r2), "=r"(r3) : "r"(addr))

// ---------------------------------------------------------------------------
// HMMA GEMM (f16), cp.async 3-stage pipeline + ldmatrix.
// EPI=0: C fp32 (+bias).  EPI=1: fused w-split epilogue -> wQ [hi|lo] + vt.
// ---------------------------------------------------------------------------
#define GP   40
#define GSTG 3

template<int EPI>
__global__ __launch_bounds__(256, 2) void mma_gemm(
    const uint16_t* __restrict__ A, int lda,
    const uint16_t* __restrict__ B, int ldb,
    float* __restrict__ C, int ldc, int K, const float* __restrict__ bias,
    __half* __restrict__ wq, __half* __restrict__ vt)
{
    extern __shared__ __align__(16) uint16_t gsm[];
    const int tid = threadIdx.x, lane = tid & 31, warp = tid >> 5;
    const int g = lane >> 2, t = lane & 3;
    const int wm0 = (warp >> 2) * 64, wn0 = (warp & 3) * 32;
    const int m0 = blockIdx.y * 128, n0 = blockIdx.x * 128;

    const uint16_t* Ab = A + (size_t)m0 * lda;
    const uint16_t* Bb = B + (size_t)n0 * ldb;
    const uint32_t smb = cvta_s(gsm);

    float acc[4][4][4] = {};
    const int NC = K >> 5;

    auto issue = [&](int c) {
        const uint32_t dst = smb + (uint32_t)(c % GSTG) * (256 * GP * 2);
        const uint16_t* ag = Ab + c * 32;
        const uint16_t* bg = Bb + c * 32;
        #pragma unroll
        for (int i = 0; i < 2; i++) {
            int idx = tid + i * 256;
            int r = idx >> 2, q = (idx & 3) * 8;
            CP_ASYNC16(dst + (uint32_t)(r * GP + q) * 2, ag + (size_t)r * lda + q);
        }
        #pragma unroll
        for (int i = 0; i < 2; i++) {
            int idx = tid + i * 256;
            int r = idx >> 2, q = (idx & 3) * 8;
            CP_ASYNC16(dst + (uint32_t)((128 + r) * GP + q) * 2, bg + (size_t)r * ldb + q);
        }
        CP_COMMIT();
    };

    #pragma unroll
    for (int s = 0; s < GSTG - 1; s++) issue(s);

    for (int c = 0; c < NC; c++) {
        CP_WAIT(GSTG - 2);
        __syncthreads();
        if (c + GSTG - 1 < NC) issue(c + GSTG - 1);
        else                   CP_COMMIT();

        const uint32_t asv = smb + (uint32_t)(c % GSTG) * (256 * GP * 2);
        const uint32_t bsv = asv + 128 * GP * 2;

        #pragma unroll
        for (int ks = 0; ks < 2; ks++) {
            const int kb = ks * 16;
            uint32_t bf[4][2];
            #pragma unroll
            for (int ni2 = 0; ni2 < 2; ni2++) {
                uint32_t r0, r1, r2, r3;
                uint32_t addr = bsv + (uint32_t)(((wn0 + ni2 * 16 + ((lane >> 4) << 3) + (lane & 7)) * GP
                                                 + kb + ((lane >> 3) & 1) * 8) << 1);
                LDMX4(r0, r1, r2, r3, addr);
                bf[ni2 * 2][0] = r0; bf[ni2 * 2][1] = r1;
                bf[ni2 * 2 + 1][0] = r2; bf[ni2 * 2 + 1][1] = r3;
            }
            #pragma unroll
            for (int mi = 0; mi < 4; mi++) {
                uint32_t af[4];
                uint32_t addr = asv + (uint32_t)(((wm0 + mi * 16 + (lane & 15)) * GP
                                                 + kb + (lane >> 4) * 8) << 1);
                LDMX4(af[0], af[1], af[2], af[3], addr);
                #pragma unroll
                for (int ni = 0; ni < 4; ni++) mma_f16(acc[mi][ni], af, bf[ni]);
            }
        }
    }

    if (EPI == 0) {
        float* Cb = C + (size_t)m0 * ldc + n0;
        #pragma unroll
        for (int mi = 0; mi < 4; mi++) {
            #pragma unroll
            for (int ni = 0; ni < 4; ni++) {
                int col = wn0 + ni * 8 + 2 * t;
                float bx = 0.0f, by = 0.0f;
                if (bias) { bx = bias[n0 + col]; by = bias[n0 + col + 1]; }
                int r1 = wm0 + mi * 16 + g;
                *(float2*)(Cb + (size_t)r1 * ldc + col) =
                    make_float2(acc[mi][ni][0] + bx, acc[mi][ni][1] + by);
                *(float2*)(Cb + (size_t)(r1 + 8) * ldc + col) =
                    make_float2(acc[mi][ni][2] + bx, acc[mi][ni][3] + by);
            }
        }
    } else {
        // fused w-split: value v at (global row M = (b,nn), global col = (h,d))
        //   wQ[((b*16+h)*2048+nn)*128 + d]      = f16(v)   (hi)
        //   wQ[... + 64 + d]                    = f16(v - hi)
        //   vt[((b*16+h)*64 + d)*2048 + nn]     = f16(v)
        #pragma unroll
        for (int mi = 0; mi < 4; mi++) {
            #pragma unroll
            for (int ni = 0; ni < 4; ni++) {
                const int gc = n0 + wn0 + ni * 8 + 2 * t;
                const int h = gc >> 6, d = gc & 63;
                #pragma unroll
                for (int half_ = 0; half_ < 2; half_++) {
                    const int gr = m0 + wm0 + mi * 16 + g + half_ * 8;
                    const int b = gr >> 11, nn = gr & 2047;
                    const float v0 = acc[mi][ni][half_ * 2];
                    const float v1 = acc[mi][ni][half_ * 2 + 1];
                    const __half h0 = __float2half_rn(v0);
                    const __half h1 = __float2half_rn(v1);
                    const __half l0 = __float2half_rn(v0 - __half2float(h0));
                    const __half l1 = __float2half_rn(v1 - __half2float(h1));
                    size_t qb = (((size_t)(b * 16 + h)) * NSEQ + nn) * 128 + d;
                    __half2 hp; hp.x = h0; hp.y = h1;
                    __half2 lp; lp.x = l0; lp.y = l1;
                    *(__half2*)&wq[qb]      = hp;
                    *(__half2*)&wq[qb + 64] = lp;
                    size_t vb = ((size_t)(b * 16 + h) * 64 + d) * NSEQ + nn;
                    vt[vb]        = h0;
                    vt[vb + NSEQ] = h1;
                }
            }
        }
    }
}

// ---------------------------------------------------------------------------
// Fused flash attention (R10 core, bit-identical math).
// Epilogue writes single-f16 atts.
// ---------------------------------------------------------------------------
#define KB    64
#define NIT   (NSEQ / KB)
#define KSP   72
#define VSP   72
#define SM_K0 0
#define SM_K1 9216
#define SM_V0 18432
#define SM_V1 27648
#define SM_M0 36864
#define SM_M1 37120
#define SM_TOT 37376

__global__ __launch_bounds__(128, 3) void flash_attn(const int* __restrict__ mask)
{
    extern __shared__ char sm[];
    const int tid = threadIdx.x, lane = tid & 31, warp = tid >> 5;
    const int g = lane >> 2, t = lane & 3;
    const int i0 = blockIdx.x * 64;
    const int bh = blockIdx.y;
    const int b = bh >> 4, h = bh & 15;

    const uint16_t* wQ = (const uint16_t*)g_wQ + (size_t)bh * NSEQ * 128;
    const uint16_t* vt = (const uint16_t*)g_vt + (size_t)bh * DHEAD * NSEQ;
    const int* mrow = mask + (size_t)b * NSEQ;
    const uint32_t smb = cvta_s(sm);

    auto issue = [&](int it2, int buf) {
        const int j0 = it2 * KB;
        const uint32_t kd = smb + (buf ? SM_K1 : SM_K0);
        const uint32_t vd = smb + (buf ? SM_V1 : SM_V0);
        const uint32_t md = smb + (buf ? SM_M1 : SM_M0);
        #pragma unroll
        for (int i = 0; i < 4; i++) {
            int idx = tid + i * 128;
            int r = idx >> 3, q = (idx & 7) * 8;
            CP_ASYNC16(kd + (uint32_t)(r * KSP + q) * 2, wQ + (size_t)(j0 + r) * 128 + q);
        }
        #pragma unroll
        for (int i = 0; i < 4; i++) {
            int idx = tid + i * 128;
            int r = idx >> 3, q = (idx & 7) * 8;
            CP_ASYNC16(vd + (uint32_t)(r * VSP + q) * 2, vt + (size_t)r * NSEQ + j0 + q);
        }
        if (tid < 16) CP_ASYNC16(md + tid * 16, mrow + j0 + tid * 4);
        CP_COMMIT();
    };

    uint32_t qh[4][4], ql[4][4];
    {
        const uint16_t* q0 = wQ + (size_t)(i0 + warp * 16 + g) * 128 + 2 * t;
        #pragma unroll
        for (int j = 0; j < 4; j++) {
            qh[j][0] = *(const uint32_t*)(q0 + j * 16);
            qh[j][1] = *(const uint32_t*)(q0 + j * 16 + 8 * 128);
            qh[j][2] = *(const uint32_t*)(q0 + j * 16 + 8);
            qh[j][3] = *(const uint32_t*)(q0 + j * 16 + 8 * 128 + 8);
            ql[j][0] = *(const uint32_t*)(q0 + 64 + j * 16);
            ql[j][1] = *(const uint32_t*)(q0 + 64 + j * 16 + 8 * 128);
            ql[j][2] = *(const uint32_t*)(q0 + 64 + j * 16 + 8);
            ql[j][3] = *(const uint32_t*)(q0 + 64 + j * 16 + 8 * 128 + 8);
        }
    }

    float Oa[8][4] = {};
    float mr0 = -1e30f, mr1 = -1e30f, lr0 = 0.0f, lr1 = 0.0f;

    issue(0, 0);
    CP_WAIT(0);
    __syncthreads();

    for (int it = 0; it < NIT; it++) {
        const int cur = it & 1;
        const uint32_t ksv = smb + (cur ? SM_K1 : SM_K0);
        const uint32_t vsv = smb + (cur ? SM_V1 : SM_V0);
        const int* Mi = (const int*)(sm + (cur ? SM_M1 : SM_M0));

        if (it + 1 < NIT) issue(it + 1, cur ^ 1);
        else              CP_COMMIT();

        float sa[8][4] = {};
        #pragma unroll
        for (int j = 0; j < 4; j++) {
            #pragma unroll
            for (int nt2 = 0; nt2 < 4; nt2++) {
                uint32_t r0, r1, r2, r3;
                uint32_t addr = ksv + (uint32_t)(((nt2 * 16 + ((lane >> 4) << 3) + (lane & 7)) * KSP
                                                 + j * 16 + ((lane >> 3) & 1) * 8) << 1);
                LDMX4(r0, r1, r2, r3, addr);
                uint32_t b0[2] = {r0, r1}, b1[2] = {r2, r3};
                mma_f16(sa[nt2 * 2],     qh[j], b0);
                mma_f16(sa[nt2 * 2 + 1], qh[j], b1);
                mma_f16(sa[nt2 * 2],     ql[j], b0);
                mma_f16(sa[nt2 * 2 + 1], ql[j], b1);
            }
        }
        #pragma unroll
        for (int nt = 0; nt < 8; nt++) {
            sa[nt][0] *= 0.125f; sa[nt][1] *= 0.125f;
            sa[nt][2] *= 0.125f; sa[nt][3] *= 0.125f;
        }

        float bm0 = -1e30f, bm1 = -1e30f;
        #pragma unroll
        for (int nt = 0; nt < 8; nt++) {
            bm0 = fmaxf(bm0, fmaxf(sa[nt][0], sa[nt][1]));
            bm1 = fmaxf(bm1, fmaxf(sa[nt][2], sa[nt][3]));
        }
        bm0 = fmaxf(bm0, __shfl_xor_sync(0xffffffffu, bm0, 1));
        bm0 = fmaxf(bm0, __shfl_xor_sync(0xffffffffu, bm0, 2));
        bm1 = fmaxf(bm1, __shfl_xor_sync(0xffffffffu, bm1, 1));
        bm1 = fmaxf(bm1, __shfl_xor_sync(0xffffffffu, bm1, 2));

        const float mn0 = fmaxf(mr0, bm0), mn1 = fmaxf(mr1, bm1);
        const float sf0 = __expf(mr0 - mn0), sf1 = __expf(mr1 - mn1);
        mr0 = mn0; mr1 = mn1;

        float rs0 = 0.0f, rs1 = 0.0f;
        #pragma unroll
        for (int nt = 0; nt < 8; nt++) {
            sa[nt][0] = __expf(sa[nt][0] - mn0);
            sa[nt][1] = __expf(sa[nt][1] - mn0);
            sa[nt][2] = __expf(sa[nt][2] - mn1);
            sa[nt][3] = __expf(sa[nt][3] - mn1);
            rs0 += sa[nt][0] + sa[nt][1];
            rs1 += sa[nt][2] + sa[nt][3];
        }
        rs0 += __shfl_xor_sync(0xffffffffu, rs0, 1);
        rs0 += __shfl_xor_sync(0xffffffffu, rs0, 2);
        rs1 += __shfl_xor_sync(0xffffffffu, rs1, 1);
        rs1 += __shfl_xor_sync(0xffffffffu, rs1, 2);
        lr0 = lr0 * sf0 + rs0;
        lr1 = lr1 * sf1 + rs1;

        #pragma unroll
        for (int nt = 0; nt < 8; nt++) {
            Oa[nt][0] *= sf0; Oa[nt][1] *= sf0;
            Oa[nt][2] *= sf1; Oa[nt][3] *= sf1;
        }

        uint32_t pfra[4][4];
        #pragma unroll
        for (int kt2 = 0; kt2 < 4; kt2++) {
            const int n0t = 2 * kt2, n1t = 2 * kt2 + 1;
            int2 mi0 = *(const int2*)&Mi[n0t * 8 + 2 * t];
            int2 mi1 = *(const int2*)&Mi[n1t * 8 + 2 * t];
            float m0x = 1.0f - (float)mi0.x, m0y = 1.0f - (float)mi0.y;
            float m1x = 1.0f - (float)mi1.x, m1y = 1.0f - (float)mi1.y;
            __half2 a0 = __floats2half2_rn(sa[n0t][0] * m0x, sa[n0t][1] * m0y);
            __half2 a1 = __floats2half2_rn(sa[n0t][2] * m0x, sa[n0t][3] * m0y);
            __half2 a2 = __floats2half2_rn(sa[n1t][0] * m1x, sa[n1t][1] * m1y);
            __half2 a3 = __floats2half2_rn(sa[n1t][2] * m1x, sa[n1t][3] * m1y);
            pfra[kt2][0] = *(uint32_t*)&a0;
            pfra[kt2][1] = *(uint32_t*)&a1;
            pfra[kt2][2] = *(uint32_t*)&a2;
            pfra[kt2][3] = *(uint32_t*)&a3;
        }

        #pragma unroll
        for (int nt2 = 0; nt2 < 4; nt2++) {
            #pragma unroll
            for (int kt2 = 0; kt2 < 4; kt2++) {
                uint32_t r0, r1, r2, r3;
                uint32_t addr = vsv + (uint32_t)(((nt2 * 16 + ((lane >> 4) << 3) + (lane & 7)) * VSP
                                                 + kt2 * 16 + ((lane >> 3) & 1) * 8) << 1);
                LDMX4(r0, r1, r2, r3, addr);
                uint32_t b0[2] = {r0, r1}, b1[2] = {r2, r3};
                mma_f16(Oa[nt2 * 2],     pfra[kt2], b0);
                mma_f16(Oa[nt2 * 2 + 1], pfra[kt2], b1);
            }
        }

        CP_WAIT(0);
        __syncthreads();
    }

    // ---- normalize + write single-f16 atts (row len DIM) ----
    const float inv0 = 1.0f / lr0, inv1 = 1.0f / lr1;
    const int r0 = i0 + warp * 16 + g;
    __half* ob  = g_att16 + ((size_t)b * NSEQ + r0) * DIM + h * 64;
    __half* ob8 = ob + (size_t)8 * DIM;
    #pragma unroll
    for (int nt = 0; nt < 8; nt++) {
        int col = nt * 8 + 2 * t;
        __half2 p0 = __floats2half2_rn(Oa[nt][0] * inv0, Oa[nt][1] * inv0);
        __half2 p1 = __floats2half2_rn(Oa[nt][2] * inv1, Oa[nt][3] * inv1);
        *(__half2*)&ob[col]  = p0;
        *(__half2*)&ob8[col] = p1;
    }
}

// ---------------- converters ---------------------------------------------------
// fp32 [R,K] -> f16 [R,2K] rows [hi|lo]
__global__ void splitA_f16(const float* __restrict__ in, __half* __restrict__ out,
                           int K, size_t total)
{
    size_t idx = (size_t)blockIdx.x * 256 + threadIdx.x;
    if (idx >= total) return;
    size_t r = idx / K; int k = (int)(idx % K);
    float x = in[idx];
    __half hi = __float2half_rn(x);
    __half* o = out + r * (size_t)(2 * K);
    o[k] = hi; o[K + k] = __float2half_rn(x - __half2float(hi));
}

// fp32 W[K,N] -> f16 out[N,2K] rows [hi|hi] (transposed, duplicated)
__global__ __launch_bounds__(256) void splitB_dup(const float* __restrict__ W,
                                                  __half* __restrict__ out,
                                                  int Kd, int Nd)
{
    __shared__ float ts[32][33];
    int k0 = blockIdx.x * 32, n0 = blockIdx.y * 32;
    int tx = threadIdx.x & 31, ty = threadIdx.x >> 5;
    for (int r = ty; r < 32; r += 8) ts[r][tx] = W[(size_t)(k0 + r) * Nd + n0 + tx];
    __syncthreads();
    for (int r = ty; r < 32; r += 8) {
        __half hi = __float2half_rn(ts[tx][r]);
        __half* o = out + (size_t)(n0 + r) * (2 * Kd) + k0 + tx;
        o[0] = hi; o[Kd] = hi;
    }
}

// fp32 W[K,N] -> f16 out[N,K] (transposed, single)
__global__ __launch_bounds__(256) void splitB_single(const float* __restrict__ W,
                                                     __half* __restrict__ out,
                                                     int Kd, int Nd)
{
    __shared__ float ts[32][33];
    int k0 = blockIdx.x * 32, n0 = blockIdx.y * 32;
    int tx = threadIdx.x & 31, ty = threadIdx.x >> 5;
    for (int r = ty; r < 32; r += 8) ts[r][tx] = W[(size_t)(k0 + r) * Nd + n0 + tx];
    __syncthreads();
    for (int r = ty; r < 32; r += 8)
        out[(size_t)(n0 + r) * Kd + k0 + tx] = __float2half_rn(ts[tx][r]);
}

// ---------------- launch ------------------------------------------------------
extern "C" void kernel_launch(void* const* d_in, const int* in_sizes, int n_in,
                              void* d_out, int out_size)
{
    const float* x    = (const float*)d_in[0];
    const int*   mask = (const int*)d_in[1];
    const float* Wqkv = (const float*)d_in[2];
    const float* Wout = (const float*)d_in[3];
    const float* bout = (const float*)d_in[4];
    float*       out  = (float*)d_out;

    __half *xs, *att16, *w1s, *w2s, *wQ, *vt;
    cudaGetSymbolAddress((void**)&xs,    g_xs);
    cudaGetSymbolAddress((void**)&att16, g_att16);
    cudaGetSymbolAddress((void**)&w1s,   g_w1s);
    cudaGetSymbolAddress((void**)&w2s,   g_w2s);
    cudaGetSymbolAddress((void**)&wQ,    g_wQ);
    cudaGetSymbolAddress((void**)&vt,    g_vt);

    const int GEMM_SMEM = GSTG * 256 * GP * 2;   // 61440
    cudaFuncSetAttribute(mma_gemm<0>, cudaFuncAttributeMaxDynamicSharedMemorySize, GEMM_SMEM);
    cudaFuncSetAttribute(mma_gemm<1>, cudaFuncAttributeMaxDynamicSharedMemorySize, GEMM_SMEM);
    cudaFuncSetAttribute(flash_attn, cudaFuncAttributeMaxDynamicSharedMemorySize, SM_TOT);

    splitA_f16<<<(BATCH*NSEQ*DIM + 255) / 256, 256>>>(x, xs, DIM, (size_t)BATCH*NSEQ*DIM);
    splitB_dup<<<dim3(DIM/32, DIM/32), 256>>>(Wqkv, w1s, DIM, DIM);
    splitB_single<<<dim3(DIM/32, DIM/32), 256>>>(Wout, w2s, DIM, DIM);

    // stage 1: w = x @ Wqkv (f16 2-split, K'=2048) with fused w-split epilogue
    mma_gemm<1><<<dim3(DIM/128, (BATCH*NSEQ)/128), 256, GEMM_SMEM>>>(
        (const uint16_t*)xs, 2*DIM, (const uint16_t*)w1s, 2*DIM,
        nullptr, 0, 2*DIM, nullptr, wQ, vt);

    // stage 2+3: fused flash attention -> single-f16 atts
    flash_attn<<<dim3(NSEQ/64, BH), 128, SM_TOT>>>(mask);

    // stage 4: out = atts @ Wout + bout (single f16, K=1024)
    mma_gemm<0><<<dim3(DIM/128, (BATCH*NSEQ)/128), 256, GEMM_SMEM>>>(
        (const uint16_t*)att16, DIM, (const uint16_t*)w2s, DIM,
        out, DIM, DIM, bout, nullptr, nullptr);
}

// round 12
// speedup vs baseline: 6.7019x; 1.3321x over previous
#include <cuda_runtime.h>
#include <cuda_bf16.h>
#include <cuda_fp16.h>
#include <cstdint>

#define HEADS 16
#define DHEAD 64
#define BATCH 2
#define NSEQ  2048
#define DIM   1024
#define BH    (BATCH*HEADS)

// ---------------- scratch (__device__ globals; allocation-free) -------------
__device__ __align__(256) __half g_xs   [(size_t)BATCH*NSEQ*DIM];    // x f16
__device__ __align__(256) __half g_att16[(size_t)BATCH*NSEQ*DIM];    // atts f16
__device__ __align__(256) __half g_w1s  [(size_t)DIM*DIM];           // Wqkv^T f16
__device__ __align__(256) __half g_w2s  [(size_t)DIM*DIM];           // Wout^T f16
__device__ __align__(256) __half g_wQ   [(size_t)BH*NSEQ*64];        // w per-head f16 (Q=K)
__device__ __align__(256) __half g_vt   [(size_t)BH*DHEAD*NSEQ];     // V^T f16

// ---------------- PTX helpers -------------------------------------------------
__device__ __forceinline__ void mma_f16(float* d, const uint32_t* a, const uint32_t* b) {
    asm volatile(
        "mma.sync.aligned.m16n8k16.row.col.f32.f16.f16.f32 "
        "{%0,%1,%2,%3}, {%4,%5,%6,%7}, {%8,%9}, {%0,%1,%2,%3};"
        : "+f"(d[0]), "+f"(d[1]), "+f"(d[2]), "+f"(d[3])
        : "r"(a[0]), "r"(a[1]), "r"(a[2]), "r"(a[3]), "r"(b[0]), "r"(b[1]));
}
__device__ __forceinline__ uint32_t cvta_s(const void* p) {
    return (uint32_t)__cvta_generic_to_shared(p);
}
#define CP_ASYNC16(dst, src) \
    asm volatile("cp.async.cg.shared.global [%0], [%1], 16;" :: "r"(dst), "l"(src))
#define CP_COMMIT() asm volatile("cp.async.commit_group;")
#define CP_WAIT(n)  asm volatile("cp.async.wait_group %0;" :: "n"(n))
#define LDMX4(r0, r1, r2, r3, addr) \
    asm volatile("ldmatrix.sync.aligned.m8n8.x4.shared.b16 {%0,%1,%2,%3}, [%4];" \
        : "=r"(r0), "=r"(r1), "=r"(r2), "=r"(r3) : "r"(addr))

// ---------------------------------------------------------------------------
// HMMA GEMM (f16), cp.async 3-stage pipeline + ldmatrix.
// EPI=0: C fp32 (+bias).  EPI=1: fused w-split epilogue -> wQ (f16) + vt.
// ---------------------------------------------------------------------------
#define GP   40
#define GSTG 3

template<int EPI>
__global__ __launch_bounds__(256, 2) void mma_gemm(
    const uint16_t* __restrict__ A, int lda,
    const uint16_t* __restrict__ B, int ldb,
    float* __restrict__ C, int ldc, int K, const float* __restrict__ bias,
    __half* __restrict__ wq, __half* __restrict__ vt)
{
    extern __shared__ __align__(16) uint16_t gsm[];
    const int tid = threadIdx.x, lane = tid & 31, warp = tid >> 5;
    const int g = lane >> 2, t = lane & 3;
    const int wm0 = (warp >> 2) * 64, wn0 = (warp & 3) * 32;
    const int m0 = blockIdx.y * 128, n0 = blockIdx.x * 128;

    const uint16_t* Ab = A + (size_t)m0 * lda;
    const uint16_t* Bb = B + (size_t)n0 * ldb;
    const uint32_t smb = cvta_s(gsm);

    float acc[4][4][4] = {};
    const int NC = K >> 5;

    auto issue = [&](int c) {
        const uint32_t dst = smb + (uint32_t)(c % GSTG) * (256 * GP * 2);
        const uint16_t* ag = Ab + c * 32;
        const uint16_t* bg = Bb + c * 32;
        #pragma unroll
        for (int i = 0; i < 2; i++) {
            int idx = tid + i * 256;
            int r = idx >> 2, q = (idx & 3) * 8;
            CP_ASYNC16(dst + (uint32_t)(r * GP + q) * 2, ag + (size_t)r * lda + q);
        }
        #pragma unroll
        for (int i = 0; i < 2; i++) {
            int idx = tid + i * 256;
            int r = idx >> 2, q = (idx & 3) * 8;
            CP_ASYNC16(dst + (uint32_t)((128 + r) * GP + q) * 2, bg + (size_t)r * ldb + q);
        }
        CP_COMMIT();
    };

    #pragma unroll
    for (int s = 0; s < GSTG - 1; s++) issue(s);

    for (int c = 0; c < NC; c++) {
        CP_WAIT(GSTG - 2);
        __syncthreads();
        if (c + GSTG - 1 < NC) issue(c + GSTG - 1);
        else                   CP_COMMIT();

        const uint32_t asv = smb + (uint32_t)(c % GSTG) * (256 * GP * 2);
        const uint32_t bsv = asv + 128 * GP * 2;

        #pragma unroll
        for (int ks = 0; ks < 2; ks++) {
            const int kb = ks * 16;
            uint32_t bf[4][2];
            #pragma unroll
            for (int ni2 = 0; ni2 < 2; ni2++) {
                uint32_t r0, r1, r2, r3;
                uint32_t addr = bsv + (uint32_t)(((wn0 + ni2 * 16 + ((lane >> 4) << 3) + (lane & 7)) * GP
                                                 + kb + ((lane >> 3) & 1) * 8) << 1);
                LDMX4(r0, r1, r2, r3, addr);
                bf[ni2 * 2][0] = r0; bf[ni2 * 2][1] = r1;
                bf[ni2 * 2 + 1][0] = r2; bf[ni2 * 2 + 1][1] = r3;
            }
            #pragma unroll
            for (int mi = 0; mi < 4; mi++) {
                uint32_t af[4];
                uint32_t addr = asv + (uint32_t)(((wm0 + mi * 16 + (lane & 15)) * GP
                                                 + kb + (lane >> 4) * 8) << 1);
                LDMX4(af[0], af[1], af[2], af[3], addr);
                #pragma unroll
                for (int ni = 0; ni < 4; ni++) mma_f16(acc[mi][ni], af, bf[ni]);
            }
        }
    }

    if (EPI == 0) {
        float* Cb = C + (size_t)m0 * ldc + n0;
        #pragma unroll
        for (int mi = 0; mi < 4; mi++) {
            #pragma unroll
            for (int ni = 0; ni < 4; ni++) {
                int col = wn0 + ni * 8 + 2 * t;
                float bx = 0.0f, by = 0.0f;
                if (bias) { bx = bias[n0 + col]; by = bias[n0 + col + 1]; }
                int r1 = wm0 + mi * 16 + g;
                *(float2*)(Cb + (size_t)r1 * ldc + col) =
                    make_float2(acc[mi][ni][0] + bx, acc[mi][ni][1] + by);
                *(float2*)(Cb + (size_t)(r1 + 8) * ldc + col) =
                    make_float2(acc[mi][ni][2] + bx, acc[mi][ni][3] + by);
            }
        }
    } else {
        // fused w epilogue: value v at (row = (b,nn), col = (h,d))
        //   wQ[((b*16+h)*2048+nn)*64 + d]   = f16(v)
        //   vt[((b*16+h)*64 + d)*2048 + nn] = f16(v)
        #pragma unroll
        for (int mi = 0; mi < 4; mi++) {
            #pragma unroll
            for (int ni = 0; ni < 4; ni++) {
                const int gc = n0 + wn0 + ni * 8 + 2 * t;
                const int h = gc >> 6, d = gc & 63;
                #pragma unroll
                for (int half_ = 0; half_ < 2; half_++) {
                    const int gr = m0 + wm0 + mi * 16 + g + half_ * 8;
                    const int b = gr >> 11, nn = gr & 2047;
                    const __half h0 = __float2half_rn(acc[mi][ni][half_ * 2]);
                    const __half h1 = __float2half_rn(acc[mi][ni][half_ * 2 + 1]);
                    __half2 hp; hp.x = h0; hp.y = h1;
                    *(__half2*)&wq[(((size_t)(b * 16 + h)) * NSEQ + nn) * 64 + d] = hp;
                    size_t vb = ((size_t)(b * 16 + h) * 64 + d) * NSEQ + nn;
                    vt[vb]        = h0;
                    vt[vb + NSEQ] = h1;
                }
            }
        }
    }
}

// ---------------------------------------------------------------------------
// Fused flash attention. S = (Qh*Kh) * 0.125 (pure f16, K=64); f16 PV.
// 128 threads / 4 warps / 64 q-rows per CTA; 3 CTAs/SM.
// ---------------------------------------------------------------------------
#define KB    64
#define NIT   (NSEQ / KB)
#define KSP   72
#define VSP   72
#define SM_K0 0
#define SM_K1 9216
#define SM_V0 18432
#define SM_V1 27648
#define SM_M0 36864
#define SM_M1 37120
#define SM_TOT 37376

__global__ __launch_bounds__(128, 3) void flash_attn(const int* __restrict__ mask)
{
    extern __shared__ char sm[];
    const int tid = threadIdx.x, lane = tid & 31, warp = tid >> 5;
    const int g = lane >> 2, t = lane & 3;
    const int i0 = blockIdx.x * 64;
    const int bh = blockIdx.y;
    const int b = bh >> 4, h = bh & 15;

    const uint16_t* wQ = (const uint16_t*)g_wQ + (size_t)bh * NSEQ * 64;
    const uint16_t* vt = (const uint16_t*)g_vt + (size_t)bh * DHEAD * NSEQ;
    const int* mrow = mask + (size_t)b * NSEQ;
    const uint32_t smb = cvta_s(sm);

    auto issue = [&](int it2, int buf) {
        const int j0 = it2 * KB;
        const uint32_t kd = smb + (buf ? SM_K1 : SM_K0);
        const uint32_t vd = smb + (buf ? SM_V1 : SM_V0);
        const uint32_t md = smb + (buf ? SM_M1 : SM_M0);
        #pragma unroll
        for (int i = 0; i < 4; i++) {
            int idx = tid + i * 128;
            int r = idx >> 3, q = (idx & 7) * 8;
            CP_ASYNC16(kd + (uint32_t)(r * KSP + q) * 2, wQ + (size_t)(j0 + r) * 64 + q);
        }
        #pragma unroll
        for (int i = 0; i < 4; i++) {
            int idx = tid + i * 128;
            int r = idx >> 3, q = (idx & 7) * 8;
            CP_ASYNC16(vd + (uint32_t)(r * VSP + q) * 2, vt + (size_t)r * NSEQ + j0 + q);
        }
        if (tid < 16) CP_ASYNC16(md + tid * 16, mrow + j0 + tid * 4);
        CP_COMMIT();
    };

    // Q fragments (rows i0+warp*16+{g,g+8}): 4 k16 tiles over 64 dims
    uint32_t qh[4][4];
    {
        const uint16_t* q0 = wQ + (size_t)(i0 + warp * 16 + g) * 64 + 2 * t;
        #pragma unroll
        for (int j = 0; j < 4; j++) {
            qh[j][0] = *(const uint32_t*)(q0 + j * 16);
            qh[j][1] = *(const uint32_t*)(q0 + j * 16 + 8 * 64);
            qh[j][2] = *(const uint32_t*)(q0 + j * 16 + 8);
            qh[j][3] = *(const uint32_t*)(q0 + j * 16 + 8 * 64 + 8);
        }
    }

    float Oa[8][4] = {};
    float mr0 = -1e30f, mr1 = -1e30f, lr0 = 0.0f, lr1 = 0.0f;

    issue(0, 0);
    CP_WAIT(0);
    __syncthreads();

    for (int it = 0; it < NIT; it++) {
        const int cur = it & 1;
        const uint32_t ksv = smb + (cur ? SM_K1 : SM_K0);
        const uint32_t vsv = smb + (cur ? SM_V1 : SM_V0);
        const int* Mi = (const int*)(sm + (cur ? SM_M1 : SM_M0));

        if (it + 1 < NIT) issue(it + 1, cur ^ 1);
        else              CP_COMMIT();

        // ---- S tile: Qh*Kh (pure f16) ----
        float sa[8][4] = {};
        #pragma unroll
        for (int j = 0; j < 4; j++) {
            #pragma unroll
            for (int nt2 = 0; nt2 < 4; nt2++) {
                uint32_t r0, r1, r2, r3;
                uint32_t addr = ksv + (uint32_t)(((nt2 * 16 + ((lane >> 4) << 3) + (lane & 7)) * KSP
                                                 + j * 16 + ((lane >> 3) & 1) * 8) << 1);
                LDMX4(r0, r1, r2, r3, addr);
                uint32_t b0[2] = {r0, r1}, b1[2] = {r2, r3};
                mma_f16(sa[nt2 * 2],     qh[j], b0);
                mma_f16(sa[nt2 * 2 + 1], qh[j], b1);
            }
        }
        #pragma unroll
        for (int nt = 0; nt < 8; nt++) {
            sa[nt][0] *= 0.125f; sa[nt][1] *= 0.125f;
            sa[nt][2] *= 0.125f; sa[nt][3] *= 0.125f;
        }

        // ---- online softmax ----
        float bm0 = -1e30f, bm1 = -1e30f;
        #pragma unroll
        for (int nt = 0; nt < 8; nt++) {
            bm0 = fmaxf(bm0, fmaxf(sa[nt][0], sa[nt][1]));
            bm1 = fmaxf(bm1, fmaxf(sa[nt][2], sa[nt][3]));
        }
        bm0 = fmaxf(bm0, __shfl_xor_sync(0xffffffffu, bm0, 1));
        bm0 = fmaxf(bm0, __shfl_xor_sync(0xffffffffu, bm0, 2));
        bm1 = fmaxf(bm1, __shfl_xor_sync(0xffffffffu, bm1, 1));
        bm1 = fmaxf(bm1, __shfl_xor_sync(0xffffffffu, bm1, 2));

        const float mn0 = fmaxf(mr0, bm0), mn1 = fmaxf(mr1, bm1);
        const float sf0 = __expf(mr0 - mn0), sf1 = __expf(mr1 - mn1);
        mr0 = mn0; mr1 = mn1;

        float rs0 = 0.0f, rs1 = 0.0f;
        #pragma unroll
        for (int nt = 0; nt < 8; nt++) {
            sa[nt][0] = __expf(sa[nt][0] - mn0);
            sa[nt][1] = __expf(sa[nt][1] - mn0);
            sa[nt][2] = __expf(sa[nt][2] - mn1);
            sa[nt][3] = __expf(sa[nt][3] - mn1);
            rs0 += sa[nt][0] + sa[nt][1];
            rs1 += sa[nt][2] + sa[nt][3];
        }
        rs0 += __shfl_xor_sync(0xffffffffu, rs0, 1);
        rs0 += __shfl_xor_sync(0xffffffffu, rs0, 2);
        rs1 += __shfl_xor_sync(0xffffffffu, rs1, 1);
        rs1 += __shfl_xor_sync(0xffffffffu, rs1, 2);
        lr0 = lr0 * sf0 + rs0;
        lr1 = lr1 * sf1 + rs1;

        #pragma unroll
        for (int nt = 0; nt < 8; nt++) {
            Oa[nt][0] *= sf0; Oa[nt][1] *= sf0;
            Oa[nt][2] *= sf1; Oa[nt][3] *= sf1;
        }

        // ---- mask + repack P into f16 A-fragments ----
        uint32_t pfra[4][4];
        #pragma unroll
        for (int kt2 = 0; kt2 < 4; kt2++) {
            const int n0t = 2 * kt2, n1t = 2 * kt2 + 1;
            int2 mi0 = *(const int2*)&Mi[n0t * 8 + 2 * t];
            int2 mi1 = *(const int2*)&Mi[n1t * 8 + 2 * t];
            float m0x = 1.0f - (float)mi0.x, m0y = 1.0f - (float)mi0.y;
            float m1x = 1.0f - (float)mi1.x, m1y = 1.0f - (float)mi1.y;
            __half2 a0 = __floats2half2_rn(sa[n0t][0] * m0x, sa[n0t][1] * m0y);
            __half2 a1 = __floats2half2_rn(sa[n0t][2] * m0x, sa[n0t][3] * m0y);
            __half2 a2 = __floats2half2_rn(sa[n1t][0] * m1x, sa[n1t][1] * m1y);
            __half2 a3 = __floats2half2_rn(sa[n1t][2] * m1x, sa[n1t][3] * m1y);
            pfra[kt2][0] = *(uint32_t*)&a0;
            pfra[kt2][1] = *(uint32_t*)&a1;
            pfra[kt2][2] = *(uint32_t*)&a2;
            pfra[kt2][3] = *(uint32_t*)&a3;
        }

        // ---- O += P @ V ----
        #pragma unroll
        for (int nt2 = 0; nt2 < 4; nt2++) {
            #pragma unroll
            for (int kt2 = 0; kt2 < 4; kt2++) {
                uint32_t r0, r1, r2, r3;
                uint32_t addr = vsv + (uint32_t)(((nt2 * 16 + ((lane >> 4) << 3) + (lane & 7)) * VSP
                                                 + kt2 * 16 + ((lane >> 3) & 1) * 8) << 1);
                LDMX4(r0, r1, r2, r3, addr);
                uint32_t b0[2] = {r0, r1}, b1[2] = {r2, r3};
                mma_f16(Oa[nt2 * 2],     pfra[kt2], b0);
                mma_f16(Oa[nt2 * 2 + 1], pfra[kt2], b1);
            }
        }

        CP_WAIT(0);
        __syncthreads();
    }

    // ---- normalize + write single-f16 atts (row len DIM) ----
    const float inv0 = 1.0f / lr0, inv1 = 1.0f / lr1;
    const int r0 = i0 + warp * 16 + g;
    __half* ob  = g_att16 + ((size_t)b * NSEQ + r0) * DIM + h * 64;
    __half* ob8 = ob + (size_t)8 * DIM;
    #pragma unroll
    for (int nt = 0; nt < 8; nt++) {
        int col = nt * 8 + 2 * t;
        __half2 p0 = __floats2half2_rn(Oa[nt][0] * inv0, Oa[nt][1] * inv0);
        __half2 p1 = __floats2half2_rn(Oa[nt][2] * inv1, Oa[nt][3] * inv1);
        *(__half2*)&ob[col]  = p0;
        *(__half2*)&ob8[col] = p1;
    }
}

// ---------------- converters ---------------------------------------------------
// fp32 -> f16 elementwise cast (vectorized 4/thread)
__global__ void cast_f16(const float* __restrict__ in, __half* __restrict__ out,
                         size_t total4)
{
    size_t idx = (size_t)blockIdx.x * 256 + threadIdx.x;
    if (idx >= total4) return;
    float4 v = *(const float4*)(in + idx * 4);
    __half2 a = __floats2half2_rn(v.x, v.y);
    __half2 b = __floats2half2_rn(v.z, v.w);
    *(__half2*)(out + idx * 4)     = a;
    *(__half2*)(out + idx * 4 + 2) = b;
}

// fp32 W[K,N] -> f16 out[N,K] (transposed, single); z selects weight
__global__ __launch_bounds__(256) void splitB_single2(const float* __restrict__ W0,
                                                      const float* __restrict__ W1,
                                                      __half* __restrict__ O0,
                                                      __half* __restrict__ O1,
                                                      int Kd, int Nd)
{
    __shared__ float ts[32][33];
    const float* W = blockIdx.z ? W1 : W0;
    __half* out = blockIdx.z ? O1 : O0;
    int k0 = blockIdx.x * 32, n0 = blockIdx.y * 32;
    int tx = threadIdx.x & 31, ty = threadIdx.x >> 5;
    for (int r = ty; r < 32; r += 8) ts[r][tx] = W[(size_t)(k0 + r) * Nd + n0 + tx];
    __syncthreads();
    for (int r = ty; r < 32; r += 8)
        out[(size_t)(n0 + r) * Kd + k0 + tx] = __float2half_rn(ts[tx][r]);
}

// ---------------- launch ------------------------------------------------------
extern "C" void kernel_launch(void* const* d_in, const int* in_sizes, int n_in,
                              void* d_out, int out_size)
{
    const float* x    = (const float*)d_in[0];
    const int*   mask = (const int*)d_in[1];
    const float* Wqkv = (const float*)d_in[2];
    const float* Wout = (const float*)d_in[3];
    const float* bout = (const float*)d_in[4];
    float*       out  = (float*)d_out;

    __half *xs, *att16, *w1s, *w2s, *wQ, *vt;
    cudaGetSymbolAddress((void**)&xs,    g_xs);
    cudaGetSymbolAddress((void**)&att16, g_att16);
    cudaGetSymbolAddress((void**)&w1s,   g_w1s);
    cudaGetSymbolAddress((void**)&w2s,   g_w2s);
    cudaGetSymbolAddress((void**)&wQ,    g_wQ);
    cudaGetSymbolAddress((void**)&vt,    g_vt);

    const int GEMM_SMEM = GSTG * 256 * GP * 2;   // 61440
    cudaFuncSetAttribute(mma_gemm<0>, cudaFuncAttributeMaxDynamicSharedMemorySize, GEMM_SMEM);
    cudaFuncSetAttribute(mma_gemm<1>, cudaFuncAttributeMaxDynamicSharedMemorySize, GEMM_SMEM);
    cudaFuncSetAttribute(flash_attn, cudaFuncAttributeMaxDynamicSharedMemorySize, SM_TOT);

    cast_f16<<<((BATCH*NSEQ*DIM/4) + 255) / 256, 256>>>(x, xs, (size_t)BATCH*NSEQ*DIM/4);
    splitB_single2<<<dim3(DIM/32, DIM/32, 2), 256>>>(Wqkv, Wout, w1s, w2s, DIM, DIM);

    // stage 1: w = x @ Wqkv (pure f16, K=1024) with fused w epilogue -> wQ + vt
    mma_gemm<1><<<dim3(DIM/128, (BATCH*NSEQ)/128), 256, GEMM_SMEM>>>(
        (const uint16_t*)xs, DIM, (const uint16_t*)w1s, DIM,
        nullptr, 0, DIM, nullptr, wQ, vt);

    // stage 2+3: fused flash attention -> single-f16 atts
    flash_attn<<<dim3(NSEQ/64, BH), 128, SM_TOT>>>(mask);

    // stage 4: out = atts @ Wout + bout (f16, K=1024)
    mma_gemm<0><<<dim3(DIM/128, (BATCH*NSEQ)/128), 256, GEMM_SMEM>>>(
        (const uint16_t*)att16, DIM, (const uint16_t*)w2s, DIM,
        out, DIM, DIM, bout, nullptr, nullptr);
}

// round 13
// speedup vs baseline: 7.3573x; 1.0978x over previous
#include <cuda_runtime.h>
#include <cuda_bf16.h>
#include <cuda_fp16.h>
#include <cstdint>

#define HEADS 16
#define DHEAD 64
#define BATCH 2
#define NSEQ  2048
#define DIM   1024
#define BH    (BATCH*HEADS)

// ---------------- scratch (__device__ globals; allocation-free) -------------
__device__ __align__(256) __half g_xs   [(size_t)BATCH*NSEQ*DIM];    // x f16
__device__ __align__(256) __half g_att16[(size_t)BATCH*NSEQ*DIM];    // atts f16
__device__ __align__(256) __half g_w1s  [(size_t)DIM*DIM];           // Wqkv^T f16
__device__ __align__(256) __half g_w2s  [(size_t)DIM*DIM];           // Wout^T f16
__device__ __align__(256) __half g_wQ   [(size_t)BH*NSEQ*64];        // sqrt(scale)*w per-head f16
__device__ __align__(256) __half g_vt   [(size_t)BH*DHEAD*NSEQ];     // V^T f16, mask-zeroed rows

// ---------------- PTX helpers -------------------------------------------------
__device__ __forceinline__ void mma_f16(float* d, const uint32_t* a, const uint32_t* b) {
    asm volatile(
        "mma.sync.aligned.m16n8k16.row.col.f32.f16.f16.f32 "
        "{%0,%1,%2,%3}, {%4,%5,%6,%7}, {%8,%9}, {%0,%1,%2,%3};"
        : "+f"(d[0]), "+f"(d[1]), "+f"(d[2]), "+f"(d[3])
        : "r"(a[0]), "r"(a[1]), "r"(a[2]), "r"(a[3]), "r"(b[0]), "r"(b[1]));
}
__device__ __forceinline__ uint32_t cvta_s(const void* p) {
    return (uint32_t)__cvta_generic_to_shared(p);
}
#define CP_ASYNC16(dst, src) \
    asm volatile("cp.async.cg.shared.global [%0], [%1], 16;" :: "r"(dst), "l"(src))
#define CP_COMMIT() asm volatile("cp.async.commit_group;")
#define CP_WAIT(n)  asm volatile("cp.async.wait_group %0;" :: "n"(n))
#define LDMX4(r0, r1, r2, r3, addr) \
    asm volatile("ldmatrix.sync.aligned.m8n8.x4.shared.b16 {%0,%1,%2,%3}, [%4];" \
        : "=r"(r0), "=r"(r1), "=r"(r2), "=r"(r3) : "r"(addr))

// ---------------------------------------------------------------------------
// HMMA GEMM (f16), cp.async 3-stage pipeline + ldmatrix.
// EPI=0: C fp32 (+bias).
// EPI=1: fused epilogue -> wQ = f16(sqrt(0.125)*v), vt = f16(v)*(1-mask[row]).
// ---------------------------------------------------------------------------
#define GP   40
#define GSTG 3

template<int EPI>
__global__ __launch_bounds__(256, 2) void mma_gemm(
    const uint16_t* __restrict__ A, int lda,
    const uint16_t* __restrict__ B, int ldb,
    float* __restrict__ C, int ldc, int K, const float* __restrict__ bias,
    __half* __restrict__ wq, __half* __restrict__ vt,
    const int* __restrict__ maskp)
{
    extern __shared__ __align__(16) uint16_t gsm[];
    const int tid = threadIdx.x, lane = tid & 31, warp = tid >> 5;
    const int g = lane >> 2, t = lane & 3;
    const int wm0 = (warp >> 2) * 64, wn0 = (warp & 3) * 32;
    const int m0 = blockIdx.y * 128, n0 = blockIdx.x * 128;

    const uint16_t* Ab = A + (size_t)m0 * lda;
    const uint16_t* Bb = B + (size_t)n0 * ldb;
    const uint32_t smb = cvta_s(gsm);

    float acc[4][4][4] = {};
    const int NC = K >> 5;

    auto issue = [&](int c) {
        const uint32_t dst = smb + (uint32_t)(c % GSTG) * (256 * GP * 2);
        const uint16_t* ag = Ab + c * 32;
        const uint16_t* bg = Bb + c * 32;
        #pragma unroll
        for (int i = 0; i < 2; i++) {
            int idx = tid + i * 256;
            int r = idx >> 2, q = (idx & 3) * 8;
            CP_ASYNC16(dst + (uint32_t)(r * GP + q) * 2, ag + (size_t)r * lda + q);
        }
        #pragma unroll
        for (int i = 0; i < 2; i++) {
            int idx = tid + i * 256;
            int r = idx >> 2, q = (idx & 3) * 8;
            CP_ASYNC16(dst + (uint32_t)((128 + r) * GP + q) * 2, bg + (size_t)r * ldb + q);
        }
        CP_COMMIT();
    };

    #pragma unroll
    for (int s = 0; s < GSTG - 1; s++) issue(s);

    for (int c = 0; c < NC; c++) {
        CP_WAIT(GSTG - 2);
        __syncthreads();
        if (c + GSTG - 1 < NC) issue(c + GSTG - 1);
        else                   CP_COMMIT();

        const uint32_t asv = smb + (uint32_t)(c % GSTG) * (256 * GP * 2);
        const uint32_t bsv = asv + 128 * GP * 2;

        #pragma unroll
        for (int ks = 0; ks < 2; ks++) {
            const int kb = ks * 16;
            uint32_t bf[4][2];
            #pragma unroll
            for (int ni2 = 0; ni2 < 2; ni2++) {
                uint32_t r0, r1, r2, r3;
                uint32_t addr = bsv + (uint32_t)(((wn0 + ni2 * 16 + ((lane >> 4) << 3) + (lane & 7)) * GP
                                                 + kb + ((lane >> 3) & 1) * 8) << 1);
                LDMX4(r0, r1, r2, r3, addr);
                bf[ni2 * 2][0] = r0; bf[ni2 * 2][1] = r1;
                bf[ni2 * 2 + 1][0] = r2; bf[ni2 * 2 + 1][1] = r3;
            }
            #pragma unroll
            for (int mi = 0; mi < 4; mi++) {
                uint32_t af[4];
                uint32_t addr = asv + (uint32_t)(((wm0 + mi * 16 + (lane & 15)) * GP
                                                 + kb + (lane >> 4) * 8) << 1);
                LDMX4(af[0], af[1], af[2], af[3], addr);
                #pragma unroll
                for (int ni = 0; ni < 4; ni++) mma_f16(acc[mi][ni], af, bf[ni]);
            }
        }
    }

    if (EPI == 0) {
        float* Cb = C + (size_t)m0 * ldc + n0;
        #pragma unroll
        for (int mi = 0; mi < 4; mi++) {
            #pragma unroll
            for (int ni = 0; ni < 4; ni++) {
                int col = wn0 + ni * 8 + 2 * t;
                float bx = 0.0f, by = 0.0f;
                if (bias) { bx = bias[n0 + col]; by = bias[n0 + col + 1]; }
                int r1 = wm0 + mi * 16 + g;
                *(float2*)(Cb + (size_t)r1 * ldc + col) =
                    make_float2(acc[mi][ni][0] + bx, acc[mi][ni][1] + by);
                *(float2*)(Cb + (size_t)(r1 + 8) * ldc + col) =
                    make_float2(acc[mi][ni][2] + bx, acc[mi][ni][3] + by);
            }
        }
    } else {
        const float QS = 0.35355339059327376f;   // sqrt(0.125)
        #pragma unroll
        for (int mi = 0; mi < 4; mi++) {
            #pragma unroll
            for (int half_ = 0; half_ < 2; half_++) {
                const int gr = m0 + wm0 + mi * 16 + g + half_ * 8;
                const int b = gr >> 11, nn = gr & 2047;
                const float keep = 1.0f - (float)maskp[(size_t)b * NSEQ + nn];
                #pragma unroll
                for (int ni = 0; ni < 4; ni++) {
                    const int gc = n0 + wn0 + ni * 8 + 2 * t;
                    const int h = gc >> 6, d = gc & 63;
                    const float v0 = acc[mi][ni][half_ * 2];
                    const float v1 = acc[mi][ni][half_ * 2 + 1];
                    __half2 qp = __floats2half2_rn(v0 * QS, v1 * QS);
                    *(__half2*)&wq[(((size_t)(b * 16 + h)) * NSEQ + nn) * 64 + d] = qp;
                    const __half h0 = __float2half_rn(v0 * keep);
                    const __half h1 = __float2half_rn(v1 * keep);
                    size_t vb = ((size_t)(b * 16 + h) * 64 + d) * NSEQ + nn;
                    vt[vb]        = h0;
                    vt[vb + NSEQ] = h1;
                }
            }
        }
    }
}

// ---------------------------------------------------------------------------
// Fused flash attention. Q/K pre-scaled by sqrt(0.125); V pre-masked.
// l accumulated as an extra mma tile with an all-ones B fragment (no smem).
// 128 threads / 4 warps / 64 q-rows per CTA; 3 CTAs/SM.
// ---------------------------------------------------------------------------
#define KB    64
#define NIT   (NSEQ / KB)
#define KSP   72
#define VSP   72
#define SM_K0 0
#define SM_K1 9216
#define SM_V0 18432
#define SM_V1 27648
#define SM_TOT 36864

__global__ __launch_bounds__(128, 3) void flash_attn()
{
    extern __shared__ char sm[];
    const int tid = threadIdx.x, lane = tid & 31, warp = tid >> 5;
    const int g = lane >> 2, t = lane & 3;
    const int i0 = blockIdx.x * 64;
    const int bh = blockIdx.y;
    const int b = bh >> 4, h = bh & 15;

    const uint16_t* wQ = (const uint16_t*)g_wQ + (size_t)bh * NSEQ * 64;
    const uint16_t* vt = (const uint16_t*)g_vt + (size_t)bh * DHEAD * NSEQ;
    const uint32_t smb = cvta_s(sm);

    auto issue = [&](int it2, int buf) {
        const int j0 = it2 * KB;
        const uint32_t kd = smb + (buf ? SM_K1 : SM_K0);
        const uint32_t vd = smb + (buf ? SM_V1 : SM_V0);
        #pragma unroll
        for (int i = 0; i < 4; i++) {
            int idx = tid + i * 128;
            int r = idx >> 3, q = (idx & 7) * 8;
            CP_ASYNC16(kd + (uint32_t)(r * KSP + q) * 2, wQ + (size_t)(j0 + r) * 64 + q);
        }
        #pragma unroll
        for (int i = 0; i < 4; i++) {
            int idx = tid + i * 128;
            int r = idx >> 3, q = (idx & 7) * 8;
            CP_ASYNC16(vd + (uint32_t)(r * VSP + q) * 2, vt + (size_t)r * NSEQ + j0 + q);
        }
        CP_COMMIT();
    };

    // Q fragments (rows i0+warp*16+{g,g+8}): 4 k16 tiles, pre-scaled f16
    uint32_t qh[4][4];
    {
        const uint16_t* q0 = wQ + (size_t)(i0 + warp * 16 + g) * 64 + 2 * t;
        #pragma unroll
        for (int j = 0; j < 4; j++) {
            qh[j][0] = *(const uint32_t*)(q0 + j * 16);
            qh[j][1] = *(const uint32_t*)(q0 + j * 16 + 8 * 64);
            qh[j][2] = *(const uint32_t*)(q0 + j * 16 + 8);
            qh[j][3] = *(const uint32_t*)(q0 + j * 16 + 8 * 64 + 8);
        }
    }

    float Oa[8][4] = {};
    float lacc[4] = {};
    float mr0 = -1e30f, mr1 = -1e30f;
    const uint32_t ones2[2] = {0x3C003C00u, 0x3C003C00u};

    issue(0, 0);
    CP_WAIT(0);
    __syncthreads();

    for (int it = 0; it < NIT; it++) {
        const int cur = it & 1;
        const uint32_t ksv = smb + (cur ? SM_K1 : SM_K0);
        const uint32_t vsv = smb + (cur ? SM_V1 : SM_V0);

        if (it + 1 < NIT) issue(it + 1, cur ^ 1);
        else              CP_COMMIT();

        // ---- S tile: Q*K (pre-scaled f16) ----
        float sa[8][4] = {};
        #pragma unroll
        for (int j = 0; j < 4; j++) {
            #pragma unroll
            for (int nt2 = 0; nt2 < 4; nt2++) {
                uint32_t r0, r1, r2, r3;
                uint32_t addr = ksv + (uint32_t)(((nt2 * 16 + ((lane >> 4) << 3) + (lane & 7)) * KSP
                                                 + j * 16 + ((lane >> 3) & 1) * 8) << 1);
                LDMX4(r0, r1, r2, r3, addr);
                uint32_t b0[2] = {r0, r1}, b1[2] = {r2, r3};
                mma_f16(sa[nt2 * 2],     qh[j], b0);
                mma_f16(sa[nt2 * 2 + 1], qh[j], b1);
            }
        }

        // ---- online softmax: max + rescale (sum comes from the l-tile mma) ----
        float bm0 = -1e30f, bm1 = -1e30f;
        #pragma unroll
        for (int nt = 0; nt < 8; nt++) {
            bm0 = fmaxf(bm0, fmaxf(sa[nt][0], sa[nt][1]));
            bm1 = fmaxf(bm1, fmaxf(sa[nt][2], sa[nt][3]));
        }
        bm0 = fmaxf(bm0, __shfl_xor_sync(0xffffffffu, bm0, 1));
        bm0 = fmaxf(bm0, __shfl_xor_sync(0xffffffffu, bm0, 2));
        bm1 = fmaxf(bm1, __shfl_xor_sync(0xffffffffu, bm1, 1));
        bm1 = fmaxf(bm1, __shfl_xor_sync(0xffffffffu, bm1, 2));

        const float mn0 = fmaxf(mr0, bm0), mn1 = fmaxf(mr1, bm1);
        const float sf0 = __expf(mr0 - mn0), sf1 = __expf(mr1 - mn1);
        mr0 = mn0; mr1 = mn1;

        #pragma unroll
        for (int nt = 0; nt < 8; nt++) {
            Oa[nt][0] *= sf0; Oa[nt][1] *= sf0;
            Oa[nt][2] *= sf1; Oa[nt][3] *= sf1;
        }
        lacc[0] *= sf0; lacc[1] *= sf0;
        lacc[2] *= sf1; lacc[3] *= sf1;

        // ---- exp + pack P fragments (unmasked; mask lives in V) ----
        uint32_t pfra[4][4];
        #pragma unroll
        for (int kt2 = 0; kt2 < 4; kt2++) {
            const int n0t = 2 * kt2, n1t = 2 * kt2 + 1;
            __half2 a0 = __floats2half2_rn(__expf(sa[n0t][0] - mn0), __expf(sa[n0t][1] - mn0));
            __half2 a1 = __floats2half2_rn(__expf(sa[n0t][2] - mn1), __expf(sa[n0t][3] - mn1));
            __half2 a2 = __floats2half2_rn(__expf(sa[n1t][0] - mn0), __expf(sa[n1t][1] - mn0));
            __half2 a3 = __floats2half2_rn(__expf(sa[n1t][2] - mn1), __expf(sa[n1t][3] - mn1));
            pfra[kt2][0] = *(uint32_t*)&a0;
            pfra[kt2][1] = *(uint32_t*)&a1;
            pfra[kt2][2] = *(uint32_t*)&a2;
            pfra[kt2][3] = *(uint32_t*)&a3;
        }

        // ---- O += P @ V' (V pre-masked);  l += P @ 1 ----
        #pragma unroll
        for (int nt2 = 0; nt2 < 4; nt2++) {
            #pragma unroll
            for (int kt2 = 0; kt2 < 4; kt2++) {
                uint32_t r0, r1, r2, r3;
                uint32_t addr = vsv + (uint32_t)(((nt2 * 16 + ((lane >> 4) << 3) + (lane & 7)) * VSP
                                                 + kt2 * 16 + ((lane >> 3) & 1) * 8) << 1);
                LDMX4(r0, r1, r2, r3, addr);
                uint32_t b0[2] = {r0, r1}, b1[2] = {r2, r3};
                mma_f16(Oa[nt2 * 2],     pfra[kt2], b0);
                mma_f16(Oa[nt2 * 2 + 1], pfra[kt2], b1);
            }
        }
        #pragma unroll
        for (int kt2 = 0; kt2 < 4; kt2++)
            mma_f16(lacc, pfra[kt2], ones2);

        CP_WAIT(0);
        __syncthreads();
    }

    // every lane's lacc[0] = l(row g), lacc[2] = l(row g+8)  (B all-ones)
    const float inv0 = 1.0f / lacc[0], inv1 = 1.0f / lacc[2];
    const int r0 = i0 + warp * 16 + g;
    __half* ob  = g_att16 + ((size_t)b * NSEQ + r0) * DIM + h * 64;
    __half* ob8 = ob + (size_t)8 * DIM;
    #pragma unroll
    for (int nt = 0; nt < 8; nt++) {
        int col = nt * 8 + 2 * t;
        __half2 p0 = __floats2half2_rn(Oa[nt][0] * inv0, Oa[nt][1] * inv0);
        __half2 p1 = __floats2half2_rn(Oa[nt][2] * inv1, Oa[nt][3] * inv1);
        *(__half2*)&ob[col]  = p0;
        *(__half2*)&ob8[col] = p1;
    }
}

// ---------------- converters ---------------------------------------------------
__global__ void cast_f16(const float* __restrict__ in, __half* __restrict__ out,
                         size_t total4)
{
    size_t idx = (size_t)blockIdx.x * 256 + threadIdx.x;
    if (idx >= total4) return;
    float4 v = *(const float4*)(in + idx * 4);
    __half2 a = __floats2half2_rn(v.x, v.y);
    __half2 b = __floats2half2_rn(v.z, v.w);
    *(__half2*)(out + idx * 4)     = a;
    *(__half2*)(out + idx * 4 + 2) = b;
}

__global__ __launch_bounds__(256) void splitB_single2(const float* __restrict__ W0,
                                                      const float* __restrict__ W1,
                                                      __half* __restrict__ O0,
                                                      __half* __restrict__ O1,
                                                      int Kd, int Nd)
{
    __shared__ float ts[32][33];
    const float* W = blockIdx.z ? W1 : W0;
    __half* out = blockIdx.z ? O1 : O0;
    int k0 = blockIdx.x * 32, n0 = blockIdx.y * 32;
    int tx = threadIdx.x & 31, ty = threadIdx.x >> 5;
    for (int r = ty; r < 32; r += 8) ts[r][tx] = W[(size_t)(k0 + r) * Nd + n0 + tx];
    __syncthreads();
    for (int r = ty; r < 32; r += 8)
        out[(size_t)(n0 + r) * Kd + k0 + tx] = __float2half_rn(ts[tx][r]);
}

// ---------------- launch ------------------------------------------------------
extern "C" void kernel_launch(void* const* d_in, const int* in_sizes, int n_in,
                              void* d_out, int out_size)
{
    const float* x    = (const float*)d_in[0];
    const int*   mask = (const int*)d_in[1];
    const float* Wqkv = (const float*)d_in[2];
    const float* Wout = (const float*)d_in[3];
    const float* bout = (const float*)d_in[4];
    float*       out  = (float*)d_out;

    __half *xs, *att16, *w1s, *w2s, *wQ, *vt;
    cudaGetSymbolAddress((void**)&xs,    g_xs);
    cudaGetSymbolAddress((void**)&att16, g_att16);
    cudaGetSymbolAddress((void**)&w1s,   g_w1s);
    cudaGetSymbolAddress((void**)&w2s,   g_w2s);
    cudaGetSymbolAddress((void**)&wQ,    g_wQ);
    cudaGetSymbolAddress((void**)&vt,    g_vt);

    const int GEMM_SMEM = GSTG * 256 * GP * 2;   // 61440
    cudaFuncSetAttribute(mma_gemm<0>, cudaFuncAttributeMaxDynamicSharedMemorySize, GEMM_SMEM);
    cudaFuncSetAttribute(mma_gemm<1>, cudaFuncAttributeMaxDynamicSharedMemorySize, GEMM_SMEM);
    cudaFuncSetAttribute(flash_attn, cudaFuncAttributeMaxDynamicSharedMemorySize, SM_TOT);

    cast_f16<<<((BATCH*NSEQ*DIM/4) + 255) / 256, 256>>>(x, xs, (size_t)BATCH*NSEQ*DIM/4);
    splitB_single2<<<dim3(DIM/32, DIM/32, 2), 256>>>(Wqkv, Wout, w1s, w2s, DIM, DIM);

    // stage 1: w = x @ Wqkv (f16) with fused epilogue -> scaled wQ + masked vt
    mma_gemm<1><<<dim3(DIM/128, (BATCH*NSEQ)/128), 256, GEMM_SMEM>>>(
        (const uint16_t*)xs, DIM, (const uint16_t*)w1s, DIM,
        nullptr, 0, DIM, nullptr, wQ, vt, mask);

    // stage 2+3: fused flash attention -> single-f16 atts
    flash_attn<<<dim3(NSEQ/64, BH), 128, SM_TOT>>>();

    // stage 4: out = atts @ Wout + bout (f16, K=1024)
    mma_gemm<0><<<dim3(DIM/128, (BATCH*NSEQ)/128), 256, GEMM_SMEM>>>(
        (const uint16_t*)att16, DIM, (const uint16_t*)w2s, DIM,
        out, DIM, DIM, bout, nullptr, nullptr, nullptr);
}

// round 14
// speedup vs baseline: 7.5701x; 1.0289x over previous
#include <cuda_runtime.h>
#include <cuda_bf16.h>
#include <cuda_fp16.h>
#include <cstdint>

#define HEADS 16
#define DHEAD 64
#define BATCH 2
#define NSEQ  2048
#define DIM   1024
#define BH    (BATCH*HEADS)

// ---------------- scratch (__device__ globals; allocation-free) -------------
__device__ __align__(256) __half g_xs   [(size_t)BATCH*NSEQ*DIM];    // x f16
__device__ __align__(256) __half g_att16[(size_t)BATCH*NSEQ*DIM];    // atts f16
__device__ __align__(256) __half g_w1s  [(size_t)DIM*DIM];           // Wqkv^T f16
__device__ __align__(256) __half g_w2s  [(size_t)DIM*DIM];           // Wout^T f16
__device__ __align__(256) __half g_wQ   [(size_t)BH*NSEQ*64];        // c*w per-head f16 (c^2=0.125*log2e)
__device__ __align__(256) __half g_vt   [(size_t)BH*DHEAD*NSEQ];     // V^T f16, mask-zeroed rows

// ---------------- PTX helpers -------------------------------------------------
__device__ __forceinline__ void mma_f16(float* d, const uint32_t* a, const uint32_t* b) {
    asm volatile(
        "mma.sync.aligned.m16n8k16.row.col.f32.f16.f16.f32 "
        "{%0,%1,%2,%3}, {%4,%5,%6,%7}, {%8,%9}, {%0,%1,%2,%3};"
        : "+f"(d[0]), "+f"(d[1]), "+f"(d[2]), "+f"(d[3])
        : "r"(a[0]), "r"(a[1]), "r"(a[2]), "r"(a[3]), "r"(b[0]), "r"(b[1]));
}
__device__ __forceinline__ uint32_t cvta_s(const void* p) {
    return (uint32_t)__cvta_generic_to_shared(p);
}
#define CP_ASYNC16(dst, src) \
    asm volatile("cp.async.cg.shared.global [%0], [%1], 16;" :: "r"(dst), "l"(src))
#define CP_COMMIT() asm volatile("cp.async.commit_group;")
#define CP_WAIT(n)  asm volatile("cp.async.wait_group %0;" :: "n"(n))
#define LDMX4(r0, r1, r2, r3, addr) \
    asm volatile("ldmatrix.sync.aligned.m8n8.x4.shared.b16 {%0,%1,%2,%3}, [%4];" \
        : "=r"(r0), "=r"(r1), "=r"(r2), "=r"(r3) : "r"(addr))

// ---------------------------------------------------------------------------
// HMMA GEMM (f16), cp.async 3-stage pipeline + ldmatrix.
// EPI=0: C fp32 (+bias).
// EPI=1: fused epilogue -> wQ = f16(c*v) with c=sqrt(0.125*log2e),
//        vt = f16(v)*(1-mask[row]).
// ---------------------------------------------------------------------------
#define GP   40
#define GSTG 3

template<int EPI>
__global__ __launch_bounds__(256, 2) void mma_gemm(
    const uint16_t* __restrict__ A, int lda,
    const uint16_t* __restrict__ B, int ldb,
    float* __restrict__ C, int ldc, int K, const float* __restrict__ bias,
    __half* __restrict__ wq, __half* __restrict__ vt,
    const int* __restrict__ maskp)
{
    extern __shared__ __align__(16) uint16_t gsm[];
    const int tid = threadIdx.x, lane = tid & 31, warp = tid >> 5;
    const int g = lane >> 2, t = lane & 3;
    const int wm0 = (warp >> 2) * 64, wn0 = (warp & 3) * 32;
    const int m0 = blockIdx.y * 128, n0 = blockIdx.x * 128;

    const uint16_t* Ab = A + (size_t)m0 * lda;
    const uint16_t* Bb = B + (size_t)n0 * ldb;
    const uint32_t smb = cvta_s(gsm);

    float acc[4][4][4] = {};
    const int NC = K >> 5;

    auto issue = [&](int c) {
        const uint32_t dst = smb + (uint32_t)(c % GSTG) * (256 * GP * 2);
        const uint16_t* ag = Ab + c * 32;
        const uint16_t* bg = Bb + c * 32;
        #pragma unroll
        for (int i = 0; i < 2; i++) {
            int idx = tid + i * 256;
            int r = idx >> 2, q = (idx & 3) * 8;
            CP_ASYNC16(dst + (uint32_t)(r * GP + q) * 2, ag + (size_t)r * lda + q);
        }
        #pragma unroll
        for (int i = 0; i < 2; i++) {
            int idx = tid + i * 256;
            int r = idx >> 2, q = (idx & 3) * 8;
            CP_ASYNC16(dst + (uint32_t)((128 + r) * GP + q) * 2, bg + (size_t)r * ldb + q);
        }
        CP_COMMIT();
    };

    #pragma unroll
    for (int s = 0; s < GSTG - 1; s++) issue(s);

    for (int c = 0; c < NC; c++) {
        CP_WAIT(GSTG - 2);
        __syncthreads();
        if (c + GSTG - 1 < NC) issue(c + GSTG - 1);
        else                   CP_COMMIT();

        const uint32_t asv = smb + (uint32_t)(c % GSTG) * (256 * GP * 2);
        const uint32_t bsv = asv + 128 * GP * 2;

        #pragma unroll
        for (int ks = 0; ks < 2; ks++) {
            const int kb = ks * 16;
            uint32_t bf[4][2];
            #pragma unroll
            for (int ni2 = 0; ni2 < 2; ni2++) {
                uint32_t r0, r1, r2, r3;
                uint32_t addr = bsv + (uint32_t)(((wn0 + ni2 * 16 + ((lane >> 4) << 3) + (lane & 7)) * GP
                                                 + kb + ((lane >> 3) & 1) * 8) << 1);
                LDMX4(r0, r1, r2, r3, addr);
                bf[ni2 * 2][0] = r0; bf[ni2 * 2][1] = r1;
                bf[ni2 * 2 + 1][0] = r2; bf[ni2 * 2 + 1][1] = r3;
            }
            #pragma unroll
            for (int mi = 0; mi < 4; mi++) {
                uint32_t af[4];
                uint32_t addr = asv + (uint32_t)(((wm0 + mi * 16 + (lane & 15)) * GP
                                                 + kb + (lane >> 4) * 8) << 1);
                LDMX4(af[0], af[1], af[2], af[3], addr);
                #pragma unroll
                for (int ni = 0; ni < 4; ni++) mma_f16(acc[mi][ni], af, bf[ni]);
            }
        }
    }

    if (EPI == 0) {
        float* Cb = C + (size_t)m0 * ldc + n0;
        #pragma unroll
        for (int mi = 0; mi < 4; mi++) {
            #pragma unroll
            for (int ni = 0; ni < 4; ni++) {
                int col = wn0 + ni * 8 + 2 * t;
                float bx = 0.0f, by = 0.0f;
                if (bias) { bx = bias[n0 + col]; by = bias[n0 + col + 1]; }
                int r1 = wm0 + mi * 16 + g;
                *(float2*)(Cb + (size_t)r1 * ldc + col) =
                    make_float2(acc[mi][ni][0] + bx, acc[mi][ni][1] + by);
                *(float2*)(Cb + (size_t)(r1 + 8) * ldc + col) =
                    make_float2(acc[mi][ni][2] + bx, acc[mi][ni][3] + by);
            }
        }
    } else {
        const float QS = 0.42466090014400953f;   // sqrt(0.125 * log2(e))
        #pragma unroll
        for (int mi = 0; mi < 4; mi++) {
            #pragma unroll
            for (int half_ = 0; half_ < 2; half_++) {
                const int gr = m0 + wm0 + mi * 16 + g + half_ * 8;
                const int b = gr >> 11, nn = gr & 2047;
                const float keep = 1.0f - (float)maskp[(size_t)b * NSEQ + nn];
                #pragma unroll
                for (int ni = 0; ni < 4; ni++) {
                    const int gc = n0 + wn0 + ni * 8 + 2 * t;
                    const int h = gc >> 6, d = gc & 63;
                    const float v0 = acc[mi][ni][half_ * 2];
                    const float v1 = acc[mi][ni][half_ * 2 + 1];
                    __half2 qp = __floats2half2_rn(v0 * QS, v1 * QS);
                    *(__half2*)&wq[(((size_t)(b * 16 + h)) * NSEQ + nn) * 64 + d] = qp;
                    const __half h0 = __float2half_rn(v0 * keep);
                    const __half h1 = __float2half_rn(v1 * keep);
                    size_t vb = ((size_t)(b * 16 + h) * 64 + d) * NSEQ + nn;
                    vt[vb]        = h0;
                    vt[vb + NSEQ] = h1;
                }
            }
        }
    }
}

// ---------------------------------------------------------------------------
// Fused flash attention. Scores live in the log2 domain (Q/K pre-scaled by
// sqrt(0.125*log2e)) -> bare exp2f. V pre-masked; l via all-ones mma tile.
// Conditional O/l rescale (exact skip when max unchanged).
// 128 threads / 4 warps / 64 q-rows per CTA; 4 CTAs/SM.
// ---------------------------------------------------------------------------
#define KB    64
#define NIT   (NSEQ / KB)
#define KSP   72
#define VSP   72
#define SM_K0 0
#define SM_K1 9216
#define SM_V0 18432
#define SM_V1 27648
#define SM_TOT 36864

__global__ __launch_bounds__(128, 4) void flash_attn()
{
    extern __shared__ char sm[];
    const int tid = threadIdx.x, lane = tid & 31, warp = tid >> 5;
    const int g = lane >> 2, t = lane & 3;
    const int i0 = blockIdx.x * 64;
    const int bh = blockIdx.y;
    const int b = bh >> 4, h = bh & 15;

    const uint16_t* wQ = (const uint16_t*)g_wQ + (size_t)bh * NSEQ * 64;
    const uint16_t* vt = (const uint16_t*)g_vt + (size_t)bh * DHEAD * NSEQ;
    const uint32_t smb = cvta_s(sm);

    auto issue = [&](int it2, int buf) {
        const int j0 = it2 * KB;
        const uint32_t kd = smb + (buf ? SM_K1 : SM_K0);
        const uint32_t vd = smb + (buf ? SM_V1 : SM_V0);
        #pragma unroll
        for (int i = 0; i < 4; i++) {
            int idx = tid + i * 128;
            int r = idx >> 3, q = (idx & 7) * 8;
            CP_ASYNC16(kd + (uint32_t)(r * KSP + q) * 2, wQ + (size_t)(j0 + r) * 64 + q);
        }
        #pragma unroll
        for (int i = 0; i < 4; i++) {
            int idx = tid + i * 128;
            int r = idx >> 3, q = (idx & 7) * 8;
            CP_ASYNC16(vd + (uint32_t)(r * VSP + q) * 2, vt + (size_t)r * NSEQ + j0 + q);
        }
        CP_COMMIT();
    };

    // Q fragments (rows i0+warp*16+{g,g+8}): 4 k16 tiles, pre-scaled f16
    uint32_t qh[4][4];
    {
        const uint16_t* q0 = wQ + (size_t)(i0 + warp * 16 + g) * 64 + 2 * t;
        #pragma unroll
        for (int j = 0; j < 4; j++) {
            qh[j][0] = *(const uint32_t*)(q0 + j * 16);
            qh[j][1] = *(const uint32_t*)(q0 + j * 16 + 8 * 64);
            qh[j][2] = *(const uint32_t*)(q0 + j * 16 + 8);
            qh[j][3] = *(const uint32_t*)(q0 + j * 16 + 8 * 64 + 8);
        }
    }

    float Oa[8][4] = {};
    float lacc[4] = {};
    float mr0 = -1e30f, mr1 = -1e30f;
    const uint32_t ones2[2] = {0x3C003C00u, 0x3C003C00u};

    issue(0, 0);
    CP_WAIT(0);
    __syncthreads();

    for (int it = 0; it < NIT; it++) {
        const int cur = it & 1;
        const uint32_t ksv = smb + (cur ? SM_K1 : SM_K0);
        const uint32_t vsv = smb + (cur ? SM_V1 : SM_V0);

        if (it + 1 < NIT) issue(it + 1, cur ^ 1);
        else              CP_COMMIT();

        // ---- S tile (log2-domain scores) ----
        float sa[8][4] = {};
        #pragma unroll
        for (int j = 0; j < 4; j++) {
            #pragma unroll
            for (int nt2 = 0; nt2 < 4; nt2++) {
                uint32_t r0, r1, r2, r3;
                uint32_t addr = ksv + (uint32_t)(((nt2 * 16 + ((lane >> 4) << 3) + (lane & 7)) * KSP
                                                 + j * 16 + ((lane >> 3) & 1) * 8) << 1);
                LDMX4(r0, r1, r2, r3, addr);
                uint32_t b0[2] = {r0, r1}, b1[2] = {r2, r3};
                mma_f16(sa[nt2 * 2],     qh[j], b0);
                mma_f16(sa[nt2 * 2 + 1], qh[j], b1);
            }
        }

        // ---- online softmax bookkeeping ----
        float bm0 = -1e30f, bm1 = -1e30f;
        #pragma unroll
        for (int nt = 0; nt < 8; nt++) {
            bm0 = fmaxf(bm0, fmaxf(sa[nt][0], sa[nt][1]));
            bm1 = fmaxf(bm1, fmaxf(sa[nt][2], sa[nt][3]));
        }
        bm0 = fmaxf(bm0, __shfl_xor_sync(0xffffffffu, bm0, 1));
        bm0 = fmaxf(bm0, __shfl_xor_sync(0xffffffffu, bm0, 2));
        bm1 = fmaxf(bm1, __shfl_xor_sync(0xffffffffu, bm1, 1));
        bm1 = fmaxf(bm1, __shfl_xor_sync(0xffffffffu, bm1, 2));

        const bool upd = __any_sync(0xffffffffu, (bm0 > mr0) || (bm1 > mr1));
        const float mn0 = fmaxf(mr0, bm0), mn1 = fmaxf(mr1, bm1);
        if (upd) {
            const float sf0 = exp2f(mr0 - mn0), sf1 = exp2f(mr1 - mn1);
            #pragma unroll
            for (int nt = 0; nt < 8; nt++) {
                Oa[nt][0] *= sf0; Oa[nt][1] *= sf0;
                Oa[nt][2] *= sf1; Oa[nt][3] *= sf1;
            }
            lacc[0] *= sf0; lacc[1] *= sf0;
            lacc[2] *= sf1; lacc[3] *= sf1;
            mr0 = mn0; mr1 = mn1;
        }

        // ---- exp2 + pack P fragments (mask lives in V) ----
        uint32_t pfra[4][4];
        #pragma unroll
        for (int kt2 = 0; kt2 < 4; kt2++) {
            const int n0t = 2 * kt2, n1t = 2 * kt2 + 1;
            __half2 a0 = __floats2half2_rn(exp2f(sa[n0t][0] - mr0), exp2f(sa[n0t][1] - mr0));
            __half2 a1 = __floats2half2_rn(exp2f(sa[n0t][2] - mr1), exp2f(sa[n0t][3] - mr1));
            __half2 a2 = __floats2half2_rn(exp2f(sa[n1t][0] - mr0), exp2f(sa[n1t][1] - mr0));
            __half2 a3 = __floats2half2_rn(exp2f(sa[n1t][2] - mr1), exp2f(sa[n1t][3] - mr1));
            pfra[kt2][0] = *(uint32_t*)&a0;
            pfra[kt2][1] = *(uint32_t*)&a1;
            pfra[kt2][2] = *(uint32_t*)&a2;
            pfra[kt2][3] = *(uint32_t*)&a3;
        }

        // ---- O += P @ V' (pre-masked);  l += P @ 1 ----
        #pragma unroll
        for (int nt2 = 0; nt2 < 4; nt2++) {
            #pragma unroll
            for (int kt2 = 0; kt2 < 4; kt2++) {
                uint32_t r0, r1, r2, r3;
                uint32_t addr = vsv + (uint32_t)(((nt2 * 16 + ((lane >> 4) << 3) + (lane & 7)) * VSP
                                                 + kt2 * 16 + ((lane >> 3) & 1) * 8) << 1);
                LDMX4(r0, r1, r2, r3, addr);
                uint32_t b0[2] = {r0, r1}, b1[2] = {r2, r3};
                mma_f16(Oa[nt2 * 2],     pfra[kt2], b0);
                mma_f16(Oa[nt2 * 2 + 1], pfra[kt2], b1);
            }
        }
        #pragma unroll
        for (int kt2 = 0; kt2 < 4; kt2++)
            mma_f16(lacc, pfra[kt2], ones2);

        CP_WAIT(0);
        __syncthreads();
    }

    const float inv0 = 1.0f / lacc[0], inv1 = 1.0f / lacc[2];
    const int r0 = i0 + warp * 16 + g;
    __half* ob  = g_att16 + ((size_t)b * NSEQ + r0) * DIM + h * 64;
    __half* ob8 = ob + (size_t)8 * DIM;
    #pragma unroll
    for (int nt = 0; nt < 8; nt++) {
        int col = nt * 8 + 2 * t;
        __half2 p0 = __floats2half2_rn(Oa[nt][0] * inv0, Oa[nt][1] * inv0);
        __half2 p1 = __floats2half2_rn(Oa[nt][2] * inv1, Oa[nt][3] * inv1);
        *(__half2*)&ob[col]  = p0;
        *(__half2*)&ob8[col] = p1;
    }
}

// ---------------- converters ---------------------------------------------------
__global__ void cast_f16(const float* __restrict__ in, __half* __restrict__ out,
                         size_t total4)
{
    size_t idx = (size_t)blockIdx.x * 256 + threadIdx.x;
    if (idx >= total4) return;
    float4 v = *(const float4*)(in + idx * 4);
    __half2 a = __floats2half2_rn(v.x, v.y);
    __half2 b = __floats2half2_rn(v.z, v.w);
    *(__half2*)(out + idx * 4)     = a;
    *(__half2*)(out + idx * 4 + 2) = b;
}

__global__ __launch_bounds__(256) void splitB_single2(const float* __restrict__ W0,
                                                      const float* __restrict__ W1,
                                                      __half* __restrict__ O0,
                                                      __half* __restrict__ O1,
                                                      int Kd, int Nd)
{
    __shared__ float ts[32][33];
    const float* W = blockIdx.z ? W1 : W0;
    __half* out = blockIdx.z ? O1 : O0;
    int k0 = blockIdx.x * 32, n0 = blockIdx.y * 32;
    int tx = threadIdx.x & 31, ty = threadIdx.x >> 5;
    for (int r = ty; r < 32; r += 8) ts[r][tx] = W[(size_t)(k0 + r) * Nd + n0 + tx];
    __syncthreads();
    for (int r = ty; r < 32; r += 8)
        out[(size_t)(n0 + r) * Kd + k0 + tx] = __float2half_rn(ts[tx][r]);
}

// ---------------- launch ------------------------------------------------------
extern "C" void kernel_launch(void* const* d_in, const int* in_sizes, int n_in,
                              void* d_out, int out_size)
{
    const float* x    = (const float*)d_in[0];
    const int*   mask = (const int*)d_in[1];
    const float* Wqkv = (const float*)d_in[2];
    const float* Wout = (const float*)d_in[3];
    const float* bout = (const float*)d_in[4];
    float*       out  = (float*)d_out;

    __half *xs, *att16, *w1s, *w2s, *wQ, *vt;
    cudaGetSymbolAddress((void**)&xs,    g_xs);
    cudaGetSymbolAddress((void**)&att16, g_att16);
    cudaGetSymbolAddress((void**)&w1s,   g_w1s);
    cudaGetSymbolAddress((void**)&w2s,   g_w2s);
    cudaGetSymbolAddress((void**)&wQ,    g_wQ);
    cudaGetSymbolAddress((void**)&vt,    g_vt);

    const int GEMM_SMEM = GSTG * 256 * GP * 2;   // 61440
    cudaFuncSetAttribute(mma_gemm<0>, cudaFuncAttributeMaxDynamicSharedMemorySize, GEMM_SMEM);
    cudaFuncSetAttribute(mma_gemm<1>, cudaFuncAttributeMaxDynamicSharedMemorySize, GEMM_SMEM);
    cudaFuncSetAttribute(flash_attn, cudaFuncAttributeMaxDynamicSharedMemorySize, SM_TOT);

    cast_f16<<<((BATCH*NSEQ*DIM/4) + 255) / 256, 256>>>(x, xs, (size_t)BATCH*NSEQ*DIM/4);
    splitB_single2<<<dim3(DIM/32, DIM/32, 2), 256>>>(Wqkv, Wout, w1s, w2s, DIM, DIM);

    // stage 1: w = x @ Wqkv (f16) with fused epilogue -> log2-scaled wQ + masked vt
    mma_gemm<1><<<dim3(DIM/128, (BATCH*NSEQ)/128), 256, GEMM_SMEM>>>(
        (const uint16_t*)xs, DIM, (const uint16_t*)w1s, DIM,
        nullptr, 0, DIM, nullptr, wQ, vt, mask);

    // stage 2+3: fused flash attention -> single-f16 atts
    flash_attn<<<dim3(NSEQ/64, BH), 128, SM_TOT>>>();

    // stage 4: out = atts @ Wout + bout (f16, K=1024)
    mma_gemm<0><<<dim3(DIM/128, (BATCH*NSEQ)/128), 256, GEMM_SMEM>>>(
        (const uint16_t*)att16, DIM, (const uint16_t*)w2s, DIM,
        out, DIM, DIM, bout, nullptr, nullptr, nullptr);
}

// round 15
// speedup vs baseline: 7.7685x; 1.0262x over previous
#include <cuda_runtime.h>
#include <cuda_bf16.h>
#include <cuda_fp16.h>
#include <cstdint>

#define HEADS 16
#define DHEAD 64
#define BATCH 2
#define NSEQ  2048
#define DIM   1024
#define BH    (BATCH*HEADS)

// ---------------- scratch (__device__ globals; allocation-free) -------------
__device__ __align__(256) __half g_xs   [(size_t)BATCH*NSEQ*DIM];    // x f16
__device__ __align__(256) __half g_att16[(size_t)BATCH*NSEQ*DIM];    // atts f16
__device__ __align__(256) __half g_w1s  [(size_t)DIM*DIM];           // Wqkv^T f16
__device__ __align__(256) __half g_w2s  [(size_t)DIM*DIM];           // Wout^T f16
__device__ __align__(256) __half g_wQ   [(size_t)BH*NSEQ*64];        // c*w per-head f16 (c^2=0.125*log2e)
__device__ __align__(256) __half g_vt   [(size_t)BH*DHEAD*NSEQ];     // V^T f16, mask-zeroed rows

// ---------------- PTX helpers -------------------------------------------------
__device__ __forceinline__ void mma_f16(float* d, const uint32_t* a, const uint32_t* b) {
    asm volatile(
        "mma.sync.aligned.m16n8k16.row.col.f32.f16.f16.f32 "
        "{%0,%1,%2,%3}, {%4,%5,%6,%7}, {%8,%9}, {%0,%1,%2,%3};"
        : "+f"(d[0]), "+f"(d[1]), "+f"(d[2]), "+f"(d[3])
        : "r"(a[0]), "r"(a[1]), "r"(a[2]), "r"(a[3]), "r"(b[0]), "r"(b[1]));
}
__device__ __forceinline__ uint32_t cvta_s(const void* p) {
    return (uint32_t)__cvta_generic_to_shared(p);
}
__device__ __forceinline__ uint32_t h2exp2_(float ulo, float uhi) {
    __half2 u = __floats2half2_rn(ulo, uhi);
    uint32_t r;
    asm("ex2.approx.f16x2 %0, %1;" : "=r"(r) : "r"(*(uint32_t*)&u));
    return r;
}
#define CP_ASYNC16(dst, src) \
    asm volatile("cp.async.cg.shared.global [%0], [%1], 16;" :: "r"(dst), "l"(src))
#define CP_COMMIT() asm volatile("cp.async.commit_group;")
#define CP_WAIT(n)  asm volatile("cp.async.wait_group %0;" :: "n"(n))
#define LDMX4(r0, r1, r2, r3, addr) \
    asm volatile("ldmatrix.sync.aligned.m8n8.x4.shared.b16 {%0,%1,%2,%3}, [%4];" \
        : "=r"(r0), "=r"(r1), "=r"(r2), "=r"(r3) : "r"(addr))

// ---------------------------------------------------------------------------
// HMMA GEMM (f16), cp.async 3-stage pipeline + ldmatrix.
// EPI=0: C fp32 (+bias).
// EPI=1: fused epilogue -> wQ = f16(c*v) with c=sqrt(0.125*log2e),
//        vt = f16(v)*(1-mask[row]).
// ---------------------------------------------------------------------------
#define GP   40
#define GSTG 3

template<int EPI>
__global__ __launch_bounds__(256, 2) void mma_gemm(
    const uint16_t* __restrict__ A, int lda,
    const uint16_t* __restrict__ B, int ldb,
    float* __restrict__ C, int ldc, int K, const float* __restrict__ bias,
    __half* __restrict__ wq, __half* __restrict__ vt,
    const int* __restrict__ maskp)
{
    extern __shared__ __align__(16) uint16_t gsm[];
    const int tid = threadIdx.x, lane = tid & 31, warp = tid >> 5;
    const int g = lane >> 2, t = lane & 3;
    const int wm0 = (warp >> 2) * 64, wn0 = (warp & 3) * 32;
    const int m0 = blockIdx.y * 128, n0 = blockIdx.x * 128;

    const uint16_t* Ab = A + (size_t)m0 * lda;
    const uint16_t* Bb = B + (size_t)n0 * ldb;
    const uint32_t smb = cvta_s(gsm);

    float acc[4][4][4] = {};
    const int NC = K >> 5;

    auto issue = [&](int c) {
        const uint32_t dst = smb + (uint32_t)(c % GSTG) * (256 * GP * 2);
        const uint16_t* ag = Ab + c * 32;
        const uint16_t* bg = Bb + c * 32;
        #pragma unroll
        for (int i = 0; i < 2; i++) {
            int idx = tid + i * 256;
            int r = idx >> 2, q = (idx & 3) * 8;
            CP_ASYNC16(dst + (uint32_t)(r * GP + q) * 2, ag + (size_t)r * lda + q);
        }
        #pragma unroll
        for (int i = 0; i < 2; i++) {
            int idx = tid + i * 256;
            int r = idx >> 2, q = (idx & 3) * 8;
            CP_ASYNC16(dst + (uint32_t)((128 + r) * GP + q) * 2, bg + (size_t)r * ldb + q);
        }
        CP_COMMIT();
    };

    #pragma unroll
    for (int s = 0; s < GSTG - 1; s++) issue(s);

    for (int c = 0; c < NC; c++) {
        CP_WAIT(GSTG - 2);
        __syncthreads();
        if (c + GSTG - 1 < NC) issue(c + GSTG - 1);
        else                   CP_COMMIT();

        const uint32_t asv = smb + (uint32_t)(c % GSTG) * (256 * GP * 2);
        const uint32_t bsv = asv + 128 * GP * 2;

        #pragma unroll
        for (int ks = 0; ks < 2; ks++) {
            const int kb = ks * 16;
            uint32_t bf[4][2];
            #pragma unroll
            for (int ni2 = 0; ni2 < 2; ni2++) {
                uint32_t r0, r1, r2, r3;
                uint32_t addr = bsv + (uint32_t)(((wn0 + ni2 * 16 + ((lane >> 4) << 3) + (lane & 7)) * GP
                                                 + kb + ((lane >> 3) & 1) * 8) << 1);
                LDMX4(r0, r1, r2, r3, addr);
                bf[ni2 * 2][0] = r0; bf[ni2 * 2][1] = r1;
                bf[ni2 * 2 + 1][0] = r2; bf[ni2 * 2 + 1][1] = r3;
            }
            #pragma unroll
            for (int mi = 0; mi < 4; mi++) {
                uint32_t af[4];
                uint32_t addr = asv + (uint32_t)(((wm0 + mi * 16 + (lane & 15)) * GP
                                                 + kb + (lane >> 4) * 8) << 1);
                LDMX4(af[0], af[1], af[2], af[3], addr);
                #pragma unroll
                for (int ni = 0; ni < 4; ni++) mma_f16(acc[mi][ni], af, bf[ni]);
            }
        }
    }

    if (EPI == 0) {
        float* Cb = C + (size_t)m0 * ldc + n0;
        #pragma unroll
        for (int mi = 0; mi < 4; mi++) {
            #pragma unroll
            for (int ni = 0; ni < 4; ni++) {
                int col = wn0 + ni * 8 + 2 * t;
                float bx = 0.0f, by = 0.0f;
                if (bias) { bx = bias[n0 + col]; by = bias[n0 + col + 1]; }
                int r1 = wm0 + mi * 16 + g;
                *(float2*)(Cb + (size_t)r1 * ldc + col) =
                    make_float2(acc[mi][ni][0] + bx, acc[mi][ni][1] + by);
                *(float2*)(Cb + (size_t)(r1 + 8) * ldc + col) =
                    make_float2(acc[mi][ni][2] + bx, acc[mi][ni][3] + by);
            }
        }
    } else {
        const float QS = 0.42466090014400953f;   // sqrt(0.125 * log2(e))
        #pragma unroll
        for (int mi = 0; mi < 4; mi++) {
            #pragma unroll
            for (int half_ = 0; half_ < 2; half_++) {
                const int gr = m0 + wm0 + mi * 16 + g + half_ * 8;
                const int b = gr >> 11, nn = gr & 2047;
                const float keep = 1.0f - (float)maskp[(size_t)b * NSEQ + nn];
                #pragma unroll
                for (int ni = 0; ni < 4; ni++) {
                    const int gc = n0 + wn0 + ni * 8 + 2 * t;
                    const int h = gc >> 6, d = gc & 63;
                    const float v0 = acc[mi][ni][half_ * 2];
                    const float v1 = acc[mi][ni][half_ * 2 + 1];
                    __half2 qp = __floats2half2_rn(v0 * QS, v1 * QS);
                    *(__half2*)&wq[(((size_t)(b * 16 + h)) * NSEQ + nn) * 64 + d] = qp;
                    const __half h0 = __float2half_rn(v0 * keep);
                    const __half h1 = __float2half_rn(v1 * keep);
                    size_t vb = ((size_t)(b * 16 + h) * 64 + d) * NSEQ + nn;
                    vt[vb]        = h0;
                    vt[vb + NSEQ] = h1;
                }
            }
        }
    }
}

// ---------------------------------------------------------------------------
// Fused flash attention. Log2-domain scores; LAZY softmax base (rescale only
// when tile max exceeds base by >6 log2 units; p <= 64 fits f16, O/l in f32,
// base cancels in O/l). P via ex2.approx.f16x2. V pre-masked; l via all-ones
// mma tile. 128 threads / 4 warps / 64 q-rows per CTA; 4 CTAs/SM.
// ---------------------------------------------------------------------------
#define KB    64
#define NIT   (NSEQ / KB)
#define KSP   72
#define VSP   72
#define SM_K0 0
#define SM_K1 9216
#define SM_V0 18432
#define SM_V1 27648
#define SM_TOT 36864

__global__ __launch_bounds__(128, 4) void flash_attn()
{
    extern __shared__ char sm[];
    const int tid = threadIdx.x, lane = tid & 31, warp = tid >> 5;
    const int g = lane >> 2, t = lane & 3;
    const int i0 = blockIdx.x * 64;
    const int bh = blockIdx.y;
    const int b = bh >> 4, h = bh & 15;

    const uint16_t* wQ = (const uint16_t*)g_wQ + (size_t)bh * NSEQ * 64;
    const uint16_t* vt = (const uint16_t*)g_vt + (size_t)bh * DHEAD * NSEQ;
    const uint32_t smb = cvta_s(sm);

    auto issue = [&](int it2, int buf) {
        const int j0 = it2 * KB;
        const uint32_t kd = smb + (buf ? SM_K1 : SM_K0);
        const uint32_t vd = smb + (buf ? SM_V1 : SM_V0);
        #pragma unroll
        for (int i = 0; i < 4; i++) {
            int idx = tid + i * 128;
            int r = idx >> 3, q = (idx & 7) * 8;
            CP_ASYNC16(kd + (uint32_t)(r * KSP + q) * 2, wQ + (size_t)(j0 + r) * 64 + q);
        }
        #pragma unroll
        for (int i = 0; i < 4; i++) {
            int idx = tid + i * 128;
            int r = idx >> 3, q = (idx & 7) * 8;
            CP_ASYNC16(vd + (uint32_t)(r * VSP + q) * 2, vt + (size_t)r * NSEQ + j0 + q);
        }
        CP_COMMIT();
    };

    // Q fragments (rows i0+warp*16+{g,g+8}): 4 k16 tiles, pre-scaled f16
    uint32_t qh[4][4];
    {
        const uint16_t* q0 = wQ + (size_t)(i0 + warp * 16 + g) * 64 + 2 * t;
        #pragma unroll
        for (int j = 0; j < 4; j++) {
            qh[j][0] = *(const uint32_t*)(q0 + j * 16);
            qh[j][1] = *(const uint32_t*)(q0 + j * 16 + 8 * 64);
            qh[j][2] = *(const uint32_t*)(q0 + j * 16 + 8);
            qh[j][3] = *(const uint32_t*)(q0 + j * 16 + 8 * 64 + 8);
        }
    }

    float Oa[8][4] = {};
    float lacc[4] = {};
    float mr0 = -1e30f, mr1 = -1e30f;     // lazy bases (log2 domain)
    const uint32_t ones2[2] = {0x3C003C00u, 0x3C003C00u};

    issue(0, 0);
    CP_WAIT(0);
    __syncthreads();

    for (int it = 0; it < NIT; it++) {
        const int cur = it & 1;
        const uint32_t ksv = smb + (cur ? SM_K1 : SM_K0);
        const uint32_t vsv = smb + (cur ? SM_V1 : SM_V0);

        if (it + 1 < NIT) issue(it + 1, cur ^ 1);
        else              CP_COMMIT();

        // ---- S tile (log2-domain scores) ----
        float sa[8][4] = {};
        #pragma unroll
        for (int j = 0; j < 4; j++) {
            #pragma unroll
            for (int nt2 = 0; nt2 < 4; nt2++) {
                uint32_t r0, r1, r2, r3;
                uint32_t addr = ksv + (uint32_t)(((nt2 * 16 + ((lane >> 4) << 3) + (lane & 7)) * KSP
                                                 + j * 16 + ((lane >> 3) & 1) * 8) << 1);
                LDMX4(r0, r1, r2, r3, addr);
                uint32_t b0[2] = {r0, r1}, b1[2] = {r2, r3};
                mma_f16(sa[nt2 * 2],     qh[j], b0);
                mma_f16(sa[nt2 * 2 + 1], qh[j], b1);
            }
        }

        // ---- lazy-base bookkeeping ----
        float bm0 = -1e30f, bm1 = -1e30f;
        #pragma unroll
        for (int nt = 0; nt < 8; nt++) {
            bm0 = fmaxf(bm0, fmaxf(sa[nt][0], sa[nt][1]));
            bm1 = fmaxf(bm1, fmaxf(sa[nt][2], sa[nt][3]));
        }
        bm0 = fmaxf(bm0, __shfl_xor_sync(0xffffffffu, bm0, 1));
        bm0 = fmaxf(bm0, __shfl_xor_sync(0xffffffffu, bm0, 2));
        bm1 = fmaxf(bm1, __shfl_xor_sync(0xffffffffu, bm1, 1));
        bm1 = fmaxf(bm1, __shfl_xor_sync(0xffffffffu, bm1, 2));

        if (__any_sync(0xffffffffu, (bm0 > mr0 + 6.0f) || (bm1 > mr1 + 6.0f))) {
            const float mn0 = fmaxf(mr0, bm0), mn1 = fmaxf(mr1, bm1);
            const float sf0 = exp2f(mr0 - mn0), sf1 = exp2f(mr1 - mn1);
            #pragma unroll
            for (int nt = 0; nt < 8; nt++) {
                Oa[nt][0] *= sf0; Oa[nt][1] *= sf0;
                Oa[nt][2] *= sf1; Oa[nt][3] *= sf1;
            }
            lacc[0] *= sf0; lacc[1] *= sf0;
            lacc[2] *= sf1; lacc[3] *= sf1;
            mr0 = mn0; mr1 = mn1;
        }

        // ---- P = exp2(s - base) via packed f16x2 MUFU (mask lives in V) ----
        uint32_t pfra[4][4];
        #pragma unroll
        for (int kt2 = 0; kt2 < 4; kt2++) {
            const int n0t = 2 * kt2, n1t = 2 * kt2 + 1;
            pfra[kt2][0] = h2exp2_(sa[n0t][0] - mr0, sa[n0t][1] - mr0);
            pfra[kt2][1] = h2exp2_(sa[n0t][2] - mr1, sa[n0t][3] - mr1);
            pfra[kt2][2] = h2exp2_(sa[n1t][0] - mr0, sa[n1t][1] - mr0);
            pfra[kt2][3] = h2exp2_(sa[n1t][2] - mr1, sa[n1t][3] - mr1);
        }

        // ---- O += P @ V' (pre-masked);  l += P @ 1 ----
        #pragma unroll
        for (int nt2 = 0; nt2 < 4; nt2++) {
            #pragma unroll
            for (int kt2 = 0; kt2 < 4; kt2++) {
                uint32_t r0, r1, r2, r3;
                uint32_t addr = vsv + (uint32_t)(((nt2 * 16 + ((lane >> 4) << 3) + (lane & 7)) * VSP
                                                 + kt2 * 16 + ((lane >> 3) & 1) * 8) << 1);
                LDMX4(r0, r1, r2, r3, addr);
                uint32_t b0[2] = {r0, r1}, b1[2] = {r2, r3};
                mma_f16(Oa[nt2 * 2],     pfra[kt2], b0);
                mma_f16(Oa[nt2 * 2 + 1], pfra[kt2], b1);
            }
        }
        #pragma unroll
        for (int kt2 = 0; kt2 < 4; kt2++)
            mma_f16(lacc, pfra[kt2], ones2);

        CP_WAIT(0);
        __syncthreads();
    }

    const float inv0 = 1.0f / lacc[0], inv1 = 1.0f / lacc[2];
    const int r0 = i0 + warp * 16 + g;
    __half* ob  = g_att16 + ((size_t)b * NSEQ + r0) * DIM + h * 64;
    __half* ob8 = ob + (size_t)8 * DIM;
    #pragma unroll
    for (int nt = 0; nt < 8; nt++) {
        int col = nt * 8 + 2 * t;
        __half2 p0 = __floats2half2_rn(Oa[nt][0] * inv0, Oa[nt][1] * inv0);
        __half2 p1 = __floats2half2_rn(Oa[nt][2] * inv1, Oa[nt][3] * inv1);
        *(__half2*)&ob[col]  = p0;
        *(__half2*)&ob8[col] = p1;
    }
}

// ---------------- converters ---------------------------------------------------
__global__ void cast_f16(const float* __restrict__ in, __half* __restrict__ out,
                         size_t total4)
{
    size_t idx = (size_t)blockIdx.x * 256 + threadIdx.x;
    if (idx >= total4) return;
    float4 v = *(const float4*)(in + idx * 4);
    __half2 a = __floats2half2_rn(v.x, v.y);
    __half2 b = __floats2half2_rn(v.z, v.w);
    *(__half2*)(out + idx * 4)     = a;
    *(__half2*)(out + idx * 4 + 2) = b;
}

__global__ __launch_bounds__(256) void splitB_single2(const float* __restrict__ W0,
                                                      const float* __restrict__ W1,
                                                      __half* __restrict__ O0,
                                                      __half* __restrict__ O1,
                                                      int Kd, int Nd)
{
    __shared__ float ts[32][33];
    const float* W = blockIdx.z ? W1 : W0;
    __half* out = blockIdx.z ? O1 : O0;
    int k0 = blockIdx.x * 32, n0 = blockIdx.y * 32;
    int tx = threadIdx.x & 31, ty = threadIdx.x >> 5;
    for (int r = ty; r < 32; r += 8) ts[r][tx] = W[(size_t)(k0 + r) * Nd + n0 + tx];
    __syncthreads();
    for (int r = ty; r < 32; r += 8)
        out[(size_t)(n0 + r) * Kd + k0 + tx] = __float2half_rn(ts[tx][r]);
}

// ---------------- launch ------------------------------------------------------
extern "C" void kernel_launch(void* const* d_in, const int* in_sizes, int n_in,
                              void* d_out, int out_size)
{
    const float* x    = (const float*)d_in[0];
    const int*   mask = (const int*)d_in[1];
    const float* Wqkv = (const float*)d_in[2];
    const float* Wout = (const float*)d_in[3];
    const float* bout = (const float*)d_in[4];
    float*       out  = (float*)d_out;

    __half *xs, *att16, *w1s, *w2s, *wQ, *vt;
    cudaGetSymbolAddress((void**)&xs,    g_xs);
    cudaGetSymbolAddress((void**)&att16, g_att16);
    cudaGetSymbolAddress((void**)&w1s,   g_w1s);
    cudaGetSymbolAddress((void**)&w2s,   g_w2s);
    cudaGetSymbolAddress((void**)&wQ,    g_wQ);
    cudaGetSymbolAddress((void**)&vt,    g_vt);

    const int GEMM_SMEM = GSTG * 256 * GP * 2;   // 61440
    cudaFuncSetAttribute(mma_gemm<0>, cudaFuncAttributeMaxDynamicSharedMemorySize, GEMM_SMEM);
    cudaFuncSetAttribute(mma_gemm<1>, cudaFuncAttributeMaxDynamicSharedMemorySize, GEMM_SMEM);
    cudaFuncSetAttribute(flash_attn, cudaFuncAttributeMaxDynamicSharedMemorySize, SM_TOT);

    cast_f16<<<((BATCH*NSEQ*DIM/4) + 255) / 256, 256>>>(x, xs, (size_t)BATCH*NSEQ*DIM/4);
    splitB_single2<<<dim3(DIM/32, DIM/32, 2), 256>>>(Wqkv, Wout, w1s, w2s, DIM, DIM);

    // stage 1: w = x @ Wqkv (f16) with fused epilogue -> log2-scaled wQ + masked vt
    mma_gemm<1><<<dim3(DIM/128, (BATCH*NSEQ)/128), 256, GEMM_SMEM>>>(
        (const uint16_t*)xs, DIM, (const uint16_t*)w1s, DIM,
        nullptr, 0, DIM, nullptr, wQ, vt, mask);

    // stage 2+3: fused flash attention -> single-f16 atts
    flash_attn<<<dim3(NSEQ/64, BH), 128, SM_TOT>>>();

    // stage 4: out = atts @ Wout + bout (f16, K=1024)
    mma_gemm<0><<<dim3(DIM/128, (BATCH*NSEQ)/128), 256, GEMM_SMEM>>>(
        (const uint16_t*)att16, DIM, (const uint16_t*)w2s, DIM,
        out, DIM, DIM, bout, nullptr, nullptr, nullptr);
}

// round 16
// speedup vs baseline: 8.1179x; 1.0450x over previous
#include <cuda_runtime.h>
#include <cuda_bf16.h>
#include <cuda_fp16.h>
#include <cstdint>

#define HEADS 16
#define DHEAD 64
#define BATCH 2
#define NSEQ  2048
#define DIM   1024
#define BH    (BATCH*HEADS)

// ---------------- scratch (__device__ globals; allocation-free) -------------
__device__ __align__(256) __half g_xs   [(size_t)BATCH*NSEQ*DIM];    // x f16
__device__ __align__(256) __half g_att16[(size_t)BATCH*NSEQ*DIM];    // atts f16
__device__ __align__(256) __half g_w1s  [(size_t)DIM*DIM];           // Wqkv^T f16
__device__ __align__(256) __half g_w2s  [(size_t)DIM*DIM];           // Wout^T f16
__device__ __align__(256) __half g_wQ   [(size_t)BH*NSEQ*64];        // c*w per-head f16 (c^2=0.125*log2e)
__device__ __align__(256) __half g_vt   [(size_t)BH*DHEAD*NSEQ];     // V^T f16, mask-zeroed rows

// ---------------- PTX helpers -------------------------------------------------
__device__ __forceinline__ void mma_f16(float* d, const uint32_t* a, const uint32_t* b) {
    asm volatile(
        "mma.sync.aligned.m16n8k16.row.col.f32.f16.f16.f32 "
        "{%0,%1,%2,%3}, {%4,%5,%6,%7}, {%8,%9}, {%0,%1,%2,%3};"
        : "+f"(d[0]), "+f"(d[1]), "+f"(d[2]), "+f"(d[3])
        : "r"(a[0]), "r"(a[1]), "r"(a[2]), "r"(a[3]), "r"(b[0]), "r"(b[1]));
}
__device__ __forceinline__ uint32_t cvta_s(const void* p) {
    return (uint32_t)__cvta_generic_to_shared(p);
}
__device__ __forceinline__ uint32_t h2exp2_(float ulo, float uhi) {
    __half2 u = __floats2half2_rn(ulo, uhi);
    uint32_t r;
    asm("ex2.approx.f16x2 %0, %1;" : "=r"(r) : "r"(*(uint32_t*)&u));
    return r;
}
#define CP_ASYNC16(dst, src) \
    asm volatile("cp.async.cg.shared.global [%0], [%1], 16;" :: "r"(dst), "l"(src))
#define CP_COMMIT() asm volatile("cp.async.commit_group;")
#define CP_WAIT(n)  asm volatile("cp.async.wait_group %0;" :: "n"(n))
#define LDMX4(r0, r1, r2, r3, addr) \
    asm volatile("ldmatrix.sync.aligned.m8n8.x4.shared.b16 {%0,%1,%2,%3}, [%4];" \
        : "=r"(r0), "=r"(r1), "=r"(r2), "=r"(r3) : "r"(addr))

// ---------------------------------------------------------------------------
// HMMA GEMM (f16), cp.async 3-stage pipeline + ldmatrix.
// EPI=0: C fp32 (+bias).
// EPI=1: fused epilogue -> wQ = f16(c*v) with c=sqrt(0.125*log2e),
//        vt = f16(v)*(1-mask[row]).
// ---------------------------------------------------------------------------
#define GP   40
#define GSTG 3

template<int EPI>
__global__ __launch_bounds__(256, 2) void mma_gemm(
    const uint16_t* __restrict__ A, int lda,
    const uint16_t* __restrict__ B, int ldb,
    float* __restrict__ C, int ldc, int K, const float* __restrict__ bias,
    __half* __restrict__ wq, __half* __restrict__ vt,
    const int* __restrict__ maskp)
{
    extern __shared__ __align__(16) uint16_t gsm[];
    const int tid = threadIdx.x, lane = tid & 31, warp = tid >> 5;
    const int g = lane >> 2, t = lane & 3;
    const int wm0 = (warp >> 2) * 64, wn0 = (warp & 3) * 32;
    const int m0 = blockIdx.y * 128, n0 = blockIdx.x * 128;

    const uint16_t* Ab = A + (size_t)m0 * lda;
    const uint16_t* Bb = B + (size_t)n0 * ldb;
    const uint32_t smb = cvta_s(gsm);

    float acc[4][4][4] = {};
    const int NC = K >> 5;

    auto issue = [&](int c) {
        const uint32_t dst = smb + (uint32_t)(c % GSTG) * (256 * GP * 2);
        const uint16_t* ag = Ab + c * 32;
        const uint16_t* bg = Bb + c * 32;
        #pragma unroll
        for (int i = 0; i < 2; i++) {
            int idx = tid + i * 256;
            int r = idx >> 2, q = (idx & 3) * 8;
            CP_ASYNC16(dst + (uint32_t)(r * GP + q) * 2, ag + (size_t)r * lda + q);
        }
        #pragma unroll
        for (int i = 0; i < 2; i++) {
            int idx = tid + i * 256;
            int r = idx >> 2, q = (idx & 3) * 8;
            CP_ASYNC16(dst + (uint32_t)((128 + r) * GP + q) * 2, bg + (size_t)r * ldb + q);
        }
        CP_COMMIT();
    };

    #pragma unroll
    for (int s = 0; s < GSTG - 1; s++) issue(s);

    for (int c = 0; c < NC; c++) {
        CP_WAIT(GSTG - 2);
        __syncthreads();
        if (c + GSTG - 1 < NC) issue(c + GSTG - 1);
        else                   CP_COMMIT();

        const uint32_t asv = smb + (uint32_t)(c % GSTG) * (256 * GP * 2);
        const uint32_t bsv = asv + 128 * GP * 2;

        #pragma unroll
        for (int ks = 0; ks < 2; ks++) {
            const int kb = ks * 16;
            uint32_t bf[4][2];
            #pragma unroll
            for (int ni2 = 0; ni2 < 2; ni2++) {
                uint32_t r0, r1, r2, r3;
                uint32_t addr = bsv + (uint32_t)(((wn0 + ni2 * 16 + ((lane >> 4) << 3) + (lane & 7)) * GP
                                                 + kb + ((lane >> 3) & 1) * 8) << 1);
                LDMX4(r0, r1, r2, r3, addr);
                bf[ni2 * 2][0] = r0; bf[ni2 * 2][1] = r1;
                bf[ni2 * 2 + 1][0] = r2; bf[ni2 * 2 + 1][1] = r3;
            }
            #pragma unroll
            for (int mi = 0; mi < 4; mi++) {
                uint32_t af[4];
                uint32_t addr = asv + (uint32_t)(((wm0 + mi * 16 + (lane & 15)) * GP
                                                 + kb + (lane >> 4) * 8) << 1);
                LDMX4(af[0], af[1], af[2], af[3], addr);
                #pragma unroll
                for (int ni = 0; ni < 4; ni++) mma_f16(acc[mi][ni], af, bf[ni]);
            }
        }
    }

    if (EPI == 0) {
        float* Cb = C + (size_t)m0 * ldc + n0;
        #pragma unroll
        for (int mi = 0; mi < 4; mi++) {
            #pragma unroll
            for (int ni = 0; ni < 4; ni++) {
                int col = wn0 + ni * 8 + 2 * t;
                float bx = 0.0f, by = 0.0f;
                if (bias) { bx = bias[n0 + col]; by = bias[n0 + col + 1]; }
                int r1 = wm0 + mi * 16 + g;
                *(float2*)(Cb + (size_t)r1 * ldc + col) =
                    make_float2(acc[mi][ni][0] + bx, acc[mi][ni][1] + by);
                *(float2*)(Cb + (size_t)(r1 + 8) * ldc + col) =
                    make_float2(acc[mi][ni][2] + bx, acc[mi][ni][3] + by);
            }
        }
    } else {
        const float QS = 0.42466090014400953f;   // sqrt(0.125 * log2(e))
        #pragma unroll
        for (int mi = 0; mi < 4; mi++) {
            #pragma unroll
            for (int half_ = 0; half_ < 2; half_++) {
                const int gr = m0 + wm0 + mi * 16 + g + half_ * 8;
                const int b = gr >> 11, nn = gr & 2047;
                const float keep = 1.0f - (float)maskp[(size_t)b * NSEQ + nn];
                #pragma unroll
                for (int ni = 0; ni < 4; ni++) {
                    const int gc = n0 + wn0 + ni * 8 + 2 * t;
                    const int h = gc >> 6, d = gc & 63;
                    const float v0 = acc[mi][ni][half_ * 2];
                    const float v1 = acc[mi][ni][half_ * 2 + 1];
                    __half2 qp = __floats2half2_rn(v0 * QS, v1 * QS);
                    *(__half2*)&wq[(((size_t)(b * 16 + h)) * NSEQ + nn) * 64 + d] = qp;
                    const __half h0 = __float2half_rn(v0 * keep);
                    const __half h1 = __float2half_rn(v1 * keep);
                    size_t vb = ((size_t)(b * 16 + h) * 64 + d) * NSEQ + nn;
                    vt[vb]        = h0;
                    vt[vb + NSEQ] = h1;
                }
            }
        }
    }
}

// ---------------------------------------------------------------------------
// Fused flash attention. Log2-domain scores with a STATIC per-row softmax
// base = S_ii = |c*w_i|^2 (q=k makes the diagonal the row max w.h.p.; any
// exceedance is <~1.5 log2 units, 14 units below f16 overflow; softmax is
// base-invariant). No running max, no rescale, no reductions in the loop.
// P via ex2.approx.f16x2; V pre-masked; l via all-ones mma tile.
// 128 threads / 4 warps / 64 q-rows per CTA; 4 CTAs/SM.
// ---------------------------------------------------------------------------
#define KB    64
#define NIT   (NSEQ / KB)
#define KSP   72
#define VSP   72
#define SM_K0 0
#define SM_K1 9216
#define SM_V0 18432
#define SM_V1 27648
#define SM_TOT 36864

__global__ __launch_bounds__(128, 4) void flash_attn()
{
    extern __shared__ char sm[];
    const int tid = threadIdx.x, lane = tid & 31, warp = tid >> 5;
    const int g = lane >> 2, t = lane & 3;
    const int i0 = blockIdx.x * 64;
    const int bh = blockIdx.y;
    const int b = bh >> 4, h = bh & 15;

    const uint16_t* wQ = (const uint16_t*)g_wQ + (size_t)bh * NSEQ * 64;
    const uint16_t* vt = (const uint16_t*)g_vt + (size_t)bh * DHEAD * NSEQ;
    const uint32_t smb = cvta_s(sm);

    auto issue = [&](int it2, int buf) {
        const int j0 = it2 * KB;
        const uint32_t kd = smb + (buf ? SM_K1 : SM_K0);
        const uint32_t vd = smb + (buf ? SM_V1 : SM_V0);
        #pragma unroll
        for (int i = 0; i < 4; i++) {
            int idx = tid + i * 128;
            int r = idx >> 3, q = (idx & 7) * 8;
            CP_ASYNC16(kd + (uint32_t)(r * KSP + q) * 2, wQ + (size_t)(j0 + r) * 64 + q);
        }
        #pragma unroll
        for (int i = 0; i < 4; i++) {
            int idx = tid + i * 128;
            int r = idx >> 3, q = (idx & 7) * 8;
            CP_ASYNC16(vd + (uint32_t)(r * VSP + q) * 2, vt + (size_t)r * NSEQ + j0 + q);
        }
        CP_COMMIT();
    };

    // Q fragments (rows i0+warp*16+{g,g+8}): 4 k16 tiles, pre-scaled f16
    uint32_t qh[4][4];
    {
        const uint16_t* q0 = wQ + (size_t)(i0 + warp * 16 + g) * 64 + 2 * t;
        #pragma unroll
        for (int j = 0; j < 4; j++) {
            qh[j][0] = *(const uint32_t*)(q0 + j * 16);
            qh[j][1] = *(const uint32_t*)(q0 + j * 16 + 8 * 64);
            qh[j][2] = *(const uint32_t*)(q0 + j * 16 + 8);
            qh[j][3] = *(const uint32_t*)(q0 + j * 16 + 8 * 64 + 8);
        }
    }

    // Static bases: base0 = |q_row_g|^2, base1 = |q_row_g+8|^2 (scaled domain)
    float base0 = 0.0f, base1 = 0.0f;
    #pragma unroll
    for (int j = 0; j < 4; j++) {
        float2 f;
        f = __half22float2(*(const __half2*)&qh[j][0]); base0 += f.x * f.x + f.y * f.y;
        f = __half22float2(*(const __half2*)&qh[j][2]); base0 += f.x * f.x + f.y * f.y;
        f = __half22float2(*(const __half2*)&qh[j][1]); base1 += f.x * f.x + f.y * f.y;
        f = __half22float2(*(const __half2*)&qh[j][3]); base1 += f.x * f.x + f.y * f.y;
    }
    base0 += __shfl_xor_sync(0xffffffffu, base0, 1);
    base0 += __shfl_xor_sync(0xffffffffu, base0, 2);
    base1 += __shfl_xor_sync(0xffffffffu, base1, 1);
    base1 += __shfl_xor_sync(0xffffffffu, base1, 2);

    float Oa[8][4] = {};
    float lacc[4] = {};
    const uint32_t ones2[2] = {0x3C003C00u, 0x3C003C00u};

    issue(0, 0);
    CP_WAIT(0);
    __syncthreads();

    for (int it = 0; it < NIT; it++) {
        const int cur = it & 1;
        const uint32_t ksv = smb + (cur ? SM_K1 : SM_K0);
        const uint32_t vsv = smb + (cur ? SM_V1 : SM_V0);

        if (it + 1 < NIT) issue(it + 1, cur ^ 1);
        else              CP_COMMIT();

        // ---- S tile (log2-domain scores) ----
        float sa[8][4] = {};
        #pragma unroll
        for (int j = 0; j < 4; j++) {
            #pragma unroll
            for (int nt2 = 0; nt2 < 4; nt2++) {
                uint32_t r0, r1, r2, r3;
                uint32_t addr = ksv + (uint32_t)(((nt2 * 16 + ((lane >> 4) << 3) + (lane & 7)) * KSP
                                                 + j * 16 + ((lane >> 3) & 1) * 8) << 1);
                LDMX4(r0, r1, r2, r3, addr);
                uint32_t b0[2] = {r0, r1}, b1[2] = {r2, r3};
                mma_f16(sa[nt2 * 2],     qh[j], b0);
                mma_f16(sa[nt2 * 2 + 1], qh[j], b1);
            }
        }

        // ---- P = exp2(s - base) via packed f16x2 MUFU (mask lives in V) ----
        uint32_t pfra[4][4];
        #pragma unroll
        for (int kt2 = 0; kt2 < 4; kt2++) {
            const int n0t = 2 * kt2, n1t = 2 * kt2 + 1;
            pfra[kt2][0] = h2exp2_(sa[n0t][0] - base0, sa[n0t][1] - base0);
            pfra[kt2][1] = h2exp2_(sa[n0t][2] - base1, sa[n0t][3] - base1);
            pfra[kt2][2] = h2exp2_(sa[n1t][0] - base0, sa[n1t][1] - base0);
            pfra[kt2][3] = h2exp2_(sa[n1t][2] - base1, sa[n1t][3] - base1);
        }

        // ---- O += P @ V' (pre-masked);  l += P @ 1 ----
        #pragma unroll
        for (int nt2 = 0; nt2 < 4; nt2++) {
            #pragma unroll
            for (int kt2 = 0; kt2 < 4; kt2++) {
                uint32_t r0, r1, r2, r3;
                uint32_t addr = vsv + (uint32_t)(((nt2 * 16 + ((lane >> 4) << 3) + (lane & 7)) * VSP
                                                 + kt2 * 16 + ((lane >> 3) & 1) * 8) << 1);
                LDMX4(r0, r1, r2, r3, addr);
                uint32_t b0[2] = {r0, r1}, b1[2] = {r2, r3};
                mma_f16(Oa[nt2 * 2],     pfra[kt2], b0);
                mma_f16(Oa[nt2 * 2 + 1], pfra[kt2], b1);
            }
        }
        #pragma unroll
        for (int kt2 = 0; kt2 < 4; kt2++)
            mma_f16(lacc, pfra[kt2], ones2);

        CP_WAIT(0);
        __syncthreads();
    }

    const float inv0 = 1.0f / lacc[0], inv1 = 1.0f / lacc[2];
    const int r0 = i0 + warp * 16 + g;
    __half* ob  = g_att16 + ((size_t)b * NSEQ + r0) * DIM + h * 64;
    __half* ob8 = ob + (size_t)8 * DIM;
    #pragma unroll
    for (int nt = 0; nt < 8; nt++) {
        int col = nt * 8 + 2 * t;
        __half2 p0 = __floats2half2_rn(Oa[nt][0] * inv0, Oa[nt][1] * inv0);
        __half2 p1 = __floats2half2_rn(Oa[nt][2] * inv1, Oa[nt][3] * inv1);
        *(__half2*)&ob[col]  = p0;
        *(__half2*)&ob8[col] = p1;
    }
}

// ---------------- converters ---------------------------------------------------
__global__ void cast_f16(const float* __restrict__ in, __half* __restrict__ out,
                         size_t total4)
{
    size_t idx = (size_t)blockIdx.x * 256 + threadIdx.x;
    if (idx >= total4) return;
    float4 v = *(const float4*)(in + idx * 4);
    __half2 a = __floats2half2_rn(v.x, v.y);
    __half2 b = __floats2half2_rn(v.z, v.w);
    *(__half2*)(out + idx * 4)     = a;
    *(__half2*)(out + idx * 4 + 2) = b;
}

__global__ __launch_bounds__(256) void splitB_single2(const float* __restrict__ W0,
                                                      const float* __restrict__ W1,
                                                      __half* __restrict__ O0,
                                                      __half* __restrict__ O1,
                                                      int Kd, int Nd)
{
    __shared__ float ts[32][33];
    const float* W = blockIdx.z ? W1 : W0;
    __half* out = blockIdx.z ? O1 : O0;
    int k0 = blockIdx.x * 32, n0 = blockIdx.y * 32;
    int tx = threadIdx.x & 31, ty = threadIdx.x >> 5;
    for (int r = ty; r < 32; r += 8) ts[r][tx] = W[(size_t)(k0 + r) * Nd + n0 + tx];
    __syncthreads();
    for (int r = ty; r < 32; r += 8)
        out[(size_t)(n0 + r) * Kd + k0 + tx] = __float2half_rn(ts[tx][r]);
}

// ---------------- launch ------------------------------------------------------
extern "C" void kernel_launch(void* const* d_in, const int* in_sizes, int n_in,
                              void* d_out, int out_size)
{
    const float* x    = (const float*)d_in[0];
    const int*   mask = (const int*)d_in[1];
    const float* Wqkv = (const float*)d_in[2];
    const float* Wout = (const float*)d_in[3];
    const float* bout = (const float*)d_in[4];
    float*       out  = (float*)d_out;

    __half *xs, *att16, *w1s, *w2s, *wQ, *vt;
    cudaGetSymbolAddress((void**)&xs,    g_xs);
    cudaGetSymbolAddress((void**)&att16, g_att16);
    cudaGetSymbolAddress((void**)&w1s,   g_w1s);
    cudaGetSymbolAddress((void**)&w2s,   g_w2s);
    cudaGetSymbolAddress((void**)&wQ,    g_wQ);
    cudaGetSymbolAddress((void**)&vt,    g_vt);

    const int GEMM_SMEM = GSTG * 256 * GP * 2;   // 61440
    cudaFuncSetAttribute(mma_gemm<0>, cudaFuncAttributeMaxDynamicSharedMemorySize, GEMM_SMEM);
    cudaFuncSetAttribute(mma_gemm<1>, cudaFuncAttributeMaxDynamicSharedMemorySize, GEMM_SMEM);
    cudaFuncSetAttribute(flash_attn, cudaFuncAttributeMaxDynamicSharedMemorySize, SM_TOT);

    cast_f16<<<((BATCH*NSEQ*DIM/4) + 255) / 256, 256>>>(x, xs, (size_t)BATCH*NSEQ*DIM/4);
    splitB_single2<<<dim3(DIM/32, DIM/32, 2), 256>>>(Wqkv, Wout, w1s, w2s, DIM, DIM);

    // stage 1: w = x @ Wqkv (f16) with fused epilogue -> log2-scaled wQ + masked vt
    mma_gemm<1><<<dim3(DIM/128, (BATCH*NSEQ)/128), 256, GEMM_SMEM>>>(
        (const uint16_t*)xs, DIM, (const uint16_t*)w1s, DIM,
        nullptr, 0, DIM, nullptr, wQ, vt, mask);

    // stage 2+3: fused flash attention -> single-f16 atts
    flash_attn<<<dim3(NSEQ/64, BH), 128, SM_TOT>>>();

    // stage 4: out = atts @ Wout + bout (f16, K=1024)
    mma_gemm<0><<<dim3(DIM/128, (BATCH*NSEQ)/128), 256, GEMM_SMEM>>>(
        (const uint16_t*)att16, DIM, (const uint16_t*)w2s, DIM,
        out, DIM, DIM, bout, nullptr, nullptr, nullptr);
}

// round 17
// speedup vs baseline: 8.3605x; 1.0299x over previous
#include <cuda_runtime.h>
#include <cuda_bf16.h>
#include <cuda_fp16.h>
#include <cstdint>

#define HEADS 16
#define DHEAD 64
#define BATCH 2
#define NSEQ  2048
#define DIM   1024
#define BH    (BATCH*HEADS)

// ---------------- scratch (__device__ globals; allocation-free) -------------
__device__ __align__(256) __half g_xs   [(size_t)BATCH*NSEQ*DIM];    // x f16
__device__ __align__(256) __half g_att16[(size_t)BATCH*NSEQ*DIM];    // atts f16
__device__ __align__(256) __half g_w1s  [(size_t)DIM*DIM];           // Wqkv^T f16
__device__ __align__(256) __half g_w2s  [(size_t)DIM*DIM];           // Wout^T f16
__device__ __align__(256) __half g_wQ   [(size_t)BH*NSEQ*64];        // c*w per-head f16 (c^2=0.125*log2e)
__device__ __align__(256) __half g_vt   [(size_t)BH*DHEAD*NSEQ];     // V^T f16, mask-zeroed rows

// ---------------- PTX helpers -------------------------------------------------
__device__ __forceinline__ void mma_f16(float* d, const uint32_t* a, const uint32_t* b) {
    asm volatile(
        "mma.sync.aligned.m16n8k16.row.col.f32.f16.f16.f32 "
        "{%0,%1,%2,%3}, {%4,%5,%6,%7}, {%8,%9}, {%0,%1,%2,%3};"
        : "+f"(d[0]), "+f"(d[1]), "+f"(d[2]), "+f"(d[3])
        : "r"(a[0]), "r"(a[1]), "r"(a[2]), "r"(a[3]), "r"(b[0]), "r"(b[1]));
}
__device__ __forceinline__ uint32_t cvta_s(const void* p) {
    return (uint32_t)__cvta_generic_to_shared(p);
}
__device__ __forceinline__ uint32_t h2exp2_(float ulo, float uhi) {
    __half2 u = __floats2half2_rn(ulo, uhi);
    uint32_t r;
    asm("ex2.approx.f16x2 %0, %1;" : "=r"(r) : "r"(*(uint32_t*)&u));
    return r;
}
#define CP_ASYNC16(dst, src) \
    asm volatile("cp.async.cg.shared.global [%0], [%1], 16;" :: "r"(dst), "l"(src))
#define CP_COMMIT() asm volatile("cp.async.commit_group;")
#define CP_WAIT(n)  asm volatile("cp.async.wait_group %0;" :: "n"(n))
#define LDMX4(r0, r1, r2, r3, addr) \
    asm volatile("ldmatrix.sync.aligned.m8n8.x4.shared.b16 {%0,%1,%2,%3}, [%4];" \
        : "=r"(r0), "=r"(r1), "=r"(r2), "=r"(r3) : "r"(addr))

// ---------------------------------------------------------------------------
// HMMA GEMM (f16), cp.async 3-stage pipeline + ldmatrix. K-chunk = 64 halfs
// (4 k16 steps per barrier: 64 mma / 24 ldmatrix / 1 sync).
// Pitch 72 halfs (144B rows == 16 mod 128 -> ldmatrix conflict-free).
// EPI=0: C fp32 (+bias).
// EPI=1: fused epilogue -> wQ = f16(c*v), c=sqrt(0.125*log2e);
//        vt = f16(v)*(1-mask[row]).
// ---------------------------------------------------------------------------
#define GP    72
#define GSTG  3
#define GSTAGE_BYTES (256 * GP * 2)   // 36864

template<int EPI>
__global__ __launch_bounds__(256, 2) void mma_gemm(
    const uint16_t* __restrict__ A, int lda,
    const uint16_t* __restrict__ B, int ldb,
    float* __restrict__ C, int ldc, int K, const float* __restrict__ bias,
    __half* __restrict__ wq, __half* __restrict__ vt,
    const int* __restrict__ maskp)
{
    extern __shared__ __align__(16) uint16_t gsm[];
    const int tid = threadIdx.x, lane = tid & 31, warp = tid >> 5;
    const int g = lane >> 2, t = lane & 3;
    const int wm0 = (warp >> 2) * 64, wn0 = (warp & 3) * 32;
    const int m0 = blockIdx.y * 128, n0 = blockIdx.x * 128;

    const uint16_t* Ab = A + (size_t)m0 * lda;
    const uint16_t* Bb = B + (size_t)n0 * ldb;
    const uint32_t smb = cvta_s(gsm);

    float acc[4][4][4] = {};
    const int NC = K >> 6;   // 64-half chunks

    auto issue = [&](int c) {
        const uint32_t dst = smb + (uint32_t)(c % GSTG) * GSTAGE_BYTES;
        const uint16_t* ag = Ab + c * 64;
        const uint16_t* bg = Bb + c * 64;
        #pragma unroll
        for (int i = 0; i < 4; i++) {
            int idx = tid + i * 256;
            int r = idx >> 3, q = (idx & 7) * 8;
            CP_ASYNC16(dst + (uint32_t)(r * GP + q) * 2, ag + (size_t)r * lda + q);
        }
        #pragma unroll
        for (int i = 0; i < 4; i++) {
            int idx = tid + i * 256;
            int r = idx >> 3, q = (idx & 7) * 8;
            CP_ASYNC16(dst + (uint32_t)((128 + r) * GP + q) * 2, bg + (size_t)r * ldb + q);
        }
        CP_COMMIT();
    };

    #pragma unroll
    for (int s = 0; s < GSTG - 1; s++) issue(s);

    for (int c = 0; c < NC; c++) {
        CP_WAIT(GSTG - 2);
        __syncthreads();
        if (c + GSTG - 1 < NC) issue(c + GSTG - 1);
        else                   CP_COMMIT();

        const uint32_t asv = smb + (uint32_t)(c % GSTG) * GSTAGE_BYTES;
        const uint32_t bsv = asv + 128 * GP * 2;

        #pragma unroll
        for (int ks = 0; ks < 4; ks++) {
            const int kb = ks * 16;
            uint32_t bf[4][2];
            #pragma unroll
            for (int ni2 = 0; ni2 < 2; ni2++) {
                uint32_t r0, r1, r2, r3;
                uint32_t addr = bsv + (uint32_t)(((wn0 + ni2 * 16 + ((lane >> 4) << 3) + (lane & 7)) * GP
                                                 + kb + ((lane >> 3) & 1) * 8) << 1);
                LDMX4(r0, r1, r2, r3, addr);
                bf[ni2 * 2][0] = r0; bf[ni2 * 2][1] = r1;
                bf[ni2 * 2 + 1][0] = r2; bf[ni2 * 2 + 1][1] = r3;
            }
            #pragma unroll
            for (int mi = 0; mi < 4; mi++) {
                uint32_t af[4];
                uint32_t addr = asv + (uint32_t)(((wm0 + mi * 16 + (lane & 15)) * GP
                                                 + kb + (lane >> 4) * 8) << 1);
                LDMX4(af[0], af[1], af[2], af[3], addr);
                #pragma unroll
                for (int ni = 0; ni < 4; ni++) mma_f16(acc[mi][ni], af, bf[ni]);
            }
        }
    }

    if (EPI == 0) {
        float* Cb = C + (size_t)m0 * ldc + n0;
        #pragma unroll
        for (int mi = 0; mi < 4; mi++) {
            #pragma unroll
            for (int ni = 0; ni < 4; ni++) {
                int col = wn0 + ni * 8 + 2 * t;
                float bx = 0.0f, by = 0.0f;
                if (bias) { bx = bias[n0 + col]; by = bias[n0 + col + 1]; }
                int r1 = wm0 + mi * 16 + g;
                *(float2*)(Cb + (size_t)r1 * ldc + col) =
                    make_float2(acc[mi][ni][0] + bx, acc[mi][ni][1] + by);
                *(float2*)(Cb + (size_t)(r1 + 8) * ldc + col) =
                    make_float2(acc[mi][ni][2] + bx, acc[mi][ni][3] + by);
            }
        }
    } else {
        const float QS = 0.42466090014400953f;   // sqrt(0.125 * log2(e))
        #pragma unroll
        for (int mi = 0; mi < 4; mi++) {
            #pragma unroll
            for (int half_ = 0; half_ < 2; half_++) {
                const int gr = m0 + wm0 + mi * 16 + g + half_ * 8;
                const int b = gr >> 11, nn = gr & 2047;
                const float keep = 1.0f - (float)maskp[(size_t)b * NSEQ + nn];
                #pragma unroll
                for (int ni = 0; ni < 4; ni++) {
                    const int gc = n0 + wn0 + ni * 8 + 2 * t;
                    const int h = gc >> 6, d = gc & 63;
                    const float v0 = acc[mi][ni][half_ * 2];
                    const float v1 = acc[mi][ni][half_ * 2 + 1];
                    __half2 qp = __floats2half2_rn(v0 * QS, v1 * QS);
                    *(__half2*)&wq[(((size_t)(b * 16 + h)) * NSEQ + nn) * 64 + d] = qp;
                    const __half h0 = __float2half_rn(v0 * keep);
                    const __half h1 = __float2half_rn(v1 * keep);
                    size_t vb = ((size_t)(b * 16 + h) * 64 + d) * NSEQ + nn;
                    vt[vb]        = h0;
                    vt[vb + NSEQ] = h1;
                }
            }
        }
    }
}

// ---------------------------------------------------------------------------
// Fused flash attention (R16 core, unchanged): static diagonal softmax base,
// ex2.approx.f16x2, pre-masked V, l via all-ones mma tile.
// 128 threads / 4 warps / 64 q-rows per CTA; 4 CTAs/SM.
// ---------------------------------------------------------------------------
#define KB    64
#define NIT   (NSEQ / KB)
#define KSP   72
#define VSP   72
#define SM_K0 0
#define SM_K1 9216
#define SM_V0 18432
#define SM_V1 27648
#define SM_TOT 36864

__global__ __launch_bounds__(128, 4) void flash_attn()
{
    extern __shared__ char sm[];
    const int tid = threadIdx.x, lane = tid & 31, warp = tid >> 5;
    const int g = lane >> 2, t = lane & 3;
    const int i0 = blockIdx.x * 64;
    const int bh = blockIdx.y;
    const int b = bh >> 4, h = bh & 15;

    const uint16_t* wQ = (const uint16_t*)g_wQ + (size_t)bh * NSEQ * 64;
    const uint16_t* vt = (const uint16_t*)g_vt + (size_t)bh * DHEAD * NSEQ;
    const uint32_t smb = cvta_s(sm);

    auto issue = [&](int it2, int buf) {
        const int j0 = it2 * KB;
        const uint32_t kd = smb + (buf ? SM_K1 : SM_K0);
        const uint32_t vd = smb + (buf ? SM_V1 : SM_V0);
        #pragma unroll
        for (int i = 0; i < 4; i++) {
            int idx = tid + i * 128;
            int r = idx >> 3, q = (idx & 7) * 8;
            CP_ASYNC16(kd + (uint32_t)(r * KSP + q) * 2, wQ + (size_t)(j0 + r) * 64 + q);
        }
        #pragma unroll
        for (int i = 0; i < 4; i++) {
            int idx = tid + i * 128;
            int r = idx >> 3, q = (idx & 7) * 8;
            CP_ASYNC16(vd + (uint32_t)(r * VSP + q) * 2, vt + (size_t)r * NSEQ + j0 + q);
        }
        CP_COMMIT();
    };

    uint32_t qh[4][4];
    {
        const uint16_t* q0 = wQ + (size_t)(i0 + warp * 16 + g) * 64 + 2 * t;
        #pragma unroll
        for (int j = 0; j < 4; j++) {
            qh[j][0] = *(const uint32_t*)(q0 + j * 16);
            qh[j][1] = *(const uint32_t*)(q0 + j * 16 + 8 * 64);
            qh[j][2] = *(const uint32_t*)(q0 + j * 16 + 8);
            qh[j][3] = *(const uint32_t*)(q0 + j * 16 + 8 * 64 + 8);
        }
    }

    // Static bases: base0 = |q_row_g|^2, base1 = |q_row_g+8|^2 (scaled domain)
    float base0 = 0.0f, base1 = 0.0f;
    #pragma unroll
    for (int j = 0; j < 4; j++) {
        float2 f;
        f = __half22float2(*(const __half2*)&qh[j][0]); base0 += f.x * f.x + f.y * f.y;
        f = __half22float2(*(const __half2*)&qh[j][2]); base0 += f.x * f.x + f.y * f.y;
        f = __half22float2(*(const __half2*)&qh[j][1]); base1 += f.x * f.x + f.y * f.y;
        f = __half22float2(*(const __half2*)&qh[j][3]); base1 += f.x * f.x + f.y * f.y;
    }
    base0 += __shfl_xor_sync(0xffffffffu, base0, 1);
    base0 += __shfl_xor_sync(0xffffffffu, base0, 2);
    base1 += __shfl_xor_sync(0xffffffffu, base1, 1);
    base1 += __shfl_xor_sync(0xffffffffu, base1, 2);

    float Oa[8][4] = {};
    float lacc[4] = {};
    const uint32_t ones2[2] = {0x3C003C00u, 0x3C003C00u};

    issue(0, 0);
    CP_WAIT(0);
    __syncthreads();

    for (int it = 0; it < NIT; it++) {
        const int cur = it & 1;
        const uint32_t ksv = smb + (cur ? SM_K1 : SM_K0);
        const uint32_t vsv = smb + (cur ? SM_V1 : SM_V0);

        if (it + 1 < NIT) issue(it + 1, cur ^ 1);
        else              CP_COMMIT();

        float sa[8][4] = {};
        #pragma unroll
        for (int j = 0; j < 4; j++) {
            #pragma unroll
            for (int nt2 = 0; nt2 < 4; nt2++) {
                uint32_t r0, r1, r2, r3;
                uint32_t addr = ksv + (uint32_t)(((nt2 * 16 + ((lane >> 4) << 3) + (lane & 7)) * KSP
                                                 + j * 16 + ((lane >> 3) & 1) * 8) << 1);
                LDMX4(r0, r1, r2, r3, addr);
                uint32_t b0[2] = {r0, r1}, b1[2] = {r2, r3};
                mma_f16(sa[nt2 * 2],     qh[j], b0);
                mma_f16(sa[nt2 * 2 + 1], qh[j], b1);
            }
        }

        uint32_t pfra[4][4];
        #pragma unroll
        for (int kt2 = 0; kt2 < 4; kt2++) {
            const int n0t = 2 * kt2, n1t = 2 * kt2 + 1;
            pfra[kt2][0] = h2exp2_(sa[n0t][0] - base0, sa[n0t][1] - base0);
            pfra[kt2][1] = h2exp2_(sa[n0t][2] - base1, sa[n0t][3] - base1);
            pfra[kt2][2] = h2exp2_(sa[n1t][0] - base0, sa[n1t][1] - base0);
            pfra[kt2][3] = h2exp2_(sa[n1t][2] - base1, sa[n1t][3] - base1);
        }

        #pragma unroll
        for (int nt2 = 0; nt2 < 4; nt2++) {
            #pragma unroll
            for (int kt2 = 0; kt2 < 4; kt2++) {
                uint32_t r0, r1, r2, r3;
                uint32_t addr = vsv + (uint32_t)(((nt2 * 16 + ((lane >> 4) << 3) + (lane & 7)) * VSP
                                                 + kt2 * 16 + ((lane >> 3) & 1) * 8) << 1);
                LDMX4(r0, r1, r2, r3, addr);
                uint32_t b0[2] = {r0, r1}, b1[2] = {r2, r3};
                mma_f16(Oa[nt2 * 2],     pfra[kt2], b0);
                mma_f16(Oa[nt2 * 2 + 1], pfra[kt2], b1);
            }
        }
        #pragma unroll
        for (int kt2 = 0; kt2 < 4; kt2++)
            mma_f16(lacc, pfra[kt2], ones2);

        CP_WAIT(0);
        __syncthreads();
    }

    const float inv0 = 1.0f / lacc[0], inv1 = 1.0f / lacc[2];
    const int r0 = i0 + warp * 16 + g;
    __half* ob  = g_att16 + ((size_t)b * NSEQ + r0) * DIM + h * 64;
    __half* ob8 = ob + (size_t)8 * DIM;
    #pragma unroll
    for (int nt = 0; nt < 8; nt++) {
        int col = nt * 8 + 2 * t;
        __half2 p0 = __floats2half2_rn(Oa[nt][0] * inv0, Oa[nt][1] * inv0);
        __half2 p1 = __floats2half2_rn(Oa[nt][2] * inv1, Oa[nt][3] * inv1);
        *(__half2*)&ob[col]  = p0;
        *(__half2*)&ob8[col] = p1;
    }
}

// ---------------- converters ---------------------------------------------------
__global__ void cast_f16(const float* __restrict__ in, __half* __restrict__ out,
                         size_t total4)
{
    size_t idx = (size_t)blockIdx.x * 256 + threadIdx.x;
    if (idx >= total4) return;
    float4 v = *(const float4*)(in + idx * 4);
    __half2 a = __floats2half2_rn(v.x, v.y);
    __half2 b = __floats2half2_rn(v.z, v.w);
    *(__half2*)(out + idx * 4)     = a;
    *(__half2*)(out + idx * 4 + 2) = b;
}

__global__ __launch_bounds__(256) void splitB_single2(const float* __restrict__ W0,
                                                      const float* __restrict__ W1,
                                                      __half* __restrict__ O0,
                                                      __half* __restrict__ O1,
                                                      int Kd, int Nd)
{
    __shared__ float ts[32][33];
    const float* W = blockIdx.z ? W1 : W0;
    __half* out = blockIdx.z ? O1 : O0;
    int k0 = blockIdx.x * 32, n0 = blockIdx.y * 32;
    int tx = threadIdx.x & 31, ty = threadIdx.x >> 5;
    for (int r = ty; r < 32; r += 8) ts[r][tx] = W[(size_t)(k0 + r) * Nd + n0 + tx];
    __syncthreads();
    for (int r = ty; r < 32; r += 8)
        out[(size_t)(n0 + r) * Kd + k0 + tx] = __float2half_rn(ts[tx][r]);
}

// ---------------- launch ------------------------------------------------------
extern "C" void kernel_launch(void* const* d_in, const int* in_sizes, int n_in,
                              void* d_out, int out_size)
{
    const float* x    = (const float*)d_in[0];
    const int*   mask = (const int*)d_in[1];
    const float* Wqkv = (const float*)d_in[2];
    const float* Wout = (const float*)d_in[3];
    const float* bout = (const float*)d_in[4];
    float*       out  = (float*)d_out;

    __half *xs, *att16, *w1s, *w2s, *wQ, *vt;
    cudaGetSymbolAddress((void**)&xs,    g_xs);
    cudaGetSymbolAddress((void**)&att16, g_att16);
    cudaGetSymbolAddress((void**)&w1s,   g_w1s);
    cudaGetSymbolAddress((void**)&w2s,   g_w2s);
    cudaGetSymbolAddress((void**)&wQ,    g_wQ);
    cudaGetSymbolAddress((void**)&vt,    g_vt);

    const int GEMM_SMEM = GSTG * GSTAGE_BYTES;   // 110592
    cudaFuncSetAttribute(mma_gemm<0>, cudaFuncAttributeMaxDynamicSharedMemorySize, GEMM_SMEM);
    cudaFuncSetAttribute(mma_gemm<1>, cudaFuncAttributeMaxDynamicSharedMemorySize, GEMM_SMEM);
    cudaFuncSetAttribute(flash_attn, cudaFuncAttributeMaxDynamicSharedMemorySize, SM_TOT);

    cast_f16<<<((BATCH*NSEQ*DIM/4) + 255) / 256, 256>>>(x, xs, (size_t)BATCH*NSEQ*DIM/4);
    splitB_single2<<<dim3(DIM/32, DIM/32, 2), 256>>>(Wqkv, Wout, w1s, w2s, DIM, DIM);

    // stage 1: w = x @ Wqkv (f16) with fused epilogue -> log2-scaled wQ + masked vt
    mma_gemm<1><<<dim3(DIM/128, (BATCH*NSEQ)/128), 256, GEMM_SMEM>>>(
        (const uint16_t*)xs, DIM, (const uint16_t*)w1s, DIM,
        nullptr, 0, DIM, nullptr, wQ, vt, mask);

    // stage 2+3: fused flash attention -> single-f16 atts
    flash_attn<<<dim3(NSEQ/64, BH), 128, SM_TOT>>>();

    // stage 4: out = atts @ Wout + bout (f16, K=1024)
    mma_gemm<0><<<dim3(DIM/128, (BATCH*NSEQ)/128), 256, GEMM_SMEM>>>(
        (const uint16_t*)att16, DIM, (const uint16_t*)w2s, DIM,
        out, DIM, DIM, bout, nullptr, nullptr, nullptr);
}